// round 1
// baseline (speedup 1.0000x reference)
#include <cuda_runtime.h>
#include <math.h>

// ---------------------------------------------------------------------------
// BiMamba: bidirectional Mamba block + FFN.  B=2, L=2048, D_MODEL=1024,
// D_INNER=2048, D_STATE=16, D_CONV=4, DT_RANK=64.
// Pipeline per direction: x@Win -> causal dwconv+silu -> @Wx -> dt GEMM
// (softplus) -> selective scan (16 states = 16 lanes) -> gate -> @Wout.
// Then dual residual-LN, FFN (relu GEMM + GEMM), final residual-LN.
// ---------------------------------------------------------------------------

#define NB   2
#define SEQ  2048
#define DM   1024
#define DI   2048
#define DS   16
#define DTR  64
#define NX   96          // DT_RANK + 2*D_STATE
#define NR   (NB*SEQ)    // 4096 rows
#define LN_EPS 1e-5f

// ---- scratch (device globals; no allocation allowed) ----------------------
__device__ float g_xz  [(size_t)NR * 2 * DI];   // 64 MB
__device__ float g_xi  [(size_t)NR * DI];       // 32 MB
__device__ float g_xdbc[(size_t)NR * NX];
__device__ float g_dt  [(size_t)NR * DI];       // 32 MB
__device__ float g_gy  [(size_t)NR * DI];       // 32 MB (y * silu(z))
__device__ float g_ymf [(size_t)NR * DM];
__device__ float g_ymb [(size_t)NR * DM];
__device__ float g_ycomb[(size_t)NR * DM];
__device__ float g_ffh [(size_t)NR * DI];       // 32 MB
__device__ float g_ff  [(size_t)NR * DM];

// ---------------------------------------------------------------------------
// Generic tiled SGEMM:  C[M,N] = A[M,K] @ B[K,N]  (+bias, epilogue)
// flipA: read A row m as row (b, L-1-t).  flipC: write C row m to (b, L-1-t).
// Requires K % BK == 0, lda/ldb multiples of 4, 256 threads.
// ---------------------------------------------------------------------------
#define EP_NONE     0
#define EP_SOFTPLUS 1
#define EP_RELU     2
#define EP_BIAS     3

__device__ __forceinline__ int fliprow(int m) {
    return (m & ~(SEQ - 1)) | ((SEQ - 1) - (m & (SEQ - 1)));
}

template<int BM, int BN, int BK, int TM, int TN>
__global__ void __launch_bounds__(256)
sgemm_kernel(const float* __restrict__ A, int lda,
             const float* __restrict__ Bm, int ldb,
             float* __restrict__ C, int ldc,
             int M, int N, int K,
             int flipA, int flipC,
             int epi, const float* __restrict__ bias)
{
    static_assert(BM * BK / 4 == 256, "A-load mapping");
    static_assert(BK * BN / 4 == 256, "B-load mapping");
    static_assert((BM / TM) * (BN / TN) == 256, "thread tile");

    __shared__ float As[BK][BM + 4];
    __shared__ float Bs[BK][BN];

    const int tid = threadIdx.x;
    const int bm  = blockIdx.y * BM;
    const int bn  = blockIdx.x * BN;

    const int tm = (tid / (BN / TN)) * TM;
    const int tn = (tid % (BN / TN)) * TN;

    // A tile load: one float4 per thread along K
    constexpr int K4 = BK / 4;
    const int a_row = tid / K4;
    const int a_k   = (tid % K4) * 4;
    // B tile load: one float4 per thread along N
    const int b_row = tid / (BN / 4);
    const int b_col = (tid % (BN / 4)) * 4;

    int grow = bm + a_row;
    if (grow >= M) grow = M - 1;               // clamp (M always tile-aligned here)
    const int arow_src = flipA ? fliprow(grow) : grow;
    const float* Aptr = A + (size_t)arow_src * lda + a_k;

    float acc[TM][TN];
    #pragma unroll
    for (int i = 0; i < TM; ++i)
        #pragma unroll
        for (int j = 0; j < TN; ++j) acc[i][j] = 0.f;

    for (int kt = 0; kt < K; kt += BK) {
        // load A (float4, aligned: lda % 4 == 0, a_k % 4 == 0)
        float4 av = *reinterpret_cast<const float4*>(Aptr + kt);
        As[a_k + 0][a_row] = av.x;
        As[a_k + 1][a_row] = av.y;
        As[a_k + 2][a_row] = av.z;
        As[a_k + 3][a_row] = av.w;
        // load B (scalar, N-predicated)
        const int gk = kt + b_row;
        #pragma unroll
        for (int j = 0; j < 4; ++j) {
            int gc = bn + b_col + j;
            Bs[b_row][b_col + j] = (gc < N) ? Bm[(size_t)gk * ldb + gc] : 0.f;
        }
        __syncthreads();

        #pragma unroll
        for (int k = 0; k < BK; ++k) {
            float ra[TM], rb[TN];
            #pragma unroll
            for (int i = 0; i < TM; i += 4) {
                float4 v = *reinterpret_cast<const float4*>(&As[k][tm + i]);
                ra[i] = v.x; ra[i+1] = v.y; ra[i+2] = v.z; ra[i+3] = v.w;
            }
            #pragma unroll
            for (int j = 0; j < TN; j += 4) {
                float4 v = *reinterpret_cast<const float4*>(&Bs[k][tn + j]);
                rb[j] = v.x; rb[j+1] = v.y; rb[j+2] = v.z; rb[j+3] = v.w;
            }
            #pragma unroll
            for (int i = 0; i < TM; ++i)
                #pragma unroll
                for (int j = 0; j < TN; ++j)
                    acc[i][j] = fmaf(ra[i], rb[j], acc[i][j]);
        }
        __syncthreads();
    }

    #pragma unroll
    for (int i = 0; i < TM; ++i) {
        int cr = bm + tm + i;
        if (cr >= M) continue;
        int orow = flipC ? fliprow(cr) : cr;
        #pragma unroll
        for (int j = 0; j < TN; ++j) {
            int cc = bn + tn + j;
            if (cc >= N) continue;
            float v = acc[i][j];
            if (epi != EP_NONE) v += bias[cc];
            if (epi == EP_SOFTPLUS) v = (v > 20.f) ? v : log1pf(expf(v));
            else if (epi == EP_RELU) v = fmaxf(v, 0.f);
            C[(size_t)orow * ldc + cc] = v;
        }
    }
}

// ---------------------------------------------------------------------------
// Causal depthwise conv (width 4) + SiLU:  g_xz[:, :DI] -> g_xi
// ---------------------------------------------------------------------------
__global__ void __launch_bounds__(256)
conv_silu_kernel(const float* __restrict__ convw, const float* __restrict__ convb)
{
    int idx = blockIdx.x * 256 + threadIdx.x;      // over NR*DI
    if (idx >= NR * DI) return;
    int d = idx % DI;
    int n = idx / DI;
    int b = n >> 11;           // /SEQ
    int t = n & (SEQ - 1);
    float4 w = *reinterpret_cast<const float4*>(convw + d * 4);
    float acc = convb[d];
    const float* base = g_xz + (size_t)(b << 11) * (2 * DI) + d;
    if (t >= 3) {
        acc = fmaf(base[(size_t)(t-3) * (2*DI)], w.x, acc);
        acc = fmaf(base[(size_t)(t-2) * (2*DI)], w.y, acc);
        acc = fmaf(base[(size_t)(t-1) * (2*DI)], w.z, acc);
        acc = fmaf(base[(size_t)(t  ) * (2*DI)], w.w, acc);
    } else {
        if (t-3 >= 0) acc = fmaf(base[(size_t)(t-3)*(2*DI)], w.x, acc);
        if (t-2 >= 0) acc = fmaf(base[(size_t)(t-2)*(2*DI)], w.y, acc);
        if (t-1 >= 0) acc = fmaf(base[(size_t)(t-1)*(2*DI)], w.z, acc);
        acc = fmaf(base[(size_t)t * (2*DI)], w.w, acc);
    }
    g_xi[idx] = acc / (1.f + expf(-acc));
}

// ---------------------------------------------------------------------------
// Selective scan: 16 states = 16 lanes, 2 channels per warp.
// h_t = exp(dt*A)*h_{t-1} + dt*u*B_t ;  y_t = <h_t, C_t> + u*Dp ;
// out = y_t * silu(z_t)
// ---------------------------------------------------------------------------
__global__ void __launch_bounds__(256)
scan_kernel(const float* __restrict__ Alog, const float* __restrict__ Dpar)
{
    const int lane = threadIdx.x & 31;
    const int gw   = blockIdx.x * 8 + (threadIdx.x >> 5);   // 2048 warps
    const int half = lane >> 4;
    const int s    = lane & 15;
    const int ch   = gw * 2 + half;          // 0..4095
    const int b    = ch >> 11;               // /DI
    const int d    = ch & (DI - 1);

    const float Ac = -expf(Alog[d * DS + s]);
    const float Dp = Dpar[d];

    const size_t rowbase = (size_t)b * SEQ;
    const float* dt_p = g_dt  + rowbase * DI + d;
    const float* u_p  = g_xi  + rowbase * DI + d;
    const float* z_p  = g_xz  + rowbase * (2*DI) + DI + d;
    const float* bc_p = g_xdbc + rowbase * NX + DTR + s;
    float*       o_p  = g_gy  + rowbase * DI + d;

    float h = 0.f;
    for (int t = 0; t < SEQ; ++t) {
        const float dtv = dt_p[(size_t)t * DI];
        const float u   = u_p [(size_t)t * DI];
        const float Bv  = bc_p[(size_t)t * NX];
        const float Cv  = bc_p[(size_t)t * NX + DS];
        const float dA  = __expf(dtv * Ac);
        h = fmaf(dA, h, dtv * u * Bv);
        float p = h * Cv;
        #pragma unroll
        for (int o = 8; o; o >>= 1)
            p += __shfl_xor_sync(0xffffffffu, p, o);
        if (s == 0) {
            const float z = z_p[(size_t)t * (2*DI)];
            const float g = z / (1.f + __expf(-z));
            o_p[(size_t)t * DI] = (p + u * Dp) * g;
        }
    }
}

// ---------------------------------------------------------------------------
// Reductions + layernorms
// ---------------------------------------------------------------------------
__device__ __forceinline__ float blockReduceSum(float v)
{
    __shared__ float sh[8];
    __syncthreads();                 // protect sh reuse across calls
    #pragma unroll
    for (int o = 16; o; o >>= 1) v += __shfl_xor_sync(0xffffffffu, v, o);
    if ((threadIdx.x & 31) == 0) sh[threadIdx.x >> 5] = v;
    __syncthreads();
    if (threadIdx.x < 32) {
        float t = (threadIdx.x < 8) ? sh[threadIdx.x] : 0.f;
        #pragma unroll
        for (int o = 4; o; o >>= 1) t += __shfl_xor_sync(0xffffffffu, t, o);
        if (threadIdx.x == 0) sh[0] = t;
    }
    __syncthreads();
    return sh[0];
}

// ycomb = LN(ymf + x) + LN(ymb + x), both with (w, b)
__global__ void __launch_bounds__(256)
ln_dual_kernel(const float* __restrict__ x,
               const float* __restrict__ w, const float* __restrict__ bs)
{
    const int row = blockIdx.x;
    const float* xr = x     + (size_t)row * DM;
    const float* fr = g_ymf + (size_t)row * DM;
    const float* br = g_ymb + (size_t)row * DM;
    float* out      = g_ycomb + (size_t)row * DM;

    float a[4], c[4];
    float sa = 0.f, sb = 0.f;
    #pragma unroll
    for (int i = 0; i < 4; ++i) {
        int idx = threadIdx.x + i * 256;
        float xv = xr[idx];
        a[i] = fr[idx] + xv;
        c[i] = br[idx] + xv;
        sa += a[i]; sb += c[i];
    }
    sa = blockReduceSum(sa);
    sb = blockReduceSum(sb);
    const float mua = sa * (1.f / DM), mub = sb * (1.f / DM);
    float va = 0.f, vb = 0.f;
    #pragma unroll
    for (int i = 0; i < 4; ++i) {
        float da = a[i] - mua; va += da * da;
        float db = c[i] - mub; vb += db * db;
    }
    va = blockReduceSum(va);
    vb = blockReduceSum(vb);
    const float ra = rsqrtf(va * (1.f / DM) + LN_EPS);
    const float rb = rsqrtf(vb * (1.f / DM) + LN_EPS);
    #pragma unroll
    for (int i = 0; i < 4; ++i) {
        int idx = threadIdx.x + i * 256;
        float wv = w[idx], bv = bs[idx];
        out[idx] = ((a[i] - mua) * ra * wv + bv)
                 + ((c[i] - mub) * rb * wv + bv);
    }
}

// out = LN(ff + ycomb) with fin params
__global__ void __launch_bounds__(256)
ln_final_kernel(const float* __restrict__ w, const float* __restrict__ bs,
                float* __restrict__ out)
{
    const int row = blockIdx.x;
    const float* fr = g_ff    + (size_t)row * DM;
    const float* yr = g_ycomb + (size_t)row * DM;
    float* orow = out + (size_t)row * DM;

    float a[4];
    float sa = 0.f;
    #pragma unroll
    for (int i = 0; i < 4; ++i) {
        int idx = threadIdx.x + i * 256;
        a[i] = fr[idx] + yr[idx];
        sa += a[i];
    }
    sa = blockReduceSum(sa);
    const float mu = sa * (1.f / DM);
    float va = 0.f;
    #pragma unroll
    for (int i = 0; i < 4; ++i) { float d = a[i] - mu; va += d * d; }
    va = blockReduceSum(va);
    const float rs = rsqrtf(va * (1.f / DM) + LN_EPS);
    #pragma unroll
    for (int i = 0; i < 4; ++i) {
        int idx = threadIdx.x + i * 256;
        orow[idx] = (a[i] - mu) * rs * w[idx] + bs[idx];
    }
}

// ---------------------------------------------------------------------------
// Launch
// ---------------------------------------------------------------------------
extern "C" void kernel_launch(void* const* d_in, const int* in_sizes, int n_in,
                              void* d_out, int out_size)
{
    (void)in_sizes; (void)n_in; (void)out_size;
    const float* x     = (const float*)d_in[0];
    const float* fwn_w = (const float*)d_in[19];
    const float* fwn_b = (const float*)d_in[20];
    const float* fin_w = (const float*)d_in[21];
    const float* fin_b = (const float*)d_in[22];
    const float* ff_W1 = (const float*)d_in[23];
    const float* ff_b1 = (const float*)d_in[24];
    const float* ff_W2 = (const float*)d_in[25];
    const float* ff_b2 = (const float*)d_in[26];

    float *xz, *xi, *xdbc, *dt, *gy, *ymf, *ymb, *ycomb, *ffh, *ff;
    cudaGetSymbolAddress((void**)&xz,    g_xz);
    cudaGetSymbolAddress((void**)&xi,    g_xi);
    cudaGetSymbolAddress((void**)&xdbc,  g_xdbc);
    cudaGetSymbolAddress((void**)&dt,    g_dt);
    cudaGetSymbolAddress((void**)&gy,    g_gy);
    cudaGetSymbolAddress((void**)&ymf,   g_ymf);
    cudaGetSymbolAddress((void**)&ymb,   g_ymb);
    cudaGetSymbolAddress((void**)&ycomb, g_ycomb);
    cudaGetSymbolAddress((void**)&ffh,   g_ffh);
    cudaGetSymbolAddress((void**)&ff,    g_ff);

    for (int dir = 0; dir < 2; ++dir) {
        const int o = dir ? 10 : 1;
        const float* Win   = (const float*)d_in[o + 0];
        const float* convw = (const float*)d_in[o + 1];
        const float* convb = (const float*)d_in[o + 2];
        const float* Wx    = (const float*)d_in[o + 3];
        const float* Wdt   = (const float*)d_in[o + 4];
        const float* bdt   = (const float*)d_in[o + 5];
        const float* Alog  = (const float*)d_in[o + 6];
        const float* Dp    = (const float*)d_in[o + 7];
        const float* Wout  = (const float*)d_in[o + 8];

        // xz = (flip?)x @ Win   [4096 x 4096]
        sgemm_kernel<128,128,8,8,8><<<dim3(32,32), 256>>>(
            x, DM, Win, 2*DI, xz, 2*DI, NR, 2*DI, DM, dir, 0, EP_NONE, nullptr);

        // causal dwconv + silu -> xi
        conv_silu_kernel<<<(NR*DI)/256, 256>>>(convw, convb);

        // xdbc = xi @ Wx   [4096 x 96]
        sgemm_kernel<64,64,16,4,4><<<dim3(2,64), 256>>>(
            xi, DI, Wx, NX, xdbc, NX, NR, NX, DI, 0, 0, EP_NONE, nullptr);

        // dt = softplus(xdbc[:, :64] @ Wdt + bdt)   [4096 x 2048]
        sgemm_kernel<128,128,8,8,8><<<dim3(16,32), 256>>>(
            xdbc, NX, Wdt, DI, dt, DI, NR, DI, DTR, 0, 0, EP_SOFTPLUS, bdt);

        // selective scan + gate -> gy
        scan_kernel<<<256, 256>>>(Alog, Dp);

        // ym = gy @ Wout, (flip back for bw)   [4096 x 1024]
        sgemm_kernel<128,128,8,8,8><<<dim3(8,32), 256>>>(
            gy, DI, Wout, DM, dir ? ymb : ymf, DM, NR, DM, DI,
            0, dir, EP_NONE, nullptr);
    }

    // ycomb = LN(ymf+x) + LN(ymb+x)
    ln_dual_kernel<<<NR, 256>>>(x, fwn_w, fwn_b);

    // ffh = relu(ycomb @ W1 + b1)
    sgemm_kernel<128,128,8,8,8><<<dim3(16,32), 256>>>(
        ycomb, DM, ff_W1, DI, ffh, DI, NR, DI, DM, 0, 0, EP_RELU, ff_b1);

    // ff = ffh @ W2 + b2
    sgemm_kernel<128,128,8,8,8><<<dim3(8,32), 256>>>(
        ffh, DI, ff_W2, DM, ff, DM, NR, DM, DI, 0, 0, EP_BIAS, ff_b2);

    // out = LN(ff + ycomb)
    ln_final_kernel<<<NR, 256>>>(fin_w, fin_b, (float*)d_out);
}

// round 3
// speedup vs baseline: 1.4411x; 1.4411x over previous
#include <cuda_runtime.h>
#include <cuda_bf16.h>
#include <math.h>
#include <stdint.h>

// ---------------------------------------------------------------------------
// BiMamba on GB300 (sm_103 baseline PTX): all large GEMMs on mma.sync bf16
// (m16n8k16) with hi/lo 3-pass split for fp32-grade accuracy.
// tcgen05 is unavailable (harness PTX targets sm_103 without the 'a' feature).
// B=2, L=2048, D_MODEL=1024, D_INNER=2048, D_STATE=16, DT_RANK=64.
// ---------------------------------------------------------------------------

#define NB   2
#define SEQ  2048
#define DM   1024
#define DI   2048
#define DS   16
#define DTR  64
#define NXP  128         // padded width of xdbc (real 96)
#define NR   (NB*SEQ)    // 4096 rows
#define LN_EPS 1e-5f

#define EP_NONE     0
#define EP_SOFTPLUS 1
#define EP_RELU     2
#define EP_BIAS     3

// ---- scratch (device globals) ----------------------------------------------
__device__ float g_xz  [(size_t)NR * 2 * DI];
__device__ float g_xi  [(size_t)NR * DI];
__device__ float g_xdbc[(size_t)NR * NXP];
__device__ float g_dt  [(size_t)NR * DI];
__device__ float g_ymf [(size_t)NR * DM];
__device__ float g_ymb [(size_t)NR * DM];
__device__ float g_ycomb[(size_t)NR * DM];
__device__ float g_ffh [(size_t)NR * DI];
__device__ float g_ff  [(size_t)NR * DM];

__device__ __nv_bfloat16 g_xhi [(size_t)NR*DM],  g_xlo [(size_t)NR*DM];
__device__ __nv_bfloat16 g_xihi[(size_t)NR*DI],  g_xilo[(size_t)NR*DI];
__device__ __nv_bfloat16 g_xdhi[(size_t)NR*NXP], g_xdlo[(size_t)NR*NXP];
__device__ __nv_bfloat16 g_gyhi[(size_t)NR*DI],  g_gylo[(size_t)NR*DI];
__device__ __nv_bfloat16 g_ychi[(size_t)NR*DM],  g_yclo[(size_t)NR*DM];
__device__ __nv_bfloat16 g_fhhi[(size_t)NR*DI],  g_fhlo[(size_t)NR*DI];

// transposed weights [N][K] bf16 hi/lo
__device__ __nv_bfloat16 g_btWinH[(size_t)4096*1024], g_btWinL[(size_t)4096*1024];
__device__ __nv_bfloat16 g_btWxH [(size_t)128*2048],  g_btWxL [(size_t)128*2048];
__device__ __nv_bfloat16 g_btWdtH[(size_t)2048*64],   g_btWdtL[(size_t)2048*64];
__device__ __nv_bfloat16 g_btWoH [(size_t)1024*2048], g_btWoL [(size_t)1024*2048];
__device__ __nv_bfloat16 g_btF1H [(size_t)2048*1024], g_btF1L [(size_t)2048*1024];
__device__ __nv_bfloat16 g_btF2H [(size_t)1024*2048], g_btF2L [(size_t)1024*2048];

// ---------------------------------------------------------------------------
// helpers
// ---------------------------------------------------------------------------
__device__ __forceinline__ uint32_t smem_u32(const void* p) {
    uint32_t a;
    asm("{ .reg .u64 t; cvta.to.shared.u64 t, %1; cvt.u32.u64 %0, t; }"
        : "=r"(a) : "l"(p));
    return a;
}
__device__ __forceinline__ void ldsm4(uint32_t* r, uint32_t addr) {
    asm volatile("ldmatrix.sync.aligned.m8n8.x4.shared.b16 {%0,%1,%2,%3}, [%4];"
        : "=r"(r[0]), "=r"(r[1]), "=r"(r[2]), "=r"(r[3]) : "r"(addr));
}
__device__ __forceinline__ void mma_bf16(float* c, const uint32_t* a, const uint32_t* b) {
    asm volatile("mma.sync.aligned.m16n8k16.row.col.f32.bf16.bf16.f32 "
        "{%0,%1,%2,%3}, {%4,%5,%6,%7}, {%8,%9}, {%0,%1,%2,%3};"
        : "+f"(c[0]), "+f"(c[1]), "+f"(c[2]), "+f"(c[3])
        : "r"(a[0]), "r"(a[1]), "r"(a[2]), "r"(a[3]), "r"(b[0]), "r"(b[1]));
}
__device__ __forceinline__ void sts128(uint32_t addr, uint4 v) {
    asm volatile("st.shared.v4.b32 [%0], {%1,%2,%3,%4};"
                 :: "r"(addr), "r"(v.x), "r"(v.y), "r"(v.z), "r"(v.w) : "memory");
}
__device__ __forceinline__ int fliprow(int m) {
    return (m & ~(SEQ - 1)) | ((SEQ - 1) - (m & (SEQ - 1)));
}
__device__ __forceinline__ void split_bf16(float v, __nv_bfloat16& h, __nv_bfloat16& l) {
    h = __float2bfloat16(v);
    l = __float2bfloat16(v - __bfloat162float(h));
}

// ---------------------------------------------------------------------------
// mma.sync GEMM: C[M,N] = A[M,K] @ Bt[N,K]^T with hi/lo bf16 3-pass split.
// CTA tile 128x128, K-stage 32, 8 warps (2x4), warp tile 64x32.
// smem per stage: 4 planes (Ah, Al, Bh, Bl), each [128 rows][32+8 pad] bf16.
// ---------------------------------------------------------------------------
#define ROWB 80              // bytes per smem row (40 bf16)
#define PS   (128 * ROWB)    // plane stride   = 10240 B
#define BS   (4 * PS)        // buffer stride  = 40960 B
#define SMEM_GEMM (2 * BS)   // 81920 B

__global__ void __launch_bounds__(256)
mma_gemm(const __nv_bfloat16* __restrict__ Ahi, const __nv_bfloat16* __restrict__ Alo, int lda,
         const __nv_bfloat16* __restrict__ Bth, const __nv_bfloat16* __restrict__ Btl, int K,
         float* __restrict__ C, int ldc,
         __nv_bfloat16* __restrict__ Chi, __nv_bfloat16* __restrict__ Clo,
         int flipA, int flipC, int epi, const float* __restrict__ bias)
{
    extern __shared__ char smem[];
    const uint32_t sb = smem_u32(smem);

    const int tid  = threadIdx.x;
    const int wid  = tid >> 5, lane = tid & 31;
    const int wm   = wid >> 2, wn = wid & 3;
    const int bm   = blockIdx.y * 128;
    const int bn   = blockIdx.x * 128;

    // ---- global->smem mapping: 8 chunks of 16B per thread per stage --------
    // j: 0,1 -> A hi ; 2,3 -> A lo ; 4,5 -> B hi ; 6,7 -> B lo
    const __nv_bfloat16* src[8];
    uint32_t dst[8];
    #pragma unroll
    for (int j = 0; j < 8; ++j) {
        const int plane = j >> 1;                  // 0 Ah, 1 Al, 2 Bh, 3 Bl
        const int c     = (j & 1) * 256 + tid;     // chunk in plane 0..511
        const int row   = c >> 2;
        const int kc    = (c & 3) * 8;             // k element offset
        dst[j] = sb + plane * PS + row * ROWB + kc * 2;
        if (plane < 2) {
            int m = bm + row; if (flipA) m = fliprow(m);
            src[j] = (plane ? Alo : Ahi) + (size_t)m * lda + kc;
        } else {
            int n = bn + row;
            src[j] = ((plane == 3) ? Btl : Bth) + (size_t)n * K + kc;
        }
    }

    // ---- ldmatrix lane offsets ---------------------------------------------
    // A (m16k16 x4): row = m0 + lane%8 + ((lane>>3)&1)*8 ; col16B = lane>>4
    const uint32_t a_loff = ((lane & 7) + ((lane >> 3) & 1) * 8) * ROWB + (lane >> 4) * 16;
    // B (2 x n8k16): row = n0 + lane%8 + (lane>>4)*8 ; col16B = (lane>>3)&1
    const uint32_t b_loff = ((lane & 7) + (lane >> 4) * 8) * ROWB + ((lane >> 3) & 1) * 16;
    const uint32_t aw = sb + wm * 64 * ROWB + a_loff;            // A hi plane base
    const uint32_t bw = sb + 2 * PS + wn * 32 * ROWB + b_loff;   // B hi plane base

    float acc[4][4][4];
    #pragma unroll
    for (int mt = 0; mt < 4; ++mt)
        #pragma unroll
        for (int nt = 0; nt < 4; ++nt)
            #pragma unroll
            for (int i = 0; i < 4; ++i) acc[mt][nt][i] = 0.f;

    // ---- prologue: stage 0 --------------------------------------------------
    #pragma unroll
    for (int j = 0; j < 8; ++j)
        sts128(dst[j], *reinterpret_cast<const uint4*>(src[j]));
    __syncthreads();

    const int S = K / 32;
    for (int s = 0; s < S; ++s) {
        const uint32_t bo = (uint32_t)(s & 1) * BS;

        // prefetch next stage to registers
        uint4 v[8];
        if (s + 1 < S) {
            const int kt = (s + 1) * 32;
            #pragma unroll
            for (int j = 0; j < 8; ++j)
                v[j] = *reinterpret_cast<const uint4*>(src[j] + kt);
        }

        // compute current stage
        #pragma unroll
        for (int ks = 0; ks < 2; ++ks) {
            uint32_t bh[8], bl[8];
            ldsm4(&bh[0], bw + bo + ks * 32);
            ldsm4(&bh[4], bw + bo + 16 * ROWB + ks * 32);
            ldsm4(&bl[0], bw + PS + bo + ks * 32);
            ldsm4(&bl[4], bw + PS + bo + 16 * ROWB + ks * 32);
            #pragma unroll
            for (int mt = 0; mt < 4; ++mt) {
                uint32_t ah[4], al[4];
                ldsm4(ah, aw + bo + mt * 16 * ROWB + ks * 32);
                ldsm4(al, aw + PS + bo + mt * 16 * ROWB + ks * 32);
                #pragma unroll
                for (int nt = 0; nt < 4; ++nt) {
                    mma_bf16(acc[mt][nt], ah, &bh[nt * 2]);   // hi*hi
                    mma_bf16(acc[mt][nt], ah, &bl[nt * 2]);   // hi*lo
                    mma_bf16(acc[mt][nt], al, &bh[nt * 2]);   // lo*hi
                }
            }
        }

        if (s + 1 < S) {
            const uint32_t nbo = (uint32_t)((s + 1) & 1) * BS;
            #pragma unroll
            for (int j = 0; j < 8; ++j)
                sts128(dst[j] + nbo, v[j]);
        }
        __syncthreads();
    }

    // ---- epilogue ------------------------------------------------------------
    #pragma unroll
    for (int mt = 0; mt < 4; ++mt) {
        const int r0 = bm + wm * 64 + mt * 16 + (lane >> 2);
        #pragma unroll
        for (int half = 0; half < 2; ++half) {
            int rg = r0 + half * 8;
            const int mg = flipC ? fliprow(rg) : rg;
            float* crow = C + (size_t)mg * ldc;
            #pragma unroll
            for (int nt = 0; nt < 4; ++nt) {
                const int col = bn + wn * 32 + nt * 8 + (lane & 3) * 2;
                float v0 = acc[mt][nt][half * 2 + 0];
                float v1 = acc[mt][nt][half * 2 + 1];
                if (epi != EP_NONE) { v0 += bias[col]; v1 += bias[col + 1]; }
                if (epi == EP_SOFTPLUS) {
                    v0 = (v0 > 20.f) ? v0 : log1pf(expf(v0));
                    v1 = (v1 > 20.f) ? v1 : log1pf(expf(v1));
                } else if (epi == EP_RELU) {
                    v0 = fmaxf(v0, 0.f); v1 = fmaxf(v1, 0.f);
                }
                *reinterpret_cast<float2*>(crow + col) = make_float2(v0, v1);
                if (Chi) {
                    __nv_bfloat16 h0, l0, h1, l1;
                    split_bf16(v0, h0, l0);
                    split_bf16(v1, h1, l1);
                    __nv_bfloat162 ph; ph.x = h0; ph.y = h1;
                    __nv_bfloat162 pl; pl.x = l0; pl.y = l1;
                    *reinterpret_cast<__nv_bfloat162*>(Chi + (size_t)mg * ldc + col) = ph;
                    *reinterpret_cast<__nv_bfloat162*>(Clo + (size_t)mg * ldc + col) = pl;
                }
            }
        }
    }
}

// ---------------------------------------------------------------------------
// transpose + hi/lo convert:  W[K][N] fp32  ->  Th/Tl [Npad][K] bf16
// ---------------------------------------------------------------------------
__global__ void __launch_bounds__(256)
transpose_conv(const float* __restrict__ W, int K, int N, int Npad,
               __nv_bfloat16* __restrict__ Th, __nv_bfloat16* __restrict__ Tl)
{
    __shared__ float t[32][33];
    const int k0 = blockIdx.y * 32, n0 = blockIdx.x * 32;
    const int tx = threadIdx.x & 31, ty = threadIdx.x >> 5;   // 32 x 8
    #pragma unroll
    for (int i = 0; i < 4; ++i) {
        int k = k0 + ty + i * 8, n = n0 + tx;
        t[ty + i * 8][tx] = (n < N) ? W[(size_t)k * N + n] : 0.f;
    }
    __syncthreads();
    #pragma unroll
    for (int i = 0; i < 4; ++i) {
        int n = n0 + ty + i * 8, k = k0 + tx;
        if (n < Npad) {
            float v = t[tx][ty + i * 8];
            __nv_bfloat16 h, l; split_bf16(v, h, l);
            Th[(size_t)n * K + k] = h;
            Tl[(size_t)n * K + k] = l;
        }
    }
}

// elementwise fp32 -> hi/lo
__global__ void __launch_bounds__(256)
convert_planes(const float* __restrict__ src, __nv_bfloat16* __restrict__ h,
               __nv_bfloat16* __restrict__ l, int n)
{
    int i = blockIdx.x * 256 + threadIdx.x;
    if (i < n) { __nv_bfloat16 hh, ll; split_bf16(src[i], hh, ll); h[i] = hh; l[i] = ll; }
}

// ---------------------------------------------------------------------------
// causal dwconv(4) + SiLU -> xi (fp32 + bf16 planes)
// ---------------------------------------------------------------------------
__global__ void __launch_bounds__(256)
conv_silu_kernel(const float* __restrict__ convw, const float* __restrict__ convb)
{
    int idx = blockIdx.x * 256 + threadIdx.x;
    if (idx >= NR * DI) return;
    int d = idx % DI, n = idx / DI;
    int b = n >> 11, t = n & (SEQ - 1);
    float4 w = *reinterpret_cast<const float4*>(convw + d * 4);
    float acc = convb[d];
    const float* base = g_xz + (size_t)(b << 11) * (2 * DI) + d;
    if (t >= 3) {
        acc = fmaf(base[(size_t)(t-3)*(2*DI)], w.x, acc);
        acc = fmaf(base[(size_t)(t-2)*(2*DI)], w.y, acc);
        acc = fmaf(base[(size_t)(t-1)*(2*DI)], w.z, acc);
        acc = fmaf(base[(size_t)(t  )*(2*DI)], w.w, acc);
    } else {
        if (t-3 >= 0) acc = fmaf(base[(size_t)(t-3)*(2*DI)], w.x, acc);
        if (t-2 >= 0) acc = fmaf(base[(size_t)(t-2)*(2*DI)], w.y, acc);
        if (t-1 >= 0) acc = fmaf(base[(size_t)(t-1)*(2*DI)], w.z, acc);
        acc = fmaf(base[(size_t)t*(2*DI)], w.w, acc);
    }
    float y = acc / (1.f + expf(-acc));
    g_xi[idx] = y;
    __nv_bfloat16 h, l; split_bf16(y, h, l);
    g_xihi[idx] = h; g_xilo[idx] = l;
}

// ---------------------------------------------------------------------------
// selective scan: 16 states = 16 lanes; writes gated output as bf16 planes
// ---------------------------------------------------------------------------
__global__ void __launch_bounds__(256)
scan_kernel(const float* __restrict__ Alog, const float* __restrict__ Dpar)
{
    const int lane = threadIdx.x & 31;
    const int gw   = blockIdx.x * 8 + (threadIdx.x >> 5);
    const int half = lane >> 4;
    const int s    = lane & 15;
    const int ch   = gw * 2 + half;
    const int b    = ch >> 11;
    const int d    = ch & (DI - 1);

    const float Ac = -expf(Alog[d * DS + s]);
    const float Dp = Dpar[d];

    const size_t rowbase = (size_t)b * SEQ;
    const float* dt_p = g_dt  + rowbase * DI + d;
    const float* u_p  = g_xi  + rowbase * DI + d;
    const float* z_p  = g_xz  + rowbase * (2*DI) + DI + d;
    const float* bc_p = g_xdbc + rowbase * NXP + DTR + s;
    __nv_bfloat16* oh = g_gyhi + rowbase * DI + d;
    __nv_bfloat16* ol = g_gylo + rowbase * DI + d;

    float h = 0.f;
    for (int t = 0; t < SEQ; ++t) {
        const float dtv = dt_p[(size_t)t * DI];
        const float u   = u_p [(size_t)t * DI];
        const float Bv  = bc_p[(size_t)t * NXP];
        const float Cv  = bc_p[(size_t)t * NXP + DS];
        const float dA  = __expf(dtv * Ac);
        h = fmaf(dA, h, dtv * u * Bv);
        float p = h * Cv;
        #pragma unroll
        for (int o = 8; o; o >>= 1) p += __shfl_xor_sync(0xffffffffu, p, o);
        if (s == 0) {
            const float z = z_p[(size_t)t * (2*DI)];
            const float g = z / (1.f + __expf(-z));
            float val = (p + u * Dp) * g;
            __nv_bfloat16 hh, ll; split_bf16(val, hh, ll);
            oh[(size_t)t * DI] = hh;
            ol[(size_t)t * DI] = ll;
        }
    }
}

// ---------------------------------------------------------------------------
// layernorms
// ---------------------------------------------------------------------------
__device__ __forceinline__ float blockReduceSum(float v)
{
    __shared__ float sh[8];
    __syncthreads();
    #pragma unroll
    for (int o = 16; o; o >>= 1) v += __shfl_xor_sync(0xffffffffu, v, o);
    if ((threadIdx.x & 31) == 0) sh[threadIdx.x >> 5] = v;
    __syncthreads();
    if (threadIdx.x < 32) {
        float t = (threadIdx.x < 8) ? sh[threadIdx.x] : 0.f;
        #pragma unroll
        for (int o = 4; o; o >>= 1) t += __shfl_xor_sync(0xffffffffu, t, o);
        if (threadIdx.x == 0) sh[0] = t;
    }
    __syncthreads();
    return sh[0];
}

__global__ void __launch_bounds__(256)
ln_dual_kernel(const float* __restrict__ x,
               const float* __restrict__ w, const float* __restrict__ bs)
{
    const int row = blockIdx.x;
    const float* xr = x     + (size_t)row * DM;
    const float* fr = g_ymf + (size_t)row * DM;
    const float* br = g_ymb + (size_t)row * DM;
    float* out      = g_ycomb + (size_t)row * DM;
    __nv_bfloat16* oh = g_ychi + (size_t)row * DM;
    __nv_bfloat16* ol = g_yclo + (size_t)row * DM;

    float a[4], c[4];
    float sa = 0.f, sb = 0.f;
    #pragma unroll
    for (int i = 0; i < 4; ++i) {
        int idx = threadIdx.x + i * 256;
        float xv = xr[idx];
        a[i] = fr[idx] + xv;
        c[i] = br[idx] + xv;
        sa += a[i]; sb += c[i];
    }
    sa = blockReduceSum(sa);
    sb = blockReduceSum(sb);
    const float mua = sa * (1.f / DM), mub = sb * (1.f / DM);
    float va = 0.f, vb = 0.f;
    #pragma unroll
    for (int i = 0; i < 4; ++i) {
        float da = a[i] - mua; va += da * da;
        float db = c[i] - mub; vb += db * db;
    }
    va = blockReduceSum(va);
    vb = blockReduceSum(vb);
    const float ra = rsqrtf(va * (1.f / DM) + LN_EPS);
    const float rb = rsqrtf(vb * (1.f / DM) + LN_EPS);
    #pragma unroll
    for (int i = 0; i < 4; ++i) {
        int idx = threadIdx.x + i * 256;
        float wv = w[idx], bv = bs[idx];
        float o = ((a[i] - mua) * ra * wv + bv) + ((c[i] - mub) * rb * wv + bv);
        out[idx] = o;
        __nv_bfloat16 hh, ll; split_bf16(o, hh, ll);
        oh[idx] = hh; ol[idx] = ll;
    }
}

__global__ void __launch_bounds__(256)
ln_final_kernel(const float* __restrict__ w, const float* __restrict__ bs,
                float* __restrict__ out)
{
    const int row = blockIdx.x;
    const float* fr = g_ff    + (size_t)row * DM;
    const float* yr = g_ycomb + (size_t)row * DM;
    float* orow = out + (size_t)row * DM;

    float a[4];
    float sa = 0.f;
    #pragma unroll
    for (int i = 0; i < 4; ++i) {
        int idx = threadIdx.x + i * 256;
        a[i] = fr[idx] + yr[idx];
        sa += a[i];
    }
    sa = blockReduceSum(sa);
    const float mu = sa * (1.f / DM);
    float va = 0.f;
    #pragma unroll
    for (int i = 0; i < 4; ++i) { float d = a[i] - mu; va += d * d; }
    va = blockReduceSum(va);
    const float rs = rsqrtf(va * (1.f / DM) + LN_EPS);
    #pragma unroll
    for (int i = 0; i < 4; ++i) {
        int idx = threadIdx.x + i * 256;
        orow[idx] = (a[i] - mu) * rs * w[idx] + bs[idx];
    }
}

// ---------------------------------------------------------------------------
// launch
// ---------------------------------------------------------------------------
extern "C" void kernel_launch(void* const* d_in, const int* in_sizes, int n_in,
                              void* d_out, int out_size)
{
    (void)in_sizes; (void)n_in; (void)out_size;
    const float* x     = (const float*)d_in[0];
    const float* fwn_w = (const float*)d_in[19];
    const float* fwn_b = (const float*)d_in[20];
    const float* fin_w = (const float*)d_in[21];
    const float* fin_b = (const float*)d_in[22];
    const float* ff_W1 = (const float*)d_in[23];
    const float* ff_b1 = (const float*)d_in[24];
    const float* ff_W2 = (const float*)d_in[25];
    const float* ff_b2 = (const float*)d_in[26];

    cudaFuncSetAttribute(mma_gemm, cudaFuncAttributeMaxDynamicSharedMemorySize, SMEM_GEMM);

    float *xz, *xi, *xdbc, *dt, *ymf, *ymb, *ycomb, *ffh, *ff;
    cudaGetSymbolAddress((void**)&xz, g_xz);       cudaGetSymbolAddress((void**)&xi, g_xi);
    cudaGetSymbolAddress((void**)&xdbc, g_xdbc);   cudaGetSymbolAddress((void**)&dt, g_dt);
    cudaGetSymbolAddress((void**)&ymf, g_ymf);     cudaGetSymbolAddress((void**)&ymb, g_ymb);
    cudaGetSymbolAddress((void**)&ycomb, g_ycomb); cudaGetSymbolAddress((void**)&ffh, g_ffh);
    cudaGetSymbolAddress((void**)&ff, g_ff);

    __nv_bfloat16 *xhi,*xlo,*xihi,*xilo,*xdhi,*xdlo,*gyhi,*gylo,*ychi,*yclo,*fhhi,*fhlo;
    cudaGetSymbolAddress((void**)&xhi, g_xhi);   cudaGetSymbolAddress((void**)&xlo, g_xlo);
    cudaGetSymbolAddress((void**)&xihi, g_xihi); cudaGetSymbolAddress((void**)&xilo, g_xilo);
    cudaGetSymbolAddress((void**)&xdhi, g_xdhi); cudaGetSymbolAddress((void**)&xdlo, g_xdlo);
    cudaGetSymbolAddress((void**)&gyhi, g_gyhi); cudaGetSymbolAddress((void**)&gylo, g_gylo);
    cudaGetSymbolAddress((void**)&ychi, g_ychi); cudaGetSymbolAddress((void**)&yclo, g_yclo);
    cudaGetSymbolAddress((void**)&fhhi, g_fhhi); cudaGetSymbolAddress((void**)&fhlo, g_fhlo);

    __nv_bfloat16 *btWinH,*btWinL,*btWxH,*btWxL,*btWdtH,*btWdtL,*btWoH,*btWoL,*btF1H,*btF1L,*btF2H,*btF2L;
    cudaGetSymbolAddress((void**)&btWinH, g_btWinH); cudaGetSymbolAddress((void**)&btWinL, g_btWinL);
    cudaGetSymbolAddress((void**)&btWxH, g_btWxH);   cudaGetSymbolAddress((void**)&btWxL, g_btWxL);
    cudaGetSymbolAddress((void**)&btWdtH, g_btWdtH); cudaGetSymbolAddress((void**)&btWdtL, g_btWdtL);
    cudaGetSymbolAddress((void**)&btWoH, g_btWoH);   cudaGetSymbolAddress((void**)&btWoL, g_btWoL);
    cudaGetSymbolAddress((void**)&btF1H, g_btF1H);   cudaGetSymbolAddress((void**)&btF1L, g_btF1L);
    cudaGetSymbolAddress((void**)&btF2H, g_btF2H);   cudaGetSymbolAddress((void**)&btF2L, g_btF2L);

    // x -> bf16 planes (shared by both directions)
    convert_planes<<<(NR*DM)/256, 256>>>(x, xhi, xlo, NR*DM);

    for (int dir = 0; dir < 2; ++dir) {
        const int o = dir ? 10 : 1;
        const float* Win   = (const float*)d_in[o + 0];
        const float* convw = (const float*)d_in[o + 1];
        const float* convb = (const float*)d_in[o + 2];
        const float* Wx    = (const float*)d_in[o + 3];
        const float* Wdt   = (const float*)d_in[o + 4];
        const float* bdt   = (const float*)d_in[o + 5];
        const float* Alog  = (const float*)d_in[o + 6];
        const float* Dp    = (const float*)d_in[o + 7];
        const float* Wout  = (const float*)d_in[o + 8];

        // weight transposes (per direction; buffers reused)
        transpose_conv<<<dim3(4096/32, 1024/32), 256>>>(Win,  1024, 4096, 4096, btWinH, btWinL);
        transpose_conv<<<dim3(128/32,  2048/32), 256>>>(Wx,   2048, 96,   128,  btWxH,  btWxL);
        transpose_conv<<<dim3(2048/32, 64/32),   256>>>(Wdt,  64,   2048, 2048, btWdtH, btWdtL);
        transpose_conv<<<dim3(1024/32, 2048/32), 256>>>(Wout, 2048, 1024, 1024, btWoH,  btWoL);

        // xz = (flip?)x @ Win     [4096 x 4096], K=1024
        mma_gemm<<<dim3(4096/128, 4096/128), 256, SMEM_GEMM>>>(
            xhi, xlo, DM, btWinH, btWinL, DM,
            xz, 2*DI, nullptr, nullptr, dir, 0, EP_NONE, nullptr);

        // conv + silu -> xi (+ planes)
        conv_silu_kernel<<<(NR*DI)/256, 256>>>(convw, convb);

        // xdbc = xi @ Wx          [4096 x 128(pad)], K=2048
        mma_gemm<<<dim3(1, 4096/128), 256, SMEM_GEMM>>>(
            xihi, xilo, DI, btWxH, btWxL, DI,
            xdbc, NXP, xdhi, xdlo, 0, 0, EP_NONE, nullptr);

        // dt = softplus(xdbc[:, :64] @ Wdt + bdt)   [4096 x 2048], K=64
        mma_gemm<<<dim3(2048/128, 4096/128), 256, SMEM_GEMM>>>(
            xdhi, xdlo, NXP, btWdtH, btWdtL, DTR,
            dt, DI, nullptr, nullptr, 0, 0, EP_SOFTPLUS, bdt);

        // selective scan + gate -> gy planes
        scan_kernel<<<256, 256>>>(Alog, Dp);

        // ym = gy @ Wout (flip back for bw)   [4096 x 1024], K=2048
        mma_gemm<<<dim3(1024/128, 4096/128), 256, SMEM_GEMM>>>(
            gyhi, gylo, DI, btWoH, btWoL, DI,
            dir ? ymb : ymf, DM, nullptr, nullptr, 0, dir, EP_NONE, nullptr);
    }

    // ycomb = LN(ymf+x) + LN(ymb+x)  (+ planes)
    ln_dual_kernel<<<NR, 256>>>(x, fwn_w, fwn_b);

    // FFN
    transpose_conv<<<dim3(2048/32, 1024/32), 256>>>(ff_W1, 1024, 2048, 2048, btF1H, btF1L);
    transpose_conv<<<dim3(1024/32, 2048/32), 256>>>(ff_W2, 2048, 1024, 1024, btF2H, btF2L);

    // ffh = relu(ycomb @ W1 + b1)  [4096 x 2048], K=1024  (+ planes)
    mma_gemm<<<dim3(2048/128, 4096/128), 256, SMEM_GEMM>>>(
        ychi, yclo, DM, btF1H, btF1L, DM,
        ffh, DI, fhhi, fhlo, 0, 0, EP_RELU, ff_b1);

    // ff = ffh @ W2 + b2   [4096 x 1024], K=2048
    mma_gemm<<<dim3(1024/128, 4096/128), 256, SMEM_GEMM>>>(
        fhhi, fhlo, DI, btF2H, btF2L, DI,
        ff, DM, nullptr, nullptr, 0, 0, EP_BIAS, ff_b2);

    // out = LN(ff + ycomb)
    ln_final_kernel<<<NR, 256>>>(fin_w, fin_b, (float*)d_out);
}

// round 4
// speedup vs baseline: 1.6048x; 1.1135x over previous
#include <cuda_runtime.h>
#include <cuda_fp16.h>
#include <math.h>
#include <stdint.h>

// ---------------------------------------------------------------------------
// BiMamba on GB300 (sm_103 baseline PTX).  GEMMs: mma.sync m16n8k16 fp16 with
// weight hi/lo 2-pass split (activations single fp16), cp.async 3-stage ring.
// ---------------------------------------------------------------------------

#define NB   2
#define SEQ  2048
#define DM   1024
#define DI   2048
#define DS   16
#define DTR  64
#define NXP  128
#define NR   (NB*SEQ)
#define LN_EPS 1e-5f

#define EP_NONE     0
#define EP_SOFTPLUS 1
#define EP_RELU     2
#define EP_BIAS     3

// ---- scratch ---------------------------------------------------------------
__device__ float g_xz  [(size_t)NR * 2 * DI];
__device__ float g_xi  [(size_t)NR * DI];
__device__ float g_xdbc[(size_t)NR * NXP];
__device__ float g_dt  [(size_t)NR * DI];
__device__ float g_ymf [(size_t)NR * DM];
__device__ float g_ymb [(size_t)NR * DM];
__device__ float g_ycomb[(size_t)NR * DM];
__device__ float g_ffh [(size_t)NR * DI];
__device__ float g_ff  [(size_t)NR * DM];

// fp16 activation planes (single)
__device__ __half g_xh  [(size_t)NR*DM];
__device__ __half g_xih [(size_t)NR*DI];
__device__ __half g_xdh [(size_t)NR*NXP];
__device__ __half g_gyh [(size_t)NR*DI];
__device__ __half g_ych [(size_t)NR*DM];
__device__ __half g_fhh [(size_t)NR*DI];

// transposed weights [N][K] fp16 hi/lo
__device__ __half g_tWinH[(size_t)4096*1024], g_tWinL[(size_t)4096*1024];
__device__ __half g_tWxH [(size_t)128*2048],  g_tWxL [(size_t)128*2048];
__device__ __half g_tWdtH[(size_t)2048*64],   g_tWdtL[(size_t)2048*64];
__device__ __half g_tWoH [(size_t)1024*2048], g_tWoL [(size_t)1024*2048];
__device__ __half g_tF1H [(size_t)2048*1024], g_tF1L [(size_t)2048*1024];
__device__ __half g_tF2H [(size_t)1024*2048], g_tF2L [(size_t)1024*2048];

// ---------------------------------------------------------------------------
// helpers
// ---------------------------------------------------------------------------
__device__ __forceinline__ uint32_t smem_u32(const void* p) {
    uint32_t a;
    asm("{ .reg .u64 t; cvta.to.shared.u64 t, %1; cvt.u32.u64 %0, t; }"
        : "=r"(a) : "l"(p));
    return a;
}
__device__ __forceinline__ void ldsm4(uint32_t* r, uint32_t addr) {
    asm volatile("ldmatrix.sync.aligned.m8n8.x4.shared.b16 {%0,%1,%2,%3}, [%4];"
        : "=r"(r[0]), "=r"(r[1]), "=r"(r[2]), "=r"(r[3]) : "r"(addr));
}
__device__ __forceinline__ void mma_f16(float* c, const uint32_t* a, const uint32_t* b) {
    asm volatile("mma.sync.aligned.m16n8k16.row.col.f32.f16.f16.f32 "
        "{%0,%1,%2,%3}, {%4,%5,%6,%7}, {%8,%9}, {%0,%1,%2,%3};"
        : "+f"(c[0]), "+f"(c[1]), "+f"(c[2]), "+f"(c[3])
        : "r"(a[0]), "r"(a[1]), "r"(a[2]), "r"(a[3]), "r"(b[0]), "r"(b[1]));
}
__device__ __forceinline__ void cp16(uint32_t dst, const void* src) {
    asm volatile("{ .reg .u64 g; cvta.to.global.u64 g, %1; "
                 "cp.async.cg.shared.global [%0], [g], 16; }"
                 :: "r"(dst), "l"(src) : "memory");
}
#define CP_COMMIT() asm volatile("cp.async.commit_group;" ::: "memory")
#define CP_WAIT1()  asm volatile("cp.async.wait_group 1;" ::: "memory")

__device__ __forceinline__ int fliprow(int m) {
    return (m & ~(SEQ - 1)) | ((SEQ - 1) - (m & (SEQ - 1)));
}
__device__ __forceinline__ void split_h(float v, __half& h, __half& l) {
    h = __float2half_rn(v);
    l = __float2half_rn(v - __half2float(h));
}

// ---------------------------------------------------------------------------
// GEMM: C[M,N] = A[M,K] @ (Bh+Bl)[N,K]^T.   A fp16 single, B fp16 hi/lo.
// CTA 128x128, 8 warps (2x4), warp 64x32, K-stage 32, cp.async 3-stage ring.
// smem stage: plane A (128 rows) | Bh (128) | Bl (128), row = 32 fp16 + pad.
// ---------------------------------------------------------------------------
#define ROWB  80               // bytes per row (32 fp16 = 64B data + 16B pad)
#define PLANE (128 * ROWB)     // 10240
#define STG   (3 * PLANE)      // 30720 per stage
#define NSTAGE 3
#define SMEM_GEMM (NSTAGE * STG)   // 92160

__global__ void __launch_bounds__(256, 2)
mma_gemm(const __half* __restrict__ Aa, int lda,
         const __half* __restrict__ Bth, const __half* __restrict__ Btl, int K,
         float* __restrict__ C, int ldc, __half* __restrict__ Ch,
         int flipA, int flipC, int epi, const float* __restrict__ bias)
{
    extern __shared__ char smem[];
    const uint32_t sb = smem_u32(smem);

    const int tid  = threadIdx.x;
    const int wid  = tid >> 5, lane = tid & 31;
    const int wm   = wid >> 2, wn = wid & 3;
    const int bm   = blockIdx.y * 128;
    const int bn   = blockIdx.x * 128;

    // ---- cp.async mapping: 6 chunks of 16B per thread per stage ------------
    // chunk c in [0,1536): plane = c>>9 (0 A, 1 Bh, 2 Bl), row = (c>>2)&127,
    // 16B sub = c&3.
    const __half* src[6];
    uint32_t dst0[6];
    #pragma unroll
    for (int j = 0; j < 6; ++j) {
        const int c = j * 256 + tid;
        const int plane = c >> 9;
        const int r = (c >> 2) & 127;
        const int q = c & 3;
        dst0[j] = sb + plane * PLANE + r * ROWB + q * 16;
        if (plane == 0) {
            int m = bm + r; if (flipA) m = fliprow(m);
            src[j] = Aa + (size_t)m * lda + q * 8;
        } else {
            src[j] = ((plane == 2) ? Btl : Bth) + (size_t)(bn + r) * K + q * 8;
        }
    }

    // ---- ldmatrix lane offsets ----------------------------------------------
    const uint32_t a_loff = ((lane & 7) + ((lane >> 3) & 1) * 8) * ROWB + (lane >> 4) * 16;
    const uint32_t b_loff = ((lane & 7) + (lane >> 4) * 8) * ROWB + ((lane >> 3) & 1) * 16;
    const uint32_t aw = wm * 64 * ROWB + a_loff;
    const uint32_t bw = PLANE + wn * 32 * ROWB + b_loff;

    float acc[4][4][4];
    #pragma unroll
    for (int mt = 0; mt < 4; ++mt)
        #pragma unroll
        for (int nt = 0; nt < 4; ++nt)
            #pragma unroll
            for (int i = 0; i < 4; ++i) acc[mt][nt][i] = 0.f;

    const int S = K / 32;

    // prologue: stages 0 .. NSTAGE-2
    int ns = 0;
    #pragma unroll
    for (int p = 0; p < NSTAGE - 1; ++p) {
        if (p < S) {
            const uint32_t so = (uint32_t)p * STG;
            #pragma unroll
            for (int j = 0; j < 6; ++j) cp16(dst0[j] + so, src[j] + p * 32);
            ++ns;
        }
        CP_COMMIT();
    }

    for (int s = 0; s < S; ++s) {
        CP_WAIT1();
        __syncthreads();

        // issue stage s+2 (writes buffer (s+2)%3 — disjoint from s, s+1)
        if (ns < S) {
            const uint32_t so = (uint32_t)(ns % NSTAGE) * STG;
            const int kt = ns * 32;
            #pragma unroll
            for (int j = 0; j < 6; ++j) cp16(dst0[j] + so, src[j] + kt);
            ++ns;
        }
        CP_COMMIT();

        // compute stage s
        const uint32_t bo = sb + (uint32_t)(s % NSTAGE) * STG;
        #pragma unroll
        for (int ks = 0; ks < 2; ++ks) {
            uint32_t bh[8], bl[8];
            ldsm4(&bh[0], bo + bw + ks * 32);
            ldsm4(&bh[4], bo + bw + 16 * ROWB + ks * 32);
            ldsm4(&bl[0], bo + bw + PLANE + ks * 32);
            ldsm4(&bl[4], bo + bw + PLANE + 16 * ROWB + ks * 32);
            #pragma unroll
            for (int mt = 0; mt < 4; ++mt) {
                uint32_t a[4];
                ldsm4(a, bo + aw + mt * 16 * ROWB + ks * 32);
                #pragma unroll
                for (int nt = 0; nt < 4; ++nt) mma_f16(acc[mt][nt], a, &bh[nt * 2]);
                #pragma unroll
                for (int nt = 0; nt < 4; ++nt) mma_f16(acc[mt][nt], a, &bl[nt * 2]);
            }
        }
    }

    // ---- epilogue -------------------------------------------------------------
    #pragma unroll
    for (int mt = 0; mt < 4; ++mt) {
        const int r0 = bm + wm * 64 + mt * 16 + (lane >> 2);
        #pragma unroll
        for (int half = 0; half < 2; ++half) {
            const int rg = r0 + half * 8;
            const int mg = flipC ? fliprow(rg) : rg;
            float* crow = C + (size_t)mg * ldc;
            #pragma unroll
            for (int nt = 0; nt < 4; ++nt) {
                const int col = bn + wn * 32 + nt * 8 + (lane & 3) * 2;
                float v0 = acc[mt][nt][half * 2 + 0];
                float v1 = acc[mt][nt][half * 2 + 1];
                if (epi != EP_NONE) { v0 += bias[col]; v1 += bias[col + 1]; }
                if (epi == EP_SOFTPLUS) {
                    v0 = (v0 > 20.f) ? v0 : log1pf(expf(v0));
                    v1 = (v1 > 20.f) ? v1 : log1pf(expf(v1));
                } else if (epi == EP_RELU) {
                    v0 = fmaxf(v0, 0.f); v1 = fmaxf(v1, 0.f);
                }
                *reinterpret_cast<float2*>(crow + col) = make_float2(v0, v1);
                if (Ch) {
                    __half2 p; p.x = __float2half_rn(v0); p.y = __float2half_rn(v1);
                    *reinterpret_cast<__half2*>(Ch + (size_t)mg * ldc + col) = p;
                }
            }
        }
    }
}

// ---------------------------------------------------------------------------
// transpose + hi/lo fp16:  W[K][N] fp32 -> Th/Tl [Npad][K]
// ---------------------------------------------------------------------------
__global__ void __launch_bounds__(256)
transpose_conv(const float* __restrict__ W, int K, int N, int Npad,
               __half* __restrict__ Th, __half* __restrict__ Tl)
{
    __shared__ float t[32][33];
    const int k0 = blockIdx.y * 32, n0 = blockIdx.x * 32;
    const int tx = threadIdx.x & 31, ty = threadIdx.x >> 5;
    #pragma unroll
    for (int i = 0; i < 4; ++i) {
        int k = k0 + ty + i * 8, n = n0 + tx;
        t[ty + i * 8][tx] = (n < N) ? W[(size_t)k * N + n] : 0.f;
    }
    __syncthreads();
    #pragma unroll
    for (int i = 0; i < 4; ++i) {
        int n = n0 + ty + i * 8, k = k0 + tx;
        if (n < Npad) {
            __half h, l; split_h(t[tx][ty + i * 8], h, l);
            Th[(size_t)n * K + k] = h;
            Tl[(size_t)n * K + k] = l;
        }
    }
}

__global__ void __launch_bounds__(256)
convert_h(const float* __restrict__ src, __half* __restrict__ h, int n)
{
    int i = blockIdx.x * 256 + threadIdx.x;
    if (i < n) h[i] = __float2half_rn(src[i]);
}

// ---------------------------------------------------------------------------
// causal dwconv(4) + SiLU
// ---------------------------------------------------------------------------
__global__ void __launch_bounds__(256)
conv_silu_kernel(const float* __restrict__ convw, const float* __restrict__ convb)
{
    int idx = blockIdx.x * 256 + threadIdx.x;
    if (idx >= NR * DI) return;
    int d = idx % DI, n = idx / DI;
    int b = n >> 11, t = n & (SEQ - 1);
    float4 w = *reinterpret_cast<const float4*>(convw + d * 4);
    float acc = convb[d];
    const float* base = g_xz + (size_t)(b << 11) * (2 * DI) + d;
    if (t >= 3) {
        acc = fmaf(base[(size_t)(t-3)*(2*DI)], w.x, acc);
        acc = fmaf(base[(size_t)(t-2)*(2*DI)], w.y, acc);
        acc = fmaf(base[(size_t)(t-1)*(2*DI)], w.z, acc);
        acc = fmaf(base[(size_t)(t  )*(2*DI)], w.w, acc);
    } else {
        if (t-3 >= 0) acc = fmaf(base[(size_t)(t-3)*(2*DI)], w.x, acc);
        if (t-2 >= 0) acc = fmaf(base[(size_t)(t-2)*(2*DI)], w.y, acc);
        if (t-1 >= 0) acc = fmaf(base[(size_t)(t-1)*(2*DI)], w.z, acc);
        acc = fmaf(base[(size_t)t*(2*DI)], w.w, acc);
    }
    float y = acc / (1.f + expf(-acc));
    g_xi[idx]  = y;
    g_xih[idx] = __float2half_rn(y);
}

// ---------------------------------------------------------------------------
// selective scan
// ---------------------------------------------------------------------------
__global__ void __launch_bounds__(256)
scan_kernel(const float* __restrict__ Alog, const float* __restrict__ Dpar)
{
    const int lane = threadIdx.x & 31;
    const int gw   = blockIdx.x * 8 + (threadIdx.x >> 5);
    const int half = lane >> 4;
    const int s    = lane & 15;
    const int ch   = gw * 2 + half;
    const int b    = ch >> 11;
    const int d    = ch & (DI - 1);

    const float Ac = -expf(Alog[d * DS + s]);
    const float Dp = Dpar[d];

    const size_t rowbase = (size_t)b * SEQ;
    const float* dt_p = g_dt  + rowbase * DI + d;
    const float* u_p  = g_xi  + rowbase * DI + d;
    const float* z_p  = g_xz  + rowbase * (2*DI) + DI + d;
    const float* bc_p = g_xdbc + rowbase * NXP + DTR + s;
    __half*      o_p  = g_gyh + rowbase * DI + d;

    float h = 0.f;
    for (int t = 0; t < SEQ; ++t) {
        const float dtv = dt_p[(size_t)t * DI];
        const float u   = u_p [(size_t)t * DI];
        const float Bv  = bc_p[(size_t)t * NXP];
        const float Cv  = bc_p[(size_t)t * NXP + DS];
        const float dA  = __expf(dtv * Ac);
        h = fmaf(dA, h, dtv * u * Bv);
        float p = h * Cv;
        #pragma unroll
        for (int o = 8; o; o >>= 1) p += __shfl_xor_sync(0xffffffffu, p, o);
        if (s == 0) {
            const float z = z_p[(size_t)t * (2*DI)];
            const float g = z / (1.f + __expf(-z));
            o_p[(size_t)t * DI] = __float2half_rn((p + u * Dp) * g);
        }
    }
}

// ---------------------------------------------------------------------------
// layernorms
// ---------------------------------------------------------------------------
__device__ __forceinline__ float blockReduceSum(float v)
{
    __shared__ float sh[8];
    __syncthreads();
    #pragma unroll
    for (int o = 16; o; o >>= 1) v += __shfl_xor_sync(0xffffffffu, v, o);
    if ((threadIdx.x & 31) == 0) sh[threadIdx.x >> 5] = v;
    __syncthreads();
    if (threadIdx.x < 32) {
        float t = (threadIdx.x < 8) ? sh[threadIdx.x] : 0.f;
        #pragma unroll
        for (int o = 4; o; o >>= 1) t += __shfl_xor_sync(0xffffffffu, t, o);
        if (threadIdx.x == 0) sh[0] = t;
    }
    __syncthreads();
    return sh[0];
}

__global__ void __launch_bounds__(256)
ln_dual_kernel(const float* __restrict__ x,
               const float* __restrict__ w, const float* __restrict__ bs)
{
    const int row = blockIdx.x;
    const float* xr = x     + (size_t)row * DM;
    const float* fr = g_ymf + (size_t)row * DM;
    const float* br = g_ymb + (size_t)row * DM;
    float* out      = g_ycomb + (size_t)row * DM;
    __half* oh      = g_ych   + (size_t)row * DM;

    float a[4], c[4];
    float sa = 0.f, sb = 0.f;
    #pragma unroll
    for (int i = 0; i < 4; ++i) {
        int idx = threadIdx.x + i * 256;
        float xv = xr[idx];
        a[i] = fr[idx] + xv;
        c[i] = br[idx] + xv;
        sa += a[i]; sb += c[i];
    }
    sa = blockReduceSum(sa);
    sb = blockReduceSum(sb);
    const float mua = sa * (1.f / DM), mub = sb * (1.f / DM);
    float va = 0.f, vb = 0.f;
    #pragma unroll
    for (int i = 0; i < 4; ++i) {
        float da = a[i] - mua; va += da * da;
        float db = c[i] - mub; vb += db * db;
    }
    va = blockReduceSum(va);
    vb = blockReduceSum(vb);
    const float ra = rsqrtf(va * (1.f / DM) + LN_EPS);
    const float rb = rsqrtf(vb * (1.f / DM) + LN_EPS);
    #pragma unroll
    for (int i = 0; i < 4; ++i) {
        int idx = threadIdx.x + i * 256;
        float wv = w[idx], bv = bs[idx];
        float o = ((a[i] - mua) * ra * wv + bv) + ((c[i] - mub) * rb * wv + bv);
        out[idx] = o;
        oh[idx]  = __float2half_rn(o);
    }
}

__global__ void __launch_bounds__(256)
ln_final_kernel(const float* __restrict__ w, const float* __restrict__ bs,
                float* __restrict__ out)
{
    const int row = blockIdx.x;
    const float* fr = g_ff    + (size_t)row * DM;
    const float* yr = g_ycomb + (size_t)row * DM;
    float* orow = out + (size_t)row * DM;

    float a[4];
    float sa = 0.f;
    #pragma unroll
    for (int i = 0; i < 4; ++i) {
        int idx = threadIdx.x + i * 256;
        a[i] = fr[idx] + yr[idx];
        sa += a[i];
    }
    sa = blockReduceSum(sa);
    const float mu = sa * (1.f / DM);
    float va = 0.f;
    #pragma unroll
    for (int i = 0; i < 4; ++i) { float d = a[i] - mu; va += d * d; }
    va = blockReduceSum(va);
    const float rs = rsqrtf(va * (1.f / DM) + LN_EPS);
    #pragma unroll
    for (int i = 0; i < 4; ++i) {
        int idx = threadIdx.x + i * 256;
        orow[idx] = (a[i] - mu) * rs * w[idx] + bs[idx];
    }
}

// ---------------------------------------------------------------------------
// launch
// ---------------------------------------------------------------------------
extern "C" void kernel_launch(void* const* d_in, const int* in_sizes, int n_in,
                              void* d_out, int out_size)
{
    (void)in_sizes; (void)n_in; (void)out_size;
    const float* x     = (const float*)d_in[0];
    const float* fwn_w = (const float*)d_in[19];
    const float* fwn_b = (const float*)d_in[20];
    const float* fin_w = (const float*)d_in[21];
    const float* fin_b = (const float*)d_in[22];
    const float* ff_W1 = (const float*)d_in[23];
    const float* ff_b1 = (const float*)d_in[24];
    const float* ff_W2 = (const float*)d_in[25];
    const float* ff_b2 = (const float*)d_in[26];

    cudaFuncSetAttribute(mma_gemm, cudaFuncAttributeMaxDynamicSharedMemorySize, SMEM_GEMM);

    float *xz, *xi, *xdbc, *dt, *ymf, *ymb, *ycomb, *ffh, *ff;
    cudaGetSymbolAddress((void**)&xz, g_xz);       cudaGetSymbolAddress((void**)&xi, g_xi);
    cudaGetSymbolAddress((void**)&xdbc, g_xdbc);   cudaGetSymbolAddress((void**)&dt, g_dt);
    cudaGetSymbolAddress((void**)&ymf, g_ymf);     cudaGetSymbolAddress((void**)&ymb, g_ymb);
    cudaGetSymbolAddress((void**)&ycomb, g_ycomb); cudaGetSymbolAddress((void**)&ffh, g_ffh);
    cudaGetSymbolAddress((void**)&ff, g_ff);

    __half *xh, *xih, *xdh, *gyh, *ych, *fhh;
    cudaGetSymbolAddress((void**)&xh, g_xh);   cudaGetSymbolAddress((void**)&xih, g_xih);
    cudaGetSymbolAddress((void**)&xdh, g_xdh); cudaGetSymbolAddress((void**)&gyh, g_gyh);
    cudaGetSymbolAddress((void**)&ych, g_ych); cudaGetSymbolAddress((void**)&fhh, g_fhh);

    __half *tWinH,*tWinL,*tWxH,*tWxL,*tWdtH,*tWdtL,*tWoH,*tWoL,*tF1H,*tF1L,*tF2H,*tF2L;
    cudaGetSymbolAddress((void**)&tWinH, g_tWinH); cudaGetSymbolAddress((void**)&tWinL, g_tWinL);
    cudaGetSymbolAddress((void**)&tWxH, g_tWxH);   cudaGetSymbolAddress((void**)&tWxL, g_tWxL);
    cudaGetSymbolAddress((void**)&tWdtH, g_tWdtH); cudaGetSymbolAddress((void**)&tWdtL, g_tWdtL);
    cudaGetSymbolAddress((void**)&tWoH, g_tWoH);   cudaGetSymbolAddress((void**)&tWoL, g_tWoL);
    cudaGetSymbolAddress((void**)&tF1H, g_tF1H);   cudaGetSymbolAddress((void**)&tF1L, g_tF1L);
    cudaGetSymbolAddress((void**)&tF2H, g_tF2H);   cudaGetSymbolAddress((void**)&tF2L, g_tF2L);

    for (int dir = 0; dir < 2; ++dir) {
        const int o = dir ? 10 : 1;
        const float* Win   = (const float*)d_in[o + 0];
        const float* convw = (const float*)d_in[o + 1];
        const float* convb = (const float*)d_in[o + 2];
        const float* Wx    = (const float*)d_in[o + 3];
        const float* Wdt   = (const float*)d_in[o + 4];
        const float* bdt   = (const float*)d_in[o + 5];
        const float* Alog  = (const float*)d_in[o + 6];
        const float* Dp    = (const float*)d_in[o + 7];
        const float* Wout  = (const float*)d_in[o + 8];

        if (dir == 0)
            convert_h<<<(NR*DM)/256, 256>>>(x, xh, NR*DM);        // launch 1

        transpose_conv<<<dim3(4096/32, 1024/32), 256>>>(Win,  1024, 4096, 4096, tWinH, tWinL);
        transpose_conv<<<dim3(128/32,  2048/32), 256>>>(Wx,   2048, 96,   128,  tWxH,  tWxL);
        transpose_conv<<<dim3(2048/32, 64/32),   256>>>(Wdt,  64,   2048, 2048, tWdtH, tWdtL);

        // xz = (flip?)x @ Win   [4096 x 4096], K=1024     <- 5th launch (profiled)
        mma_gemm<<<dim3(32, 32), 256, SMEM_GEMM>>>(
            xh, DM, tWinH, tWinL, DM,
            xz, 2*DI, nullptr, dir, 0, EP_NONE, nullptr);

        transpose_conv<<<dim3(1024/32, 2048/32), 256>>>(Wout, 2048, 1024, 1024, tWoH, tWoL);

        conv_silu_kernel<<<(NR*DI)/256, 256>>>(convw, convb);

        // xdbc = xi @ Wx   [4096 x 128], K=2048
        mma_gemm<<<dim3(1, 32), 256, SMEM_GEMM>>>(
            xih, DI, tWxH, tWxL, DI,
            xdbc, NXP, xdh, 0, 0, EP_NONE, nullptr);

        // dt = softplus(xdbc[:, :64] @ Wdt + bdt)   [4096 x 2048], K=64
        mma_gemm<<<dim3(16, 32), 256, SMEM_GEMM>>>(
            xdh, NXP, tWdtH, tWdtL, DTR,
            dt, DI, nullptr, 0, 0, EP_SOFTPLUS, bdt);

        scan_kernel<<<256, 256>>>(Alog, Dp);

        // ym = gy @ Wout   [4096 x 1024], K=2048
        mma_gemm<<<dim3(8, 32), 256, SMEM_GEMM>>>(
            gyh, DI, tWoH, tWoL, DI,
            dir ? ymb : ymf, DM, nullptr, 0, dir, EP_NONE, nullptr);
    }

    ln_dual_kernel<<<NR, 256>>>(x, fwn_w, fwn_b);

    transpose_conv<<<dim3(2048/32, 1024/32), 256>>>(ff_W1, 1024, 2048, 2048, tF1H, tF1L);
    transpose_conv<<<dim3(1024/32, 2048/32), 256>>>(ff_W2, 2048, 1024, 1024, tF2H, tF2L);

    // ffh = relu(ycomb @ W1 + b1)   [4096 x 2048], K=1024
    mma_gemm<<<dim3(16, 32), 256, SMEM_GEMM>>>(
        ych, DM, tF1H, tF1L, DM,
        ffh, DI, fhh, 0, 0, EP_RELU, ff_b1);

    // ff = ffh @ W2 + b2   [4096 x 1024], K=2048
    mma_gemm<<<dim3(8, 32), 256, SMEM_GEMM>>>(
        fhh, DI, tF2H, tF2L, DI,
        ff, DM, nullptr, 0, 0, EP_BIAS, ff_b2);

    ln_final_kernel<<<NR, 256>>>(fin_w, fin_b, (float*)d_out);
}

// round 5
// speedup vs baseline: 3.2338x; 2.0151x over previous
#include <cuda_runtime.h>
#include <cuda_fp16.h>
#include <math.h>
#include <stdint.h>

// ---------------------------------------------------------------------------
// BiMamba on GB300 (sm_103 baseline PTX).  Both directions fused into one
// batched pipeline (M=8192 GEMMs, per-half weights).  GEMMs: mma.sync
// m16n8k16 fp16, weight hi/lo 2-pass split, cp.async 3-stage ring.
// ---------------------------------------------------------------------------

#define NB   2
#define SEQ  2048
#define DM   1024
#define DI   2048
#define DS   16
#define DTR  64
#define NXP  128
#define NR   (NB*SEQ)        // 4096 rows per direction
#define NR2  (2*NR)          // 8192 combined rows
#define LN_EPS 1e-5f

#define EP_NONE     0
#define EP_SOFTPLUS 1
#define EP_RELU     2
#define EP_BIAS     3

// ---- scratch ---------------------------------------------------------------
__device__ float g_xz  [(size_t)NR2 * 2 * DI];    // 128 MB
__device__ float g_xi  [(size_t)NR2 * DI];        // 64 MB
__device__ float g_xdbc[(size_t)NR2 * NXP];
__device__ float g_dt  [(size_t)NR2 * DI];        // 64 MB
__device__ float g_ym  [(size_t)NR2 * DM];        // fw rows 0..4095, bw rows 4096..8191 (flip-stored)
__device__ float g_ycomb[(size_t)NR * DM];
__device__ float g_ffh [(size_t)NR * DI];
__device__ float g_ff  [(size_t)NR * DM];

// fp16 activation planes
__device__ __half g_xh  [(size_t)NR*DM];
__device__ __half g_xih [(size_t)NR2*DI];
__device__ __half g_xdh [(size_t)NR2*NXP];
__device__ __half g_gyh [(size_t)NR2*DI];
__device__ __half g_ych [(size_t)NR*DM];
__device__ __half g_fhh [(size_t)NR*DI];

// transposed weights [N][K] fp16 hi/lo, per direction where needed
__device__ __half g_tWinH0[(size_t)4096*1024], g_tWinL0[(size_t)4096*1024];
__device__ __half g_tWinH1[(size_t)4096*1024], g_tWinL1[(size_t)4096*1024];
__device__ __half g_tWxH0 [(size_t)128*2048],  g_tWxL0 [(size_t)128*2048];
__device__ __half g_tWxH1 [(size_t)128*2048],  g_tWxL1 [(size_t)128*2048];
__device__ __half g_tWdtH0[(size_t)2048*64],   g_tWdtL0[(size_t)2048*64];
__device__ __half g_tWdtH1[(size_t)2048*64],   g_tWdtL1[(size_t)2048*64];
__device__ __half g_tWoH0 [(size_t)1024*2048], g_tWoL0 [(size_t)1024*2048];
__device__ __half g_tWoH1 [(size_t)1024*2048], g_tWoL1 [(size_t)1024*2048];
__device__ __half g_tF1H  [(size_t)2048*1024], g_tF1L  [(size_t)2048*1024];
__device__ __half g_tF2H  [(size_t)1024*2048], g_tF2L  [(size_t)1024*2048];

// ---------------------------------------------------------------------------
// helpers
// ---------------------------------------------------------------------------
__device__ __forceinline__ uint32_t smem_u32(const void* p) {
    uint32_t a;
    asm("{ .reg .u64 t; cvta.to.shared.u64 t, %1; cvt.u32.u64 %0, t; }"
        : "=r"(a) : "l"(p));
    return a;
}
__device__ __forceinline__ void ldsm4(uint32_t* r, uint32_t addr) {
    asm volatile("ldmatrix.sync.aligned.m8n8.x4.shared.b16 {%0,%1,%2,%3}, [%4];"
        : "=r"(r[0]), "=r"(r[1]), "=r"(r[2]), "=r"(r[3]) : "r"(addr));
}
__device__ __forceinline__ void mma_f16(float* c, const uint32_t* a, const uint32_t* b) {
    asm volatile("mma.sync.aligned.m16n8k16.row.col.f32.f16.f16.f32 "
        "{%0,%1,%2,%3}, {%4,%5,%6,%7}, {%8,%9}, {%0,%1,%2,%3};"
        : "+f"(c[0]), "+f"(c[1]), "+f"(c[2]), "+f"(c[3])
        : "r"(a[0]), "r"(a[1]), "r"(a[2]), "r"(a[3]), "r"(b[0]), "r"(b[1]));
}
__device__ __forceinline__ void cp16(uint32_t dst, const void* src) {
    asm volatile("{ .reg .u64 g; cvta.to.global.u64 g, %1; "
                 "cp.async.cg.shared.global [%0], [g], 16; }"
                 :: "r"(dst), "l"(src) : "memory");
}
#define CP_COMMIT() asm volatile("cp.async.commit_group;" ::: "memory")
#define CP_WAIT1()  asm volatile("cp.async.wait_group 1;" ::: "memory")

__device__ __forceinline__ int fliprow(int m) {            // flip t within (b,t)
    return (m & ~(SEQ - 1)) | ((SEQ - 1) - (m & (SEQ - 1)));
}
__device__ __forceinline__ void split_h(float v, __half& h, __half& l) {
    h = __float2half_rn(v);
    l = __float2half_rn(v - __half2float(h));
}

// ---------------------------------------------------------------------------
// GEMM: C[M,N] = A[M,K] @ (Bh+Bl)[N,K]^T, fp16 A, fp16 hi/lo B (2-pass).
// Dual-weight mode: rows >= mhalf use {B2,bias2}; flipA2 flips A source rows
// of the second half (within 4096-row block); flipC2 flip-stores second half.
// CTA 128x128, 8 warps, K-stage 32, cp.async 3-stage ring.
// ---------------------------------------------------------------------------
#define ROWB  80
#define PLANE (128 * ROWB)
#define STG   (3 * PLANE)
#define NSTAGE 3
#define SMEM_GEMM (NSTAGE * STG)

__global__ void __launch_bounds__(256, 2)
mma_gemm(const __half* __restrict__ Aa, int lda,
         const __half* __restrict__ B1h, const __half* __restrict__ B1l,
         const __half* __restrict__ B2h, const __half* __restrict__ B2l, int K,
         float* __restrict__ C, int ldc, __half* __restrict__ Ch,
         int mhalf, int flipA2, int flipC2,
         int epi, const float* __restrict__ bias1, const float* __restrict__ bias2)
{
    extern __shared__ char smem[];
    const uint32_t sb = smem_u32(smem);

    const int tid  = threadIdx.x;
    const int wid  = tid >> 5, lane = tid & 31;
    const int wm   = wid >> 2, wn = wid & 3;
    const int bm   = blockIdx.y * 128;
    const int bn   = blockIdx.x * 128;

    const int half2 = (mhalf > 0) && (bm >= mhalf);
    const __half* Bth = half2 ? B2h : B1h;
    const __half* Btl = half2 ? B2l : B1l;
    const float*  bias = half2 ? bias2 : bias1;

    // cp.async mapping: 6 x 16B chunks per thread per stage
    const __half* src[6];
    uint32_t dst0[6];
    #pragma unroll
    for (int j = 0; j < 6; ++j) {
        const int c = j * 256 + tid;
        const int plane = c >> 9;
        const int r = (c >> 2) & 127;
        const int q = c & 3;
        dst0[j] = sb + plane * PLANE + r * ROWB + q * 16;
        if (plane == 0) {
            int m = bm + r;
            if (half2 && flipA2) m = fliprow(m & (mhalf - 1));
            src[j] = Aa + (size_t)m * lda + q * 8;
        } else {
            src[j] = ((plane == 2) ? Btl : Bth) + (size_t)(bn + r) * K + q * 8;
        }
    }

    const uint32_t a_loff = ((lane & 7) + ((lane >> 3) & 1) * 8) * ROWB + (lane >> 4) * 16;
    const uint32_t b_loff = ((lane & 7) + (lane >> 4) * 8) * ROWB + ((lane >> 3) & 1) * 16;
    const uint32_t aw = wm * 64 * ROWB + a_loff;
    const uint32_t bw = PLANE + wn * 32 * ROWB + b_loff;

    float acc[4][4][4];
    #pragma unroll
    for (int mt = 0; mt < 4; ++mt)
        #pragma unroll
        for (int nt = 0; nt < 4; ++nt)
            #pragma unroll
            for (int i = 0; i < 4; ++i) acc[mt][nt][i] = 0.f;

    const int S = K / 32;
    int ns = 0;
    #pragma unroll
    for (int p = 0; p < NSTAGE - 1; ++p) {
        if (p < S) {
            const uint32_t so = (uint32_t)p * STG;
            #pragma unroll
            for (int j = 0; j < 6; ++j) cp16(dst0[j] + so, src[j] + p * 32);
            ++ns;
        }
        CP_COMMIT();
    }

    for (int s = 0; s < S; ++s) {
        CP_WAIT1();
        __syncthreads();

        if (ns < S) {
            const uint32_t so = (uint32_t)(ns % NSTAGE) * STG;
            const int kt = ns * 32;
            #pragma unroll
            for (int j = 0; j < 6; ++j) cp16(dst0[j] + so, src[j] + kt);
            ++ns;
        }
        CP_COMMIT();

        const uint32_t bo = sb + (uint32_t)(s % NSTAGE) * STG;
        #pragma unroll
        for (int ks = 0; ks < 2; ++ks) {
            uint32_t bh[8], bl[8];
            ldsm4(&bh[0], bo + bw + ks * 32);
            ldsm4(&bh[4], bo + bw + 16 * ROWB + ks * 32);
            ldsm4(&bl[0], bo + bw + PLANE + ks * 32);
            ldsm4(&bl[4], bo + bw + PLANE + 16 * ROWB + ks * 32);
            #pragma unroll
            for (int mt = 0; mt < 4; ++mt) {
                uint32_t a[4];
                ldsm4(a, bo + aw + mt * 16 * ROWB + ks * 32);
                #pragma unroll
                for (int nt = 0; nt < 4; ++nt) mma_f16(acc[mt][nt], a, &bh[nt * 2]);
                #pragma unroll
                for (int nt = 0; nt < 4; ++nt) mma_f16(acc[mt][nt], a, &bl[nt * 2]);
            }
        }
    }

    // epilogue
    #pragma unroll
    for (int mt = 0; mt < 4; ++mt) {
        const int r0 = bm + wm * 64 + mt * 16 + (lane >> 2);
        #pragma unroll
        for (int half = 0; half < 2; ++half) {
            const int rg = r0 + half * 8;
            int mg = rg;
            if (half2 && flipC2) mg = mhalf + fliprow(rg & (mhalf - 1));
            float* crow = C + (size_t)mg * ldc;
            #pragma unroll
            for (int nt = 0; nt < 4; ++nt) {
                const int col = bn + wn * 32 + nt * 8 + (lane & 3) * 2;
                float v0 = acc[mt][nt][half * 2 + 0];
                float v1 = acc[mt][nt][half * 2 + 1];
                if (epi != EP_NONE) { v0 += bias[col]; v1 += bias[col + 1]; }
                if (epi == EP_SOFTPLUS) {
                    v0 = (v0 > 20.f) ? v0 : log1pf(expf(v0));
                    v1 = (v1 > 20.f) ? v1 : log1pf(expf(v1));
                } else if (epi == EP_RELU) {
                    v0 = fmaxf(v0, 0.f); v1 = fmaxf(v1, 0.f);
                }
                *reinterpret_cast<float2*>(crow + col) = make_float2(v0, v1);
                if (Ch) {
                    __half2 p; p.x = __float2half_rn(v0); p.y = __float2half_rn(v1);
                    *reinterpret_cast<__half2*>(Ch + (size_t)mg * ldc + col) = p;
                }
            }
        }
    }
}

// ---------------------------------------------------------------------------
// transpose + hi/lo fp16
// ---------------------------------------------------------------------------
__global__ void __launch_bounds__(256)
transpose_conv(const float* __restrict__ W, int K, int N, int Npad,
               __half* __restrict__ Th, __half* __restrict__ Tl)
{
    __shared__ float t[32][33];
    const int k0 = blockIdx.y * 32, n0 = blockIdx.x * 32;
    const int tx = threadIdx.x & 31, ty = threadIdx.x >> 5;
    #pragma unroll
    for (int i = 0; i < 4; ++i) {
        int k = k0 + ty + i * 8, n = n0 + tx;
        t[ty + i * 8][tx] = (n < N) ? W[(size_t)k * N + n] : 0.f;
    }
    __syncthreads();
    #pragma unroll
    for (int i = 0; i < 4; ++i) {
        int n = n0 + ty + i * 8, k = k0 + tx;
        if (n < Npad) {
            __half h, l; split_h(t[tx][ty + i * 8], h, l);
            Th[(size_t)n * K + k] = h;
            Tl[(size_t)n * K + k] = l;
        }
    }
}

__global__ void __launch_bounds__(256)
convert_h(const float* __restrict__ src, __half* __restrict__ h, int n)
{
    int i = blockIdx.x * 256 + threadIdx.x;
    if (i < n) h[i] = __float2half_rn(src[i]);
}

// ---------------------------------------------------------------------------
// causal dwconv(4) + SiLU, both directions in one launch
// ---------------------------------------------------------------------------
__global__ void __launch_bounds__(256)
conv_silu_kernel(const float* __restrict__ convw0, const float* __restrict__ convb0,
                 const float* __restrict__ convw1, const float* __restrict__ convb1)
{
    int idx = blockIdx.x * 256 + threadIdx.x;          // over NR2*DI
    if (idx >= NR2 * DI) return;
    int d = idx % DI, n = idx / DI;                    // n: combined row 0..8191
    int dir = n >> 12;
    int t = n & (SEQ - 1);
    const float* convw = dir ? convw1 : convw0;
    const float* convb = dir ? convb1 : convb0;
    float4 w = *reinterpret_cast<const float4*>(convw + d * 4);
    float acc = convb[d];
    const float* base = g_xz + (size_t)(n & ~(SEQ - 1)) * (2 * DI) + d;
    if (t >= 3) {
        acc = fmaf(base[(size_t)(t-3)*(2*DI)], w.x, acc);
        acc = fmaf(base[(size_t)(t-2)*(2*DI)], w.y, acc);
        acc = fmaf(base[(size_t)(t-1)*(2*DI)], w.z, acc);
        acc = fmaf(base[(size_t)(t  )*(2*DI)], w.w, acc);
    } else {
        if (t-3 >= 0) acc = fmaf(base[(size_t)(t-3)*(2*DI)], w.x, acc);
        if (t-2 >= 0) acc = fmaf(base[(size_t)(t-2)*(2*DI)], w.y, acc);
        if (t-1 >= 0) acc = fmaf(base[(size_t)(t-1)*(2*DI)], w.z, acc);
        acc = fmaf(base[(size_t)t*(2*DI)], w.w, acc);
    }
    float y = acc / (1.f + expf(-acc));
    g_xi[idx]  = y;
    g_xih[idx] = __float2half_rn(y);
}

// ---------------------------------------------------------------------------
// selective scan, both directions, unroll x4 for MLP
// ---------------------------------------------------------------------------
__global__ void __launch_bounds__(256)
scan_kernel(const float* __restrict__ Alog0, const float* __restrict__ Dpar0,
            const float* __restrict__ Alog1, const float* __restrict__ Dpar1)
{
    const int lane = threadIdx.x & 31;
    const int gw   = blockIdx.x * 8 + (threadIdx.x >> 5);   // 4096 warps
    const int half = lane >> 4;
    const int s    = lane & 15;
    const int ch   = gw * 2 + half;                          // 0..8191
    const int dir  = ch >> 12;
    const int d    = ch & (DI - 1);
    const int rowc = (ch >> 11) & ~0;                        // combined block = ch>>11
    const size_t rowbase = (size_t)(ch >> 11) * SEQ;         // (dir*2+b)*2048
    (void)rowc;

    const float* Alog = dir ? Alog1 : Alog0;
    const float* Dpar = dir ? Dpar1 : Dpar0;
    const float Ac = -expf(Alog[d * DS + s]);
    const float Dp = Dpar[d];

    const float* dt_p = g_dt  + rowbase * DI + d;
    const float* u_p  = g_xi  + rowbase * DI + d;
    const float* z_p  = g_xz  + rowbase * (2*DI) + DI + d;
    const float* bc_p = g_xdbc + rowbase * NXP + DTR + s;
    __half*      o_p  = g_gyh + rowbase * DI + d;

    float h = 0.f;
    for (int t0 = 0; t0 < SEQ; t0 += 4) {
        float dtv[4], uu[4], Bv[4], Cv[4], zz[4];
        #pragma unroll
        for (int i = 0; i < 4; ++i) {
            const size_t t = t0 + i;
            dtv[i] = dt_p[t * DI];
            uu[i]  = u_p [t * DI];
            Bv[i]  = bc_p[t * NXP];
            Cv[i]  = bc_p[t * NXP + DS];
        }
        if (s == 0) {
            #pragma unroll
            for (int i = 0; i < 4; ++i) zz[i] = z_p[(size_t)(t0 + i) * (2*DI)];
        }
        #pragma unroll
        for (int i = 0; i < 4; ++i) {
            const float dA = __expf(dtv[i] * Ac);
            h = fmaf(dA, h, dtv[i] * uu[i] * Bv[i]);
            float p = h * Cv[i];
            #pragma unroll
            for (int o = 8; o; o >>= 1) p += __shfl_xor_sync(0xffffffffu, p, o);
            if (s == 0) {
                const float z = zz[i];
                const float g = z / (1.f + __expf(-z));
                o_p[(size_t)(t0 + i) * DI] = __float2half_rn((p + uu[i] * Dp) * g);
            }
        }
    }
}

// ---------------------------------------------------------------------------
// layernorms
// ---------------------------------------------------------------------------
__device__ __forceinline__ float blockReduceSum(float v)
{
    __shared__ float sh[8];
    __syncthreads();
    #pragma unroll
    for (int o = 16; o; o >>= 1) v += __shfl_xor_sync(0xffffffffu, v, o);
    if ((threadIdx.x & 31) == 0) sh[threadIdx.x >> 5] = v;
    __syncthreads();
    if (threadIdx.x < 32) {
        float t = (threadIdx.x < 8) ? sh[threadIdx.x] : 0.f;
        #pragma unroll
        for (int o = 4; o; o >>= 1) t += __shfl_xor_sync(0xffffffffu, t, o);
        if (threadIdx.x == 0) sh[0] = t;
    }
    __syncthreads();
    return sh[0];
}

__global__ void __launch_bounds__(256)
ln_dual_kernel(const float* __restrict__ x,
               const float* __restrict__ w, const float* __restrict__ bs)
{
    const int row = blockIdx.x;
    const float* xr = x    + (size_t)row * DM;
    const float* fr = g_ym + (size_t)row * DM;
    const float* br = g_ym + (size_t)(NR + row) * DM;
    float* out      = g_ycomb + (size_t)row * DM;
    __half* oh      = g_ych   + (size_t)row * DM;

    float a[4], c[4];
    float sa = 0.f, sb = 0.f;
    #pragma unroll
    for (int i = 0; i < 4; ++i) {
        int idx = threadIdx.x + i * 256;
        float xv = xr[idx];
        a[i] = fr[idx] + xv;
        c[i] = br[idx] + xv;
        sa += a[i]; sb += c[i];
    }
    sa = blockReduceSum(sa);
    sb = blockReduceSum(sb);
    const float mua = sa * (1.f / DM), mub = sb * (1.f / DM);
    float va = 0.f, vb = 0.f;
    #pragma unroll
    for (int i = 0; i < 4; ++i) {
        float da = a[i] - mua; va += da * da;
        float db = c[i] - mub; vb += db * db;
    }
    va = blockReduceSum(va);
    vb = blockReduceSum(vb);
    const float ra = rsqrtf(va * (1.f / DM) + LN_EPS);
    const float rb = rsqrtf(vb * (1.f / DM) + LN_EPS);
    #pragma unroll
    for (int i = 0; i < 4; ++i) {
        int idx = threadIdx.x + i * 256;
        float wv = w[idx], bv = bs[idx];
        float o = ((a[i] - mua) * ra * wv + bv) + ((c[i] - mub) * rb * wv + bv);
        out[idx] = o;
        oh[idx]  = __float2half_rn(o);
    }
}

__global__ void __launch_bounds__(256)
ln_final_kernel(const float* __restrict__ w, const float* __restrict__ bs,
                float* __restrict__ out)
{
    const int row = blockIdx.x;
    const float* fr = g_ff    + (size_t)row * DM;
    const float* yr = g_ycomb + (size_t)row * DM;
    float* orow = out + (size_t)row * DM;

    float a[4];
    float sa = 0.f;
    #pragma unroll
    for (int i = 0; i < 4; ++i) {
        int idx = threadIdx.x + i * 256;
        a[i] = fr[idx] + yr[idx];
        sa += a[i];
    }
    sa = blockReduceSum(sa);
    const float mu = sa * (1.f / DM);
    float va = 0.f;
    #pragma unroll
    for (int i = 0; i < 4; ++i) { float d = a[i] - mu; va += d * d; }
    va = blockReduceSum(va);
    const float rs = rsqrtf(va * (1.f / DM) + LN_EPS);
    #pragma unroll
    for (int i = 0; i < 4; ++i) {
        int idx = threadIdx.x + i * 256;
        orow[idx] = (a[i] - mu) * rs * w[idx] + bs[idx];
    }
}

// ---------------------------------------------------------------------------
// launch
// ---------------------------------------------------------------------------
extern "C" void kernel_launch(void* const* d_in, const int* in_sizes, int n_in,
                              void* d_out, int out_size)
{
    (void)in_sizes; (void)n_in; (void)out_size;
    const float* x      = (const float*)d_in[0];
    const float* Win0   = (const float*)d_in[1];
    const float* convw0 = (const float*)d_in[2];
    const float* convb0 = (const float*)d_in[3];
    const float* Wx0    = (const float*)d_in[4];
    const float* Wdt0   = (const float*)d_in[5];
    const float* bdt0   = (const float*)d_in[6];
    const float* Alog0  = (const float*)d_in[7];
    const float* Dp0    = (const float*)d_in[8];
    const float* Wout0  = (const float*)d_in[9];
    const float* Win1   = (const float*)d_in[10];
    const float* convw1 = (const float*)d_in[11];
    const float* convb1 = (const float*)d_in[12];
    const float* Wx1    = (const float*)d_in[13];
    const float* Wdt1   = (const float*)d_in[14];
    const float* bdt1   = (const float*)d_in[15];
    const float* Alog1  = (const float*)d_in[16];
    const float* Dp1    = (const float*)d_in[17];
    const float* Wout1  = (const float*)d_in[18];
    const float* fwn_w  = (const float*)d_in[19];
    const float* fwn_b  = (const float*)d_in[20];
    const float* fin_w  = (const float*)d_in[21];
    const float* fin_b  = (const float*)d_in[22];
    const float* ff_W1  = (const float*)d_in[23];
    const float* ff_b1  = (const float*)d_in[24];
    const float* ff_W2  = (const float*)d_in[25];
    const float* ff_b2  = (const float*)d_in[26];

    cudaFuncSetAttribute(mma_gemm, cudaFuncAttributeMaxDynamicSharedMemorySize, SMEM_GEMM);

    float *xz, *xi, *xdbc, *dt, *ym, *ycomb, *ffh, *ff;
    cudaGetSymbolAddress((void**)&xz, g_xz);       cudaGetSymbolAddress((void**)&xi, g_xi);
    cudaGetSymbolAddress((void**)&xdbc, g_xdbc);   cudaGetSymbolAddress((void**)&dt, g_dt);
    cudaGetSymbolAddress((void**)&ym, g_ym);       cudaGetSymbolAddress((void**)&ycomb, g_ycomb);
    cudaGetSymbolAddress((void**)&ffh, g_ffh);     cudaGetSymbolAddress((void**)&ff, g_ff);

    __half *xh, *xih, *xdh, *gyh, *ych, *fhh;
    cudaGetSymbolAddress((void**)&xh, g_xh);   cudaGetSymbolAddress((void**)&xih, g_xih);
    cudaGetSymbolAddress((void**)&xdh, g_xdh); cudaGetSymbolAddress((void**)&gyh, g_gyh);
    cudaGetSymbolAddress((void**)&ych, g_ych); cudaGetSymbolAddress((void**)&fhh, g_fhh);

    __half *tWinH0,*tWinL0,*tWinH1,*tWinL1,*tWxH0,*tWxL0,*tWxH1,*tWxL1;
    __half *tWdtH0,*tWdtL0,*tWdtH1,*tWdtL1,*tWoH0,*tWoL0,*tWoH1,*tWoL1;
    __half *tF1H,*tF1L,*tF2H,*tF2L;
    cudaGetSymbolAddress((void**)&tWinH0, g_tWinH0); cudaGetSymbolAddress((void**)&tWinL0, g_tWinL0);
    cudaGetSymbolAddress((void**)&tWinH1, g_tWinH1); cudaGetSymbolAddress((void**)&tWinL1, g_tWinL1);
    cudaGetSymbolAddress((void**)&tWxH0, g_tWxH0);   cudaGetSymbolAddress((void**)&tWxL0, g_tWxL0);
    cudaGetSymbolAddress((void**)&tWxH1, g_tWxH1);   cudaGetSymbolAddress((void**)&tWxL1, g_tWxL1);
    cudaGetSymbolAddress((void**)&tWdtH0, g_tWdtH0); cudaGetSymbolAddress((void**)&tWdtL0, g_tWdtL0);
    cudaGetSymbolAddress((void**)&tWdtH1, g_tWdtH1); cudaGetSymbolAddress((void**)&tWdtL1, g_tWdtL1);
    cudaGetSymbolAddress((void**)&tWoH0, g_tWoH0);   cudaGetSymbolAddress((void**)&tWoL0, g_tWoL0);
    cudaGetSymbolAddress((void**)&tWoH1, g_tWoH1);   cudaGetSymbolAddress((void**)&tWoL1, g_tWoL1);
    cudaGetSymbolAddress((void**)&tF1H, g_tF1H);     cudaGetSymbolAddress((void**)&tF1L, g_tF1L);
    cudaGetSymbolAddress((void**)&tF2H, g_tF2H);     cudaGetSymbolAddress((void**)&tF2L, g_tF2L);

    // 0..2: inputs for the big GEMM
    convert_h<<<(NR*DM)/256, 256>>>(x, xh, NR*DM);
    transpose_conv<<<dim3(4096/32, 1024/32), 256>>>(Win0, 1024, 4096, 4096, tWinH0, tWinL0);
    transpose_conv<<<dim3(4096/32, 1024/32), 256>>>(Win1, 1024, 4096, 4096, tWinH1, tWinL1);

    // 3 (profiled): xz = [x ; flip(x)] @ {Win0|Win1}   M=8192 N=4096 K=1024
    mma_gemm<<<dim3(32, 64), 256, SMEM_GEMM>>>(
        xh, DM, tWinH0, tWinL0, tWinH1, tWinL1, DM,
        xz, 2*DI, nullptr, NR, 1, 0, EP_NONE, nullptr, nullptr);

    // remaining weight preps (independent)
    transpose_conv<<<dim3(128/32,  2048/32), 256>>>(Wx0,  2048, 96,  128, tWxH0, tWxL0);
    transpose_conv<<<dim3(128/32,  2048/32), 256>>>(Wx1,  2048, 96,  128, tWxH1, tWxL1);
    transpose_conv<<<dim3(2048/32, 64/32),   256>>>(Wdt0, 64, 2048, 2048, tWdtH0, tWdtL0);
    transpose_conv<<<dim3(2048/32, 64/32),   256>>>(Wdt1, 64, 2048, 2048, tWdtH1, tWdtL1);
    transpose_conv<<<dim3(1024/32, 2048/32), 256>>>(Wout0, 2048, 1024, 1024, tWoH0, tWoL0);
    transpose_conv<<<dim3(1024/32, 2048/32), 256>>>(Wout1, 2048, 1024, 1024, tWoH1, tWoL1);
    transpose_conv<<<dim3(2048/32, 1024/32), 256>>>(ff_W1, 1024, 2048, 2048, tF1H, tF1L);
    transpose_conv<<<dim3(1024/32, 2048/32), 256>>>(ff_W2, 2048, 1024, 1024, tF2H, tF2L);

    // conv + silu (both dirs)
    conv_silu_kernel<<<(NR2*DI)/256, 256>>>(convw0, convb0, convw1, convb1);

    // xdbc = xi @ {Wx0|Wx1}   M=8192 N=128 K=2048
    mma_gemm<<<dim3(1, 64), 256, SMEM_GEMM>>>(
        xih, DI, tWxH0, tWxL0, tWxH1, tWxL1, DI,
        xdbc, NXP, xdh, NR, 0, 0, EP_NONE, nullptr, nullptr);

    // dt = softplus(xdbc[:, :64] @ {Wdt0|Wdt1} + {bdt0|bdt1})  M=8192 N=2048 K=64
    mma_gemm<<<dim3(16, 64), 256, SMEM_GEMM>>>(
        xdh, NXP, tWdtH0, tWdtL0, tWdtH1, tWdtL1, DTR,
        dt, DI, nullptr, NR, 0, 0, EP_SOFTPLUS, bdt0, bdt1);

    // selective scan (both dirs)
    scan_kernel<<<512, 256>>>(Alog0, Dp0, Alog1, Dp1);

    // ym = gy @ {Wout0|Wout1}, bw half flip-stored   M=8192 N=1024 K=2048
    mma_gemm<<<dim3(8, 64), 256, SMEM_GEMM>>>(
        gyh, DI, tWoH0, tWoL0, tWoH1, tWoL1, DI,
        ym, DM, nullptr, NR, 0, 1, EP_NONE, nullptr, nullptr);

    // ycomb = LN(ym_fw + x) + LN(ym_bw + x)
    ln_dual_kernel<<<NR, 256>>>(x, fwn_w, fwn_b);

    // ffh = relu(ycomb @ W1 + b1)  M=4096 N=2048 K=1024
    mma_gemm<<<dim3(16, 32), 256, SMEM_GEMM>>>(
        ych, DM, tF1H, tF1L, nullptr, nullptr, DM,
        ffh, DI, fhh, 0, 0, 0, EP_RELU, ff_b1, nullptr);

    // ff = ffh @ W2 + b2   M=4096 N=1024 K=2048
    mma_gemm<<<dim3(8, 32), 256, SMEM_GEMM>>>(
        fhh, DI, tF2H, tF2L, nullptr, nullptr, DI,
        ff, DM, nullptr, 0, 0, 0, EP_BIAS, ff_b2, nullptr);

    // out = LN(ff + ycomb)
    ln_final_kernel<<<NR, 256>>>(fin_w, fin_b, (float*)d_out);
}

// round 6
// speedup vs baseline: 6.1563x; 1.9037x over previous
#include <cuda_runtime.h>
#include <cuda_fp16.h>
#include <math.h>
#include <stdint.h>

// ---------------------------------------------------------------------------
// BiMamba on GB300 (sm_103 baseline PTX).  Directions fused (M=8192 GEMMs).
// Big GEMMs single-pass fp16; Wx (split-K=4) and Wdt 2-pass hi/lo fp16.
// ---------------------------------------------------------------------------

#define NB   2
#define SEQ  2048
#define DM   1024
#define DI   2048
#define DS   16
#define DTR  64
#define NXP  128
#define NR   (NB*SEQ)        // 4096 rows per direction
#define NR2  (2*NR)          // 8192 combined
#define LN_EPS 1e-5f

#define EP_NONE     0
#define EP_SOFTPLUS 1
#define EP_RELU     2
#define EP_BIAS     3

// ---- scratch ---------------------------------------------------------------
__device__ float g_xz  [(size_t)NR2 * 2 * DI];
__device__ float g_xi  [(size_t)NR2 * DI];
__device__ float g_xdbc[(size_t)NR2 * NXP];
__device__ float g_xdp [(size_t)4 * NR2 * NXP];   // split-K partials
__device__ float g_dt  [(size_t)NR2 * DI];
__device__ float g_ym  [(size_t)NR2 * DM];
__device__ float g_ycomb[(size_t)NR * DM];
__device__ float g_ff  [(size_t)NR * DM];

__device__ __half g_xh  [(size_t)NR*DM];
__device__ __half g_xih [(size_t)NR2*DI];
__device__ __half g_xdh [(size_t)NR2*NXP];
__device__ __half g_gyh [(size_t)NR2*DI];
__device__ __half g_ych [(size_t)NR*DM];
__device__ __half g_fhh [(size_t)NR*DI];

// transposed weights [N][K] fp16 hi/lo
__device__ __half g_tWinH0[(size_t)4096*1024], g_tWinL0[(size_t)4096*1024];
__device__ __half g_tWinH1[(size_t)4096*1024], g_tWinL1[(size_t)4096*1024];
__device__ __half g_tWxH0 [(size_t)128*2048],  g_tWxL0 [(size_t)128*2048];
__device__ __half g_tWxH1 [(size_t)128*2048],  g_tWxL1 [(size_t)128*2048];
__device__ __half g_tWdtH0[(size_t)2048*64],   g_tWdtL0[(size_t)2048*64];
__device__ __half g_tWdtH1[(size_t)2048*64],   g_tWdtL1[(size_t)2048*64];
__device__ __half g_tWoH0 [(size_t)1024*2048], g_tWoL0 [(size_t)1024*2048];
__device__ __half g_tWoH1 [(size_t)1024*2048], g_tWoL1 [(size_t)1024*2048];
__device__ __half g_tF1H  [(size_t)2048*1024], g_tF1L  [(size_t)2048*1024];
__device__ __half g_tF2H  [(size_t)1024*2048], g_tF2L  [(size_t)1024*2048];

// ---------------------------------------------------------------------------
// helpers
// ---------------------------------------------------------------------------
__device__ __forceinline__ uint32_t smem_u32(const void* p) {
    uint32_t a;
    asm("{ .reg .u64 t; cvta.to.shared.u64 t, %1; cvt.u32.u64 %0, t; }"
        : "=r"(a) : "l"(p));
    return a;
}
__device__ __forceinline__ void ldsm4(uint32_t* r, uint32_t addr) {
    asm volatile("ldmatrix.sync.aligned.m8n8.x4.shared.b16 {%0,%1,%2,%3}, [%4];"
        : "=r"(r[0]), "=r"(r[1]), "=r"(r[2]), "=r"(r[3]) : "r"(addr));
}
__device__ __forceinline__ void mma_f16(float* c, const uint32_t* a, const uint32_t* b) {
    asm volatile("mma.sync.aligned.m16n8k16.row.col.f32.f16.f16.f32 "
        "{%0,%1,%2,%3}, {%4,%5,%6,%7}, {%8,%9}, {%0,%1,%2,%3};"
        : "+f"(c[0]), "+f"(c[1]), "+f"(c[2]), "+f"(c[3])
        : "r"(a[0]), "r"(a[1]), "r"(a[2]), "r"(a[3]), "r"(b[0]), "r"(b[1]));
}
__device__ __forceinline__ void cp16(uint32_t dst, const void* src) {
    asm volatile("{ .reg .u64 g; cvta.to.global.u64 g, %1; "
                 "cp.async.cg.shared.global [%0], [g], 16; }"
                 :: "r"(dst), "l"(src) : "memory");
}
#define CP_COMMIT() asm volatile("cp.async.commit_group;" ::: "memory")
#define CP_WAIT1()  asm volatile("cp.async.wait_group 1;" ::: "memory")

__device__ __forceinline__ int fliprow(int m) {
    return (m & ~(SEQ - 1)) | ((SEQ - 1) - (m & (SEQ - 1)));
}
__device__ __forceinline__ void split_h(float v, __half& h, __half& l) {
    h = __float2half_rn(v);
    l = __float2half_rn(v - __half2float(h));
}

// ---------------------------------------------------------------------------
// GEMM: C[M,N] = A[M,K] @ B[N,K]^T.  A fp16; B fp16 (1-pass) or hi/lo (2-pass).
// Dual weights by M-half; optional flipA2/flipC2 on second half; optional
// split-K via blockIdx.z (chunk size K, B row stride ldb, partial buffers).
// CTA 128x128, 8 warps, K-stage 32, cp.async 3-stage ring.
// ---------------------------------------------------------------------------
#define ROWB  80
#define PLANE (128 * ROWB)
#define STG   (3 * PLANE)
#define NSTAGE 3
#define SMEM_GEMM (NSTAGE * STG)

template<bool TWOPASS, bool SPLITK>
__global__ void __launch_bounds__(256, 2)
mma_gemm(const __half* __restrict__ Aa, int lda,
         const __half* __restrict__ B1h, const __half* __restrict__ B1l,
         const __half* __restrict__ B2h, const __half* __restrict__ B2l,
         int K, int ldb,
         float* __restrict__ C, int ldc, __half* __restrict__ Ch,
         int mhalf, int flipA2, int flipC2,
         int epi, const float* __restrict__ bias1, const float* __restrict__ bias2,
         int zrows)
{
    extern __shared__ char smem[];
    const uint32_t sb = smem_u32(smem);

    const int tid  = threadIdx.x;
    const int wid  = tid >> 5, lane = tid & 31;
    const int wm   = wid >> 2, wn = wid & 3;
    const int bm   = blockIdx.y * 128;
    const int bn   = blockIdx.x * 128;
    const int koff = SPLITK ? blockIdx.z * K : 0;
    if (SPLITK) C += (size_t)blockIdx.z * zrows * ldc;

    const int half2 = (mhalf > 0) && (bm >= mhalf);
    const __half* Bth = half2 ? B2h : B1h;
    const __half* Btl = half2 ? B2l : B1l;
    const float*  bias = half2 ? bias2 : bias1;

    constexpr int NJ = TWOPASS ? 6 : 4;
    const __half* src[NJ];
    uint32_t dst0[NJ];
    #pragma unroll
    for (int j = 0; j < NJ; ++j) {
        const int c = j * 256 + tid;
        const int plane = c >> 9;                 // 0 A, 1 Bh, 2 Bl
        const int r = (c >> 2) & 127;
        const int q = c & 3;
        dst0[j] = sb + plane * PLANE + r * ROWB + q * 16;
        if (plane == 0) {
            int m = bm + r;
            if (half2 && flipA2) m = fliprow(m & (mhalf - 1));
            src[j] = Aa + (size_t)m * lda + koff + q * 8;
        } else {
            src[j] = ((plane == 2) ? Btl : Bth) + (size_t)(bn + r) * ldb + koff + q * 8;
        }
    }

    const uint32_t a_loff = ((lane & 7) + ((lane >> 3) & 1) * 8) * ROWB + (lane >> 4) * 16;
    const uint32_t b_loff = ((lane & 7) + (lane >> 4) * 8) * ROWB + ((lane >> 3) & 1) * 16;
    const uint32_t aw = wm * 64 * ROWB + a_loff;
    const uint32_t bw = PLANE + wn * 32 * ROWB + b_loff;

    float acc[4][4][4];
    #pragma unroll
    for (int mt = 0; mt < 4; ++mt)
        #pragma unroll
        for (int nt = 0; nt < 4; ++nt)
            #pragma unroll
            for (int i = 0; i < 4; ++i) acc[mt][nt][i] = 0.f;

    const int S = K / 32;
    int ns = 0;
    #pragma unroll
    for (int p = 0; p < NSTAGE - 1; ++p) {
        if (p < S) {
            const uint32_t so = (uint32_t)p * STG;
            #pragma unroll
            for (int j = 0; j < NJ; ++j) cp16(dst0[j] + so, src[j] + p * 32);
            ++ns;
        }
        CP_COMMIT();
    }

    for (int s = 0; s < S; ++s) {
        CP_WAIT1();
        __syncthreads();

        if (ns < S) {
            const uint32_t so = (uint32_t)(ns % NSTAGE) * STG;
            const int kt = ns * 32;
            #pragma unroll
            for (int j = 0; j < NJ; ++j) cp16(dst0[j] + so, src[j] + kt);
            ++ns;
        }
        CP_COMMIT();

        const uint32_t bo = sb + (uint32_t)(s % NSTAGE) * STG;
        #pragma unroll
        for (int ks = 0; ks < 2; ++ks) {
            uint32_t bh[8];
            ldsm4(&bh[0], bo + bw + ks * 32);
            ldsm4(&bh[4], bo + bw + 16 * ROWB + ks * 32);
            uint32_t bl[8];
            if (TWOPASS) {
                ldsm4(&bl[0], bo + bw + PLANE + ks * 32);
                ldsm4(&bl[4], bo + bw + PLANE + 16 * ROWB + ks * 32);
            }
            #pragma unroll
            for (int mt = 0; mt < 4; ++mt) {
                uint32_t a[4];
                ldsm4(a, bo + aw + mt * 16 * ROWB + ks * 32);
                #pragma unroll
                for (int nt = 0; nt < 4; ++nt) mma_f16(acc[mt][nt], a, &bh[nt * 2]);
                if (TWOPASS) {
                    #pragma unroll
                    for (int nt = 0; nt < 4; ++nt) mma_f16(acc[mt][nt], a, &bl[nt * 2]);
                }
            }
        }
    }

    // epilogue
    #pragma unroll
    for (int mt = 0; mt < 4; ++mt) {
        const int r0 = bm + wm * 64 + mt * 16 + (lane >> 2);
        #pragma unroll
        for (int half = 0; half < 2; ++half) {
            const int rg = r0 + half * 8;
            int mg = rg;
            if (half2 && flipC2) mg = mhalf + fliprow(rg & (mhalf - 1));
            float* crow = C + (size_t)mg * ldc;
            #pragma unroll
            for (int nt = 0; nt < 4; ++nt) {
                const int col = bn + wn * 32 + nt * 8 + (lane & 3) * 2;
                float v0 = acc[mt][nt][half * 2 + 0];
                float v1 = acc[mt][nt][half * 2 + 1];
                if (epi != EP_NONE) { v0 += bias[col]; v1 += bias[col + 1]; }
                if (epi == EP_SOFTPLUS) {
                    v0 = (v0 > 20.f) ? v0 : log1pf(expf(v0));
                    v1 = (v1 > 20.f) ? v1 : log1pf(expf(v1));
                } else if (epi == EP_RELU) {
                    v0 = fmaxf(v0, 0.f); v1 = fmaxf(v1, 0.f);
                }
                if (C) *reinterpret_cast<float2*>(crow + col) = make_float2(v0, v1);
                if (Ch) {
                    __half2 p; p.x = __float2half_rn(v0); p.y = __float2half_rn(v1);
                    *reinterpret_cast<__half2*>(Ch + (size_t)mg * ldc + col) = p;
                }
            }
        }
    }
}

// ---------------------------------------------------------------------------
// batched transpose + hi/lo fp16:  W[K][N] fp32 -> Th/Tl [Npad][K]
// ---------------------------------------------------------------------------
struct TBatch {
    const float* W[8];
    __half* Th[8];
    __half* Tl[8];
    int K[8], N[8], Npad[8], ntiles[8];
    int count;
};

__global__ void __launch_bounds__(256)
transpose_batch(TBatch P)
{
    int t = blockIdx.x;
    int di = 0, base = 0;
    while (di < P.count && t >= base + P.ntiles[di]) { base += P.ntiles[di]; ++di; }
    if (di >= P.count) return;
    const int local = t - base;
    const int nx = P.Npad[di] / 32;
    const int k0 = (local / nx) * 32;
    const int n0 = (local % nx) * 32;
    const float* W = P.W[di];
    const int K = P.K[di], N = P.N[di];

    __shared__ float tsh[32][33];
    const int tx = threadIdx.x & 31, ty = threadIdx.x >> 5;
    #pragma unroll
    for (int i = 0; i < 4; ++i) {
        int k = k0 + ty + i * 8, n = n0 + tx;
        tsh[ty + i * 8][tx] = (n < N) ? W[(size_t)k * N + n] : 0.f;
    }
    __syncthreads();
    __half* Th = P.Th[di]; __half* Tl = P.Tl[di];
    #pragma unroll
    for (int i = 0; i < 4; ++i) {
        int n = n0 + ty + i * 8, k = k0 + tx;
        __half h, l; split_h(tsh[tx][ty + i * 8], h, l);
        Th[(size_t)n * K + k] = h;
        Tl[(size_t)n * K + k] = l;
    }
}

__global__ void __launch_bounds__(256)
convert_h(const float* __restrict__ src, __half* __restrict__ h, int n)
{
    int i = blockIdx.x * 256 + threadIdx.x;
    if (i < n) h[i] = __float2half_rn(src[i]);
}

// reduce 4 split-K partials -> xdbc fp32 + xdh fp16
__global__ void __launch_bounds__(256)
reduce_xdbc()
{
    int i = blockIdx.x * 256 + threadIdx.x;      // over NR2*NXP
    const size_t P = (size_t)NR2 * NXP;
    float s = g_xdp[i] + g_xdp[P + i] + g_xdp[2*P + i] + g_xdp[3*P + i];
    g_xdbc[i] = s;
    g_xdh[i]  = __float2half_rn(s);
}

// ---------------------------------------------------------------------------
// causal dwconv(4) + SiLU, both directions
// ---------------------------------------------------------------------------
__global__ void __launch_bounds__(256)
conv_silu_kernel(const float* __restrict__ convw0, const float* __restrict__ convb0,
                 const float* __restrict__ convw1, const float* __restrict__ convb1)
{
    int idx = blockIdx.x * 256 + threadIdx.x;
    if (idx >= NR2 * DI) return;
    int d = idx % DI, n = idx / DI;
    int dir = n >> 12;
    int t = n & (SEQ - 1);
    const float* convw = dir ? convw1 : convw0;
    const float* convb = dir ? convb1 : convb0;
    float4 w = *reinterpret_cast<const float4*>(convw + d * 4);
    float acc = convb[d];
    const float* base = g_xz + (size_t)(n & ~(SEQ - 1)) * (2 * DI) + d;
    if (t >= 3) {
        acc = fmaf(base[(size_t)(t-3)*(2*DI)], w.x, acc);
        acc = fmaf(base[(size_t)(t-2)*(2*DI)], w.y, acc);
        acc = fmaf(base[(size_t)(t-1)*(2*DI)], w.z, acc);
        acc = fmaf(base[(size_t)(t  )*(2*DI)], w.w, acc);
    } else {
        if (t-3 >= 0) acc = fmaf(base[(size_t)(t-3)*(2*DI)], w.x, acc);
        if (t-2 >= 0) acc = fmaf(base[(size_t)(t-2)*(2*DI)], w.y, acc);
        if (t-1 >= 0) acc = fmaf(base[(size_t)(t-1)*(2*DI)], w.z, acc);
        acc = fmaf(base[(size_t)t*(2*DI)], w.w, acc);
    }
    float y = acc / (1.f + expf(-acc));
    g_xi[idx]  = y;
    g_xih[idx] = __float2half_rn(y);
}

// ---------------------------------------------------------------------------
// selective scan, both directions, unroll x4
// ---------------------------------------------------------------------------
__global__ void __launch_bounds__(256)
scan_kernel(const float* __restrict__ Alog0, const float* __restrict__ Dpar0,
            const float* __restrict__ Alog1, const float* __restrict__ Dpar1)
{
    const int lane = threadIdx.x & 31;
    const int gw   = blockIdx.x * 8 + (threadIdx.x >> 5);
    const int half = lane >> 4;
    const int s    = lane & 15;
    const int ch   = gw * 2 + half;
    const int dir  = ch >> 12;
    const int d    = ch & (DI - 1);
    const size_t rowbase = (size_t)(ch >> 11) * SEQ;

    const float* Alog = dir ? Alog1 : Alog0;
    const float* Dpar = dir ? Dpar1 : Dpar0;
    const float Ac = -expf(Alog[d * DS + s]);
    const float Dp = Dpar[d];

    const float* dt_p = g_dt  + rowbase * DI + d;
    const float* u_p  = g_xi  + rowbase * DI + d;
    const float* z_p  = g_xz  + rowbase * (2*DI) + DI + d;
    const float* bc_p = g_xdbc + rowbase * NXP + DTR + s;
    __half*      o_p  = g_gyh + rowbase * DI + d;

    float h = 0.f;
    for (int t0 = 0; t0 < SEQ; t0 += 4) {
        float dtv[4], uu[4], Bv[4], Cv[4], zz[4];
        #pragma unroll
        for (int i = 0; i < 4; ++i) {
            const size_t t = t0 + i;
            dtv[i] = dt_p[t * DI];
            uu[i]  = u_p [t * DI];
            Bv[i]  = bc_p[t * NXP];
            Cv[i]  = bc_p[t * NXP + DS];
        }
        if (s == 0) {
            #pragma unroll
            for (int i = 0; i < 4; ++i) zz[i] = z_p[(size_t)(t0 + i) * (2*DI)];
        }
        #pragma unroll
        for (int i = 0; i < 4; ++i) {
            const float dA = __expf(dtv[i] * Ac);
            h = fmaf(dA, h, dtv[i] * uu[i] * Bv[i]);
            float p = h * Cv[i];
            #pragma unroll
            for (int o = 8; o; o >>= 1) p += __shfl_xor_sync(0xffffffffu, p, o);
            if (s == 0) {
                const float z = zz[i];
                const float g = z / (1.f + __expf(-z));
                o_p[(size_t)(t0 + i) * DI] = __float2half_rn((p + uu[i] * Dp) * g);
            }
        }
    }
}

// ---------------------------------------------------------------------------
// layernorms
// ---------------------------------------------------------------------------
__device__ __forceinline__ float blockReduceSum(float v)
{
    __shared__ float sh[8];
    __syncthreads();
    #pragma unroll
    for (int o = 16; o; o >>= 1) v += __shfl_xor_sync(0xffffffffu, v, o);
    if ((threadIdx.x & 31) == 0) sh[threadIdx.x >> 5] = v;
    __syncthreads();
    if (threadIdx.x < 32) {
        float t = (threadIdx.x < 8) ? sh[threadIdx.x] : 0.f;
        #pragma unroll
        for (int o = 4; o; o >>= 1) t += __shfl_xor_sync(0xffffffffu, t, o);
        if (threadIdx.x == 0) sh[0] = t;
    }
    __syncthreads();
    return sh[0];
}

__global__ void __launch_bounds__(256)
ln_dual_kernel(const float* __restrict__ x,
               const float* __restrict__ w, const float* __restrict__ bs)
{
    const int row = blockIdx.x;
    const float* xr = x    + (size_t)row * DM;
    const float* fr = g_ym + (size_t)row * DM;
    const float* br = g_ym + (size_t)(NR + row) * DM;
    float* out      = g_ycomb + (size_t)row * DM;
    __half* oh      = g_ych   + (size_t)row * DM;

    float a[4], c[4];
    float sa = 0.f, sb = 0.f;
    #pragma unroll
    for (int i = 0; i < 4; ++i) {
        int idx = threadIdx.x + i * 256;
        float xv = xr[idx];
        a[i] = fr[idx] + xv;
        c[i] = br[idx] + xv;
        sa += a[i]; sb += c[i];
    }
    sa = blockReduceSum(sa);
    sb = blockReduceSum(sb);
    const float mua = sa * (1.f / DM), mub = sb * (1.f / DM);
    float va = 0.f, vb = 0.f;
    #pragma unroll
    for (int i = 0; i < 4; ++i) {
        float da = a[i] - mua; va += da * da;
        float db = c[i] - mub; vb += db * db;
    }
    va = blockReduceSum(va);
    vb = blockReduceSum(vb);
    const float ra = rsqrtf(va * (1.f / DM) + LN_EPS);
    const float rb = rsqrtf(vb * (1.f / DM) + LN_EPS);
    #pragma unroll
    for (int i = 0; i < 4; ++i) {
        int idx = threadIdx.x + i * 256;
        float wv = w[idx], bv = bs[idx];
        float o = ((a[i] - mua) * ra * wv + bv) + ((c[i] - mub) * rb * wv + bv);
        out[idx] = o;
        oh[idx]  = __float2half_rn(o);
    }
}

__global__ void __launch_bounds__(256)
ln_final_kernel(const float* __restrict__ w, const float* __restrict__ bs,
                float* __restrict__ out)
{
    const int row = blockIdx.x;
    const float* fr = g_ff    + (size_t)row * DM;
    const float* yr = g_ycomb + (size_t)row * DM;
    float* orow = out + (size_t)row * DM;

    float a[4];
    float sa = 0.f;
    #pragma unroll
    for (int i = 0; i < 4; ++i) {
        int idx = threadIdx.x + i * 256;
        a[i] = fr[idx] + yr[idx];
        sa += a[i];
    }
    sa = blockReduceSum(sa);
    const float mu = sa * (1.f / DM);
    float va = 0.f;
    #pragma unroll
    for (int i = 0; i < 4; ++i) { float d = a[i] - mu; va += d * d; }
    va = blockReduceSum(va);
    const float rs = rsqrtf(va * (1.f / DM) + LN_EPS);
    #pragma unroll
    for (int i = 0; i < 4; ++i) {
        int idx = threadIdx.x + i * 256;
        orow[idx] = (a[i] - mu) * rs * w[idx] + bs[idx];
    }
}

// ---------------------------------------------------------------------------
// launch
// ---------------------------------------------------------------------------
extern "C" void kernel_launch(void* const* d_in, const int* in_sizes, int n_in,
                              void* d_out, int out_size)
{
    (void)in_sizes; (void)n_in; (void)out_size;
    const float* x      = (const float*)d_in[0];
    const float* Win0   = (const float*)d_in[1];
    const float* convw0 = (const float*)d_in[2];
    const float* convb0 = (const float*)d_in[3];
    const float* Wx0    = (const float*)d_in[4];
    const float* Wdt0   = (const float*)d_in[5];
    const float* bdt0   = (const float*)d_in[6];
    const float* Alog0  = (const float*)d_in[7];
    const float* Dp0    = (const float*)d_in[8];
    const float* Wout0  = (const float*)d_in[9];
    const float* Win1   = (const float*)d_in[10];
    const float* convw1 = (const float*)d_in[11];
    const float* convb1 = (const float*)d_in[12];
    const float* Wx1    = (const float*)d_in[13];
    const float* Wdt1   = (const float*)d_in[14];
    const float* bdt1   = (const float*)d_in[15];
    const float* Alog1  = (const float*)d_in[16];
    const float* Dp1    = (const float*)d_in[17];
    const float* Wout1  = (const float*)d_in[18];
    const float* fwn_w  = (const float*)d_in[19];
    const float* fwn_b  = (const float*)d_in[20];
    const float* fin_w  = (const float*)d_in[21];
    const float* fin_b  = (const float*)d_in[22];
    const float* ff_W1  = (const float*)d_in[23];
    const float* ff_b1  = (const float*)d_in[24];
    const float* ff_W2  = (const float*)d_in[25];
    const float* ff_b2  = (const float*)d_in[26];

    cudaFuncSetAttribute(mma_gemm<true,false>,  cudaFuncAttributeMaxDynamicSharedMemorySize, SMEM_GEMM);
    cudaFuncSetAttribute(mma_gemm<false,false>, cudaFuncAttributeMaxDynamicSharedMemorySize, SMEM_GEMM);
    cudaFuncSetAttribute(mma_gemm<true,true>,   cudaFuncAttributeMaxDynamicSharedMemorySize, SMEM_GEMM);

    float *xz, *xi, *xdbc, *xdp, *dt, *ym, *ycomb, *ff;
    cudaGetSymbolAddress((void**)&xz, g_xz);       cudaGetSymbolAddress((void**)&xi, g_xi);
    cudaGetSymbolAddress((void**)&xdbc, g_xdbc);   cudaGetSymbolAddress((void**)&xdp, g_xdp);
    cudaGetSymbolAddress((void**)&dt, g_dt);       cudaGetSymbolAddress((void**)&ym, g_ym);
    cudaGetSymbolAddress((void**)&ycomb, g_ycomb); cudaGetSymbolAddress((void**)&ff, g_ff);

    __half *xh, *xih, *xdh, *gyh, *ych, *fhh;
    cudaGetSymbolAddress((void**)&xh, g_xh);   cudaGetSymbolAddress((void**)&xih, g_xih);
    cudaGetSymbolAddress((void**)&xdh, g_xdh); cudaGetSymbolAddress((void**)&gyh, g_gyh);
    cudaGetSymbolAddress((void**)&ych, g_ych); cudaGetSymbolAddress((void**)&fhh, g_fhh);

    __half *tWinH0,*tWinL0,*tWinH1,*tWinL1,*tWxH0,*tWxL0,*tWxH1,*tWxL1;
    __half *tWdtH0,*tWdtL0,*tWdtH1,*tWdtL1,*tWoH0,*tWoL0,*tWoH1,*tWoL1;
    __half *tF1H,*tF1L,*tF2H,*tF2L;
    cudaGetSymbolAddress((void**)&tWinH0, g_tWinH0); cudaGetSymbolAddress((void**)&tWinL0, g_tWinL0);
    cudaGetSymbolAddress((void**)&tWinH1, g_tWinH1); cudaGetSymbolAddress((void**)&tWinL1, g_tWinL1);
    cudaGetSymbolAddress((void**)&tWxH0, g_tWxH0);   cudaGetSymbolAddress((void**)&tWxL0, g_tWxL0);
    cudaGetSymbolAddress((void**)&tWxH1, g_tWxH1);   cudaGetSymbolAddress((void**)&tWxL1, g_tWxL1);
    cudaGetSymbolAddress((void**)&tWdtH0, g_tWdtH0); cudaGetSymbolAddress((void**)&tWdtL0, g_tWdtL0);
    cudaGetSymbolAddress((void**)&tWdtH1, g_tWdtH1); cudaGetSymbolAddress((void**)&tWdtL1, g_tWdtL1);
    cudaGetSymbolAddress((void**)&tWoH0, g_tWoH0);   cudaGetSymbolAddress((void**)&tWoL0, g_tWoL0);
    cudaGetSymbolAddress((void**)&tWoH1, g_tWoH1);   cudaGetSymbolAddress((void**)&tWoL1, g_tWoL1);
    cudaGetSymbolAddress((void**)&tF1H, g_tF1H);     cudaGetSymbolAddress((void**)&tF1L, g_tF1L);
    cudaGetSymbolAddress((void**)&tF2H, g_tF2H);     cudaGetSymbolAddress((void**)&tF2L, g_tF2L);

    // 0: x -> fp16
    convert_h<<<(NR*DM)/256, 256>>>(x, xh, NR*DM);

    // 1: Win transposes (2 x 4096 tiles)
    {
        TBatch P = {};
        P.count = 2;
        P.W[0]=Win0; P.Th[0]=tWinH0; P.Tl[0]=tWinL0; P.K[0]=1024; P.N[0]=4096; P.Npad[0]=4096; P.ntiles[0]=4096;
        P.W[1]=Win1; P.Th[1]=tWinH1; P.Tl[1]=tWinL1; P.K[1]=1024; P.N[1]=4096; P.Npad[1]=4096; P.ntiles[1]=4096;
        transpose_batch<<<8192, 256>>>(P);
    }
    // 2: remaining transposes (8 descs, 8960 tiles)
    {
        TBatch P = {};
        P.count = 8;
        P.W[0]=Wx0;   P.Th[0]=tWxH0;  P.Tl[0]=tWxL0;  P.K[0]=2048; P.N[0]=96;   P.Npad[0]=128;  P.ntiles[0]=256;
        P.W[1]=Wx1;   P.Th[1]=tWxH1;  P.Tl[1]=tWxL1;  P.K[1]=2048; P.N[1]=96;   P.Npad[1]=128;  P.ntiles[1]=256;
        P.W[2]=Wdt0;  P.Th[2]=tWdtH0; P.Tl[2]=tWdtL0; P.K[2]=64;   P.N[2]=2048; P.Npad[2]=2048; P.ntiles[2]=128;
        P.W[3]=Wdt1;  P.Th[3]=tWdtH1; P.Tl[3]=tWdtL1; P.K[3]=64;   P.N[3]=2048; P.Npad[3]=2048; P.ntiles[3]=128;
        P.W[4]=Wout0; P.Th[4]=tWoH0;  P.Tl[4]=tWoL0;  P.K[4]=2048; P.N[4]=1024; P.Npad[4]=1024; P.ntiles[4]=2048;
        P.W[5]=Wout1; P.Th[5]=tWoH1;  P.Tl[5]=tWoL1;  P.K[5]=2048; P.N[5]=1024; P.Npad[5]=1024; P.ntiles[5]=2048;
        P.W[6]=ff_W1; P.Th[6]=tF1H;   P.Tl[6]=tF1L;   P.K[6]=1024; P.N[6]=2048; P.Npad[6]=2048; P.ntiles[6]=2048;
        P.W[7]=ff_W2; P.Th[7]=tF2H;   P.Tl[7]=tF2L;   P.K[7]=2048; P.N[7]=1024; P.Npad[7]=1024; P.ntiles[7]=2048;
        transpose_batch<<<8960, 256>>>(P);
    }

    // 3 (profiled): xz = [x ; flip(x)] @ {Win0|Win1}  1-pass, M=8192 N=4096 K=1024
    mma_gemm<false,false><<<dim3(32, 64), 256, SMEM_GEMM>>>(
        xh, DM, tWinH0, nullptr, tWinH1, nullptr, DM, DM,
        xz, 2*DI, nullptr, NR, 1, 0, EP_NONE, nullptr, nullptr, 0);

    // conv + silu
    conv_silu_kernel<<<(NR2*DI)/256, 256>>>(convw0, convb0, convw1, convb1);

    // xdbc partials: split-K=4, 2-pass.  M=8192 N=128 Kchunk=512, ldb=2048
    mma_gemm<true,true><<<dim3(1, 64, 4), 256, SMEM_GEMM>>>(
        xih, DI, tWxH0, tWxL0, tWxH1, tWxL1, 512, DI,
        xdp, NXP, nullptr, NR, 0, 0, EP_NONE, nullptr, nullptr, NR2);

    reduce_xdbc<<<(NR2*NXP)/256, 256>>>();

    // dt = softplus(xdh[:, :64] @ {Wdt0|Wdt1} + bdt)  2-pass, M=8192 N=2048 K=64
    mma_gemm<true,false><<<dim3(16, 64), 256, SMEM_GEMM>>>(
        xdh, NXP, tWdtH0, tWdtL0, tWdtH1, tWdtL1, DTR, DTR,
        dt, DI, nullptr, NR, 0, 0, EP_SOFTPLUS, bdt0, bdt1, 0);

    // selective scan
    scan_kernel<<<512, 256>>>(Alog0, Dp0, Alog1, Dp1);

    // ym = gy @ {Wout0|Wout1}  1-pass, bw flip-stored.  M=8192 N=1024 K=2048
    mma_gemm<false,false><<<dim3(8, 64), 256, SMEM_GEMM>>>(
        gyh, DI, tWoH0, nullptr, tWoH1, nullptr, DI, DI,
        ym, DM, nullptr, NR, 0, 1, EP_NONE, nullptr, nullptr, 0);

    // ycomb = LN(ym_fw + x) + LN(ym_bw + x)
    ln_dual_kernel<<<NR, 256>>>(x, fwn_w, fwn_b);

    // ffh(fp16 only) = relu(ycomb @ W1 + b1)  1-pass, M=4096 N=2048 K=1024
    mma_gemm<false,false><<<dim3(16, 32), 256, SMEM_GEMM>>>(
        ych, DM, tF1H, nullptr, nullptr, nullptr, DM, DM,
        nullptr, DI, fhh, 0, 0, 0, EP_RELU, ff_b1, nullptr, 0);

    // ff = ffh @ W2 + b2  1-pass, M=4096 N=1024 K=2048
    mma_gemm<false,false><<<dim3(8, 32), 256, SMEM_GEMM>>>(
        fhh, DI, tF2H, nullptr, nullptr, nullptr, DI, DI,
        ff, DM, nullptr, 0, 0, 0, EP_BIAS, ff_b2, nullptr, 0);

    // out = LN(ff + ycomb)
    ln_final_kernel<<<NR, 256>>>(fin_w, fin_b, (float*)d_out);
}

// round 9
// speedup vs baseline: 6.8589x; 1.1141x over previous
#include <cuda_runtime.h>
#include <cuda_fp16.h>
#include <math.h>
#include <stdint.h>

// ---------------------------------------------------------------------------
// BiMamba on GB300 (sm_103 baseline PTX).  R6 GEMM structure (known good),
// plus t-major scan fed by explicit fp32 transposes.
// ---------------------------------------------------------------------------

#define NB   2
#define SEQ  2048
#define DM   1024
#define DI   2048
#define DS   16
#define DTR  64
#define NXP  128
#define NR   (NB*SEQ)        // 4096 rows per direction
#define NR2  (2*NR)          // 8192 combined
#define LN_EPS 1e-5f

#define EP_NONE     0
#define EP_SOFTPLUS 1
#define EP_RELU     2
#define EP_BIAS     3

// ---- scratch ---------------------------------------------------------------
__device__ float g_xz  [(size_t)NR2 * 2 * DI];    // [token][4096] row-major
__device__ float g_xi  [(size_t)NR2 * DI];        // [token][d]
__device__ float g_xdbc[(size_t)NR2 * NXP];
__device__ float g_xdp [(size_t)4 * NR2 * NXP];
__device__ float g_dt  [(size_t)NR2 * DI];        // [token][d]
__device__ float g_dtT [(size_t)NR2 * DI];        // [ch][t]
__device__ float g_xiT [(size_t)NR2 * DI];        // [ch][t]
__device__ float g_zT  [(size_t)NR2 * DI];        // [ch][t]
__device__ float g_ym  [(size_t)NR2 * DM];
__device__ float g_ycomb[(size_t)NR * DM];
__device__ float g_ff  [(size_t)NR * DM];

__device__ __half g_xh  [(size_t)NR*DM];
__device__ __half g_xih [(size_t)NR2*DI];         // [token][d] fp16
__device__ __half g_xdh [(size_t)NR2*NXP];
__device__ __half g_gyT [(size_t)NR2*DI];         // [ch][t] fp16 (scan out)
__device__ __half g_gyh [(size_t)NR2*DI];         // [token][d] fp16 (ym GEMM in)
__device__ __half g_ych [(size_t)NR*DM];
__device__ __half g_fhh [(size_t)NR*DI];

// transposed weights [N][K] fp16 hi/lo (lo only for Wx, Wdt)
__device__ __half g_tWinH0[(size_t)4096*1024];
__device__ __half g_tWinH1[(size_t)4096*1024];
__device__ __half g_tWxH0 [(size_t)128*2048],  g_tWxL0 [(size_t)128*2048];
__device__ __half g_tWxH1 [(size_t)128*2048],  g_tWxL1 [(size_t)128*2048];
__device__ __half g_tWdtH0[(size_t)2048*64],   g_tWdtL0[(size_t)2048*64];
__device__ __half g_tWdtH1[(size_t)2048*64],   g_tWdtL1[(size_t)2048*64];
__device__ __half g_tWoH0 [(size_t)1024*2048];
__device__ __half g_tWoH1 [(size_t)1024*2048];
__device__ __half g_tF1H  [(size_t)2048*1024];
__device__ __half g_tF2H  [(size_t)1024*2048];

// ---------------------------------------------------------------------------
// helpers
// ---------------------------------------------------------------------------
__device__ __forceinline__ uint32_t smem_u32(const void* p) {
    uint32_t a;
    asm("{ .reg .u64 t; cvta.to.shared.u64 t, %1; cvt.u32.u64 %0, t; }"
        : "=r"(a) : "l"(p));
    return a;
}
__device__ __forceinline__ void ldsm4(uint32_t* r, uint32_t addr) {
    asm volatile("ldmatrix.sync.aligned.m8n8.x4.shared.b16 {%0,%1,%2,%3}, [%4];"
        : "=r"(r[0]), "=r"(r[1]), "=r"(r[2]), "=r"(r[3]) : "r"(addr));
}
__device__ __forceinline__ void mma_f16(float* c, const uint32_t* a, const uint32_t* b) {
    asm volatile("mma.sync.aligned.m16n8k16.row.col.f32.f16.f16.f32 "
        "{%0,%1,%2,%3}, {%4,%5,%6,%7}, {%8,%9}, {%0,%1,%2,%3};"
        : "+f"(c[0]), "+f"(c[1]), "+f"(c[2]), "+f"(c[3])
        : "r"(a[0]), "r"(a[1]), "r"(a[2]), "r"(a[3]), "r"(b[0]), "r"(b[1]));
}
__device__ __forceinline__ void cp16(uint32_t dst, const void* src) {
    asm volatile("{ .reg .u64 g; cvta.to.global.u64 g, %1; "
                 "cp.async.cg.shared.global [%0], [g], 16; }"
                 :: "r"(dst), "l"(src) : "memory");
}
#define CP_COMMIT() asm volatile("cp.async.commit_group;" ::: "memory")
#define CP_WAIT1()  asm volatile("cp.async.wait_group 1;" ::: "memory")

__device__ __forceinline__ int fliprow(int m) {
    return (m & ~(SEQ - 1)) | ((SEQ - 1) - (m & (SEQ - 1)));
}
__device__ __forceinline__ void split_h(float v, __half& h, __half& l) {
    h = __float2half_rn(v);
    l = __float2half_rn(v - __half2float(h));
}

// ---------------------------------------------------------------------------
// GEMM (R6 verbatim): C[M,N] = A[M,K] @ B[N,K]^T.  A fp16; B fp16 (1-pass)
// or hi/lo (2-pass).  Dual weights by M-half; flipA2/flipC2 on second half;
// split-K via blockIdx.z.  CTA 128x128, 8 warps, K-stage 32, 3-stage ring.
// ---------------------------------------------------------------------------
#define ROWB  80
#define PLANE (128 * ROWB)
#define STG   (3 * PLANE)
#define NSTAGE 3
#define SMEM_GEMM (NSTAGE * STG)

template<bool TWOPASS, bool SPLITK>
__global__ void __launch_bounds__(256, 2)
mma_gemm(const __half* __restrict__ Aa, int lda,
         const __half* __restrict__ B1h, const __half* __restrict__ B1l,
         const __half* __restrict__ B2h, const __half* __restrict__ B2l,
         int K, int ldb,
         float* __restrict__ C, int ldc, __half* __restrict__ Ch,
         int mhalf, int flipA2, int flipC2,
         int epi, const float* __restrict__ bias1, const float* __restrict__ bias2,
         int zrows)
{
    extern __shared__ char smem[];
    const uint32_t sb = smem_u32(smem);

    const int tid  = threadIdx.x;
    const int wid  = tid >> 5, lane = tid & 31;
    const int wm   = wid >> 2, wn = wid & 3;
    const int bm   = blockIdx.y * 128;
    const int bn   = blockIdx.x * 128;
    const int koff = SPLITK ? blockIdx.z * K : 0;
    if (SPLITK && C) C += (size_t)blockIdx.z * zrows * ldc;

    const int half2 = (mhalf > 0) && (bm >= mhalf);
    const __half* Bth = half2 ? B2h : B1h;
    const __half* Btl = half2 ? B2l : B1l;
    const float*  bias = half2 ? bias2 : bias1;

    constexpr int NJ = TWOPASS ? 6 : 4;
    const __half* src[NJ];
    uint32_t dst0[NJ];
    #pragma unroll
    for (int j = 0; j < NJ; ++j) {
        const int c = j * 256 + tid;
        const int plane = c >> 9;                 // 0 A, 1 Bh, 2 Bl
        const int r = (c >> 2) & 127;
        const int q = c & 3;
        dst0[j] = sb + plane * PLANE + r * ROWB + q * 16;
        if (plane == 0) {
            int m = bm + r;
            if (half2 && flipA2) m = fliprow(m & (mhalf - 1));
            src[j] = Aa + (size_t)m * lda + koff + q * 8;
        } else {
            src[j] = ((plane == 2) ? Btl : Bth) + (size_t)(bn + r) * ldb + koff + q * 8;
        }
    }

    const uint32_t a_loff = ((lane & 7) + ((lane >> 3) & 1) * 8) * ROWB + (lane >> 4) * 16;
    const uint32_t b_loff = ((lane & 7) + (lane >> 4) * 8) * ROWB + ((lane >> 3) & 1) * 16;
    const uint32_t aw = wm * 64 * ROWB + a_loff;
    const uint32_t bw = PLANE + wn * 32 * ROWB + b_loff;

    float acc[4][4][4];
    #pragma unroll
    for (int mt = 0; mt < 4; ++mt)
        #pragma unroll
        for (int nt = 0; nt < 4; ++nt)
            #pragma unroll
            for (int i = 0; i < 4; ++i) acc[mt][nt][i] = 0.f;

    const int S = K / 32;
    int ns = 0;
    #pragma unroll
    for (int p = 0; p < NSTAGE - 1; ++p) {
        if (p < S) {
            const uint32_t so = (uint32_t)p * STG;
            #pragma unroll
            for (int j = 0; j < NJ; ++j) cp16(dst0[j] + so, src[j] + p * 32);
            ++ns;
        }
        CP_COMMIT();
    }

    for (int s = 0; s < S; ++s) {
        CP_WAIT1();
        __syncthreads();

        if (ns < S) {
            const uint32_t so = (uint32_t)(ns % NSTAGE) * STG;
            const int kt = ns * 32;
            #pragma unroll
            for (int j = 0; j < NJ; ++j) cp16(dst0[j] + so, src[j] + kt);
            ++ns;
        }
        CP_COMMIT();

        const uint32_t bo = sb + (uint32_t)(s % NSTAGE) * STG;
        #pragma unroll
        for (int ks = 0; ks < 2; ++ks) {
            uint32_t bh[8];
            ldsm4(&bh[0], bo + bw + ks * 32);
            ldsm4(&bh[4], bo + bw + 16 * ROWB + ks * 32);
            uint32_t bl[8];
            if (TWOPASS) {
                ldsm4(&bl[0], bo + bw + PLANE + ks * 32);
                ldsm4(&bl[4], bo + bw + PLANE + 16 * ROWB + ks * 32);
            }
            #pragma unroll
            for (int mt = 0; mt < 4; ++mt) {
                uint32_t a[4];
                ldsm4(a, bo + aw + mt * 16 * ROWB + ks * 32);
                #pragma unroll
                for (int nt = 0; nt < 4; ++nt) mma_f16(acc[mt][nt], a, &bh[nt * 2]);
                if (TWOPASS) {
                    #pragma unroll
                    for (int nt = 0; nt < 4; ++nt) mma_f16(acc[mt][nt], a, &bl[nt * 2]);
                }
            }
        }
    }

    // epilogue
    #pragma unroll
    for (int mt = 0; mt < 4; ++mt) {
        const int r0 = bm + wm * 64 + mt * 16 + (lane >> 2);
        #pragma unroll
        for (int half = 0; half < 2; ++half) {
            const int rg = r0 + half * 8;
            int mg = rg;
            if (half2 && flipC2) mg = mhalf + fliprow(rg & (mhalf - 1));
            float* crow = C + (size_t)mg * ldc;
            #pragma unroll
            for (int nt = 0; nt < 4; ++nt) {
                const int col = bn + wn * 32 + nt * 8 + (lane & 3) * 2;
                float v0 = acc[mt][nt][half * 2 + 0];
                float v1 = acc[mt][nt][half * 2 + 1];
                if (epi != EP_NONE) { v0 += bias[col]; v1 += bias[col + 1]; }
                if (epi == EP_SOFTPLUS) {
                    v0 = (v0 > 20.f) ? v0 : log1pf(expf(v0));
                    v1 = (v1 > 20.f) ? v1 : log1pf(expf(v1));
                } else if (epi == EP_RELU) {
                    v0 = fmaxf(v0, 0.f); v1 = fmaxf(v1, 0.f);
                }
                if (C) *reinterpret_cast<float2*>(crow + col) = make_float2(v0, v1);
                if (Ch) {
                    __half2 p; p.x = __float2half_rn(v0); p.y = __float2half_rn(v1);
                    *reinterpret_cast<__half2*>(Ch + (size_t)mg * ldc + col) = p;
                }
            }
        }
    }
}

// ---------------------------------------------------------------------------
// batched transpose + hi/lo fp16:  W[K][N] fp32 -> Th/Tl [Npad][K]
// ---------------------------------------------------------------------------
struct TBatch {
    const float* W[8];
    __half* Th[8];
    __half* Tl[8];
    int K[8], N[8], Npad[8], ntiles[8];
    int count;
};

__global__ void __launch_bounds__(256)
transpose_batch(TBatch P)
{
    int t = blockIdx.x;
    int di = 0, base = 0;
    while (di < P.count && t >= base + P.ntiles[di]) { base += P.ntiles[di]; ++di; }
    if (di >= P.count) return;
    const int local = t - base;
    const int nx = P.Npad[di] / 32;
    const int k0 = (local / nx) * 32;
    const int n0 = (local % nx) * 32;
    const float* W = P.W[di];
    const int K = P.K[di], N = P.N[di];

    __shared__ float tsh[32][33];
    const int tx = threadIdx.x & 31, ty = threadIdx.x >> 5;
    #pragma unroll
    for (int i = 0; i < 4; ++i) {
        int k = k0 + ty + i * 8, n = n0 + tx;
        tsh[ty + i * 8][tx] = (n < N) ? W[(size_t)k * N + n] : 0.f;
    }
    __syncthreads();
    __half* Th = P.Th[di]; __half* Tl = P.Tl[di];
    #pragma unroll
    for (int i = 0; i < 4; ++i) {
        int n = n0 + ty + i * 8, k = k0 + tx;
        float v = tsh[tx][ty + i * 8];
        __half h, l; split_h(v, h, l);
        Th[(size_t)n * K + k] = h;
        if (Tl) Tl[(size_t)n * K + k] = l;
    }
}

__global__ void __launch_bounds__(256)
convert_h(const float* __restrict__ src, __half* __restrict__ h, int n)
{
    int i = blockIdx.x * 256 + threadIdx.x;
    if (i < n) h[i] = __float2half_rn(src[i]);
}

__global__ void __launch_bounds__(256)
reduce_xdbc()
{
    int i = blockIdx.x * 256 + threadIdx.x;
    const size_t P = (size_t)NR2 * NXP;
    float s = g_xdp[i] + g_xdp[P + i] + g_xdp[2*P + i] + g_xdp[3*P + i];
    g_xdbc[i] = s;
    g_xdh[i]  = __float2half_rn(s);
}

// ---------------------------------------------------------------------------
// causal dwconv(4) + SiLU (R6 form, row-major)
// ---------------------------------------------------------------------------
__global__ void __launch_bounds__(256)
conv_silu_kernel(const float* __restrict__ convw0, const float* __restrict__ convb0,
                 const float* __restrict__ convw1, const float* __restrict__ convb1)
{
    int idx = blockIdx.x * 256 + threadIdx.x;
    if (idx >= NR2 * DI) return;
    int d = idx % DI, n = idx / DI;
    int dir = n >> 12;
    int t = n & (SEQ - 1);
    const float* convw = dir ? convw1 : convw0;
    const float* convb = dir ? convb1 : convb0;
    float4 w = *reinterpret_cast<const float4*>(convw + d * 4);
    float acc = convb[d];
    const float* base = g_xz + (size_t)(n & ~(SEQ - 1)) * (2 * DI) + d;
    if (t >= 3) {
        acc = fmaf(base[(size_t)(t-3)*(2*DI)], w.x, acc);
        acc = fmaf(base[(size_t)(t-2)*(2*DI)], w.y, acc);
        acc = fmaf(base[(size_t)(t-1)*(2*DI)], w.z, acc);
        acc = fmaf(base[(size_t)(t  )*(2*DI)], w.w, acc);
    } else {
        if (t-3 >= 0) acc = fmaf(base[(size_t)(t-3)*(2*DI)], w.x, acc);
        if (t-2 >= 0) acc = fmaf(base[(size_t)(t-2)*(2*DI)], w.y, acc);
        if (t-1 >= 0) acc = fmaf(base[(size_t)(t-1)*(2*DI)], w.z, acc);
        acc = fmaf(base[(size_t)t*(2*DI)], w.w, acc);
    }
    float y = acc / (1.f + expf(-acc));
    g_xi[idx]  = y;
    g_xih[idx] = __float2half_rn(y);
}

// ---------------------------------------------------------------------------
// transpose3: dt/xi/z  [token][d] -> [ch][t]   (token = dirb*2048+t,
// ch = dirb*2048+d; per-dirb 2048x2048 transpose, 32x32 tiles)
// ---------------------------------------------------------------------------
__global__ void __launch_bounds__(256)
transpose3_kernel()
{
    __shared__ float s_dt[32][33];
    __shared__ float s_xi[32][33];
    __shared__ float s_z [32][33];

    const int d0   = blockIdx.x * 32;
    const int t0   = blockIdx.y * 32;
    const int dirb = blockIdx.z;
    const size_t rowbase = (size_t)dirb * 2048;

    const int tx = threadIdx.x & 31, ty = threadIdx.x >> 5;
    #pragma unroll
    for (int i = 0; i < 4; ++i) {
        const int tt = t0 + ty + i * 8;
        const size_t tok = rowbase + tt;
        const int dd = d0 + tx;
        s_dt[ty + i * 8][tx] = g_dt[tok * DI + dd];
        s_xi[ty + i * 8][tx] = g_xi[tok * DI + dd];
        s_z [ty + i * 8][tx] = g_xz[tok * (2 * DI) + DI + dd];
    }
    __syncthreads();
    #pragma unroll
    for (int i = 0; i < 4; ++i) {
        const int dd = d0 + ty + i * 8;
        const size_t ch = rowbase + dd;
        const int tt = t0 + tx;
        g_dtT[ch * SEQ + tt] = s_dt[tx][ty + i * 8];
        g_xiT[ch * SEQ + tt] = s_xi[tx][ty + i * 8];
        g_zT [ch * SEQ + tt] = s_z [tx][ty + i * 8];
    }
}

// transpose gyT [ch][t] fp16 -> gyh [token][d] fp16
__global__ void __launch_bounds__(256)
transpose_gy16()
{
    __shared__ __half s[32][34];
    const int t0   = blockIdx.x * 32;
    const int d0   = blockIdx.y * 32;
    const int dirb = blockIdx.z;
    const size_t rowbase = (size_t)dirb * 2048;

    const int tx = threadIdx.x & 31, ty = threadIdx.x >> 5;
    #pragma unroll
    for (int i = 0; i < 4; ++i) {
        const size_t ch = rowbase + d0 + ty + i * 8;
        s[ty + i * 8][tx] = g_gyT[ch * SEQ + t0 + tx];
    }
    __syncthreads();
    #pragma unroll
    for (int i = 0; i < 4; ++i) {
        const size_t tok = rowbase + t0 + ty + i * 8;
        g_gyh[tok * DI + d0 + tx] = s[tx][ty + i * 8];
    }
}

// ---------------------------------------------------------------------------
// selective scan, t-major, unroll x8
// ---------------------------------------------------------------------------
__global__ void __launch_bounds__(256)
scan_kernel(const float* __restrict__ Alog0, const float* __restrict__ Dpar0,
            const float* __restrict__ Alog1, const float* __restrict__ Dpar1)
{
    const int lane = threadIdx.x & 31;
    const int gw   = blockIdx.x * 8 + (threadIdx.x >> 5);   // 4096 warps
    const int half = lane >> 4;
    const int s    = lane & 15;
    const int ch   = gw * 2 + half;                          // 0..8191
    const int dirb = ch >> 11;
    const int d    = ch & 2047;
    const int dir  = dirb >> 1;

    const float* Alog = dir ? Alog1 : Alog0;
    const float* Dpar = dir ? Dpar1 : Dpar0;
    const float Ac = -expf(Alog[d * DS + s]);
    const float Dp = Dpar[d];

    const float* dt_p = g_dtT + (size_t)ch * SEQ;
    const float* u_p  = g_xiT + (size_t)ch * SEQ;
    const float* z_p  = g_zT  + (size_t)ch * SEQ;
    const float* bc_p = g_xdbc + (size_t)dirb * SEQ * NXP + DTR + s;
    __half*      o_p  = g_gyT + (size_t)ch * SEQ;

    float h = 0.f;
    for (int t0 = 0; t0 < SEQ; t0 += 8) {
        float4 dtA = *reinterpret_cast<const float4*>(dt_p + t0);
        float4 dtB = *reinterpret_cast<const float4*>(dt_p + t0 + 4);
        float4 uA  = *reinterpret_cast<const float4*>(u_p + t0);
        float4 uB  = *reinterpret_cast<const float4*>(u_p + t0 + 4);
        float4 zA  = *reinterpret_cast<const float4*>(z_p + t0);
        float4 zB  = *reinterpret_cast<const float4*>(z_p + t0 + 4);
        float dtv[8] = {dtA.x, dtA.y, dtA.z, dtA.w, dtB.x, dtB.y, dtB.z, dtB.w};
        float uu[8]  = {uA.x, uA.y, uA.z, uA.w, uB.x, uB.y, uB.z, uB.w};
        float zf[8]  = {zA.x, zA.y, zA.z, zA.w, zB.x, zB.y, zB.z, zB.w};
        float Bv[8], Cv[8];
        #pragma unroll
        for (int i = 0; i < 8; ++i) {
            Bv[i] = bc_p[(size_t)(t0 + i) * NXP];
            Cv[i] = bc_p[(size_t)(t0 + i) * NXP + DS];
        }
        __half ov[8];
        #pragma unroll
        for (int i = 0; i < 8; ++i) {
            const float dA = __expf(dtv[i] * Ac);
            h = fmaf(dA, h, dtv[i] * uu[i] * Bv[i]);
            float p = h * Cv[i];
            #pragma unroll
            for (int o = 8; o; o >>= 1) p += __shfl_xor_sync(0xffffffffu, p, o);
            const float z = zf[i];
            const float gt = z / (1.f + __expf(-z));
            ov[i] = __float2half_rn((p + uu[i] * Dp) * gt);
        }
        if (s == 0)
            *reinterpret_cast<uint4*>(o_p + t0) = *reinterpret_cast<uint4*>(ov);
    }
}

// ---------------------------------------------------------------------------
// layernorms
// ---------------------------------------------------------------------------
__device__ __forceinline__ float blockReduceSum(float v)
{
    __shared__ float sh[8];
    __syncthreads();
    #pragma unroll
    for (int o = 16; o; o >>= 1) v += __shfl_xor_sync(0xffffffffu, v, o);
    if ((threadIdx.x & 31) == 0) sh[threadIdx.x >> 5] = v;
    __syncthreads();
    if (threadIdx.x < 32) {
        float t = (threadIdx.x < 8) ? sh[threadIdx.x] : 0.f;
        #pragma unroll
        for (int o = 4; o; o >>= 1) t += __shfl_xor_sync(0xffffffffu, t, o);
        if (threadIdx.x == 0) sh[0] = t;
    }
    __syncthreads();
    return sh[0];
}

__global__ void __launch_bounds__(256)
ln_dual_kernel(const float* __restrict__ x,
               const float* __restrict__ w, const float* __restrict__ bs)
{
    const int row = blockIdx.x;
    const float* xr = x    + (size_t)row * DM;
    const float* fr = g_ym + (size_t)row * DM;
    const float* br = g_ym + (size_t)(NR + row) * DM;
    float* out      = g_ycomb + (size_t)row * DM;
    __half* oh      = g_ych   + (size_t)row * DM;

    float a[4], c[4];
    float sa = 0.f, sb = 0.f;
    #pragma unroll
    for (int i = 0; i < 4; ++i) {
        int idx = threadIdx.x + i * 256;
        float xv = xr[idx];
        a[i] = fr[idx] + xv;
        c[i] = br[idx] + xv;
        sa += a[i]; sb += c[i];
    }
    sa = blockReduceSum(sa);
    sb = blockReduceSum(sb);
    const float mua = sa * (1.f / DM), mub = sb * (1.f / DM);
    float va = 0.f, vb = 0.f;
    #pragma unroll
    for (int i = 0; i < 4; ++i) {
        float da = a[i] - mua; va += da * da;
        float db = c[i] - mub; vb += db * db;
    }
    va = blockReduceSum(va);
    vb = blockReduceSum(vb);
    const float ra = rsqrtf(va * (1.f / DM) + LN_EPS);
    const float rb = rsqrtf(vb * (1.f / DM) + LN_EPS);
    #pragma unroll
    for (int i = 0; i < 4; ++i) {
        int idx = threadIdx.x + i * 256;
        float wv = w[idx], bv = bs[idx];
        float o = ((a[i] - mua) * ra * wv + bv) + ((c[i] - mub) * rb * wv + bv);
        out[idx] = o;
        oh[idx]  = __float2half_rn(o);
    }
}

__global__ void __launch_bounds__(256)
ln_final_kernel(const float* __restrict__ w, const float* __restrict__ bs,
                float* __restrict__ out)
{
    const int row = blockIdx.x;
    const float* fr = g_ff    + (size_t)row * DM;
    const float* yr = g_ycomb + (size_t)row * DM;
    float* orow = out + (size_t)row * DM;

    float a[4];
    float sa = 0.f;
    #pragma unroll
    for (int i = 0; i < 4; ++i) {
        int idx = threadIdx.x + i * 256;
        a[i] = fr[idx] + yr[idx];
        sa += a[i];
    }
    sa = blockReduceSum(sa);
    const float mu = sa * (1.f / DM);
    float va = 0.f;
    #pragma unroll
    for (int i = 0; i < 4; ++i) { float dd = a[i] - mu; va += dd * dd; }
    va = blockReduceSum(va);
    const float rs = rsqrtf(va * (1.f / DM) + LN_EPS);
    #pragma unroll
    for (int i = 0; i < 4; ++i) {
        int idx = threadIdx.x + i * 256;
        orow[idx] = (a[i] - mu) * rs * w[idx] + bs[idx];
    }
}

// ---------------------------------------------------------------------------
// launch
// ---------------------------------------------------------------------------
extern "C" void kernel_launch(void* const* d_in, const int* in_sizes, int n_in,
                              void* d_out, int out_size)
{
    (void)in_sizes; (void)n_in; (void)out_size;
    const float* x      = (const float*)d_in[0];
    const float* Win0   = (const float*)d_in[1];
    const float* convw0 = (const float*)d_in[2];
    const float* convb0 = (const float*)d_in[3];
    const float* Wx0    = (const float*)d_in[4];
    const float* Wdt0   = (const float*)d_in[5];
    const float* bdt0   = (const float*)d_in[6];
    const float* Alog0  = (const float*)d_in[7];
    const float* Dp0    = (const float*)d_in[8];
    const float* Wout0  = (const float*)d_in[9];
    const float* Win1   = (const float*)d_in[10];
    const float* convw1 = (const float*)d_in[11];
    const float* convb1 = (const float*)d_in[12];
    const float* Wx1    = (const float*)d_in[13];
    const float* Wdt1   = (const float*)d_in[14];
    const float* bdt1   = (const float*)d_in[15];
    const float* Alog1  = (const float*)d_in[16];
    const float* Dp1    = (const float*)d_in[17];
    const float* Wout1  = (const float*)d_in[18];
    const float* fwn_w  = (const float*)d_in[19];
    const float* fwn_b  = (const float*)d_in[20];
    const float* fin_w  = (const float*)d_in[21];
    const float* fin_b  = (const float*)d_in[22];
    const float* ff_W1  = (const float*)d_in[23];
    const float* ff_b1  = (const float*)d_in[24];
    const float* ff_W2  = (const float*)d_in[25];
    const float* ff_b2  = (const float*)d_in[26];

    cudaFuncSetAttribute(mma_gemm<true,false>,  cudaFuncAttributeMaxDynamicSharedMemorySize, SMEM_GEMM);
    cudaFuncSetAttribute(mma_gemm<false,false>, cudaFuncAttributeMaxDynamicSharedMemorySize, SMEM_GEMM);
    cudaFuncSetAttribute(mma_gemm<true,true>,   cudaFuncAttributeMaxDynamicSharedMemorySize, SMEM_GEMM);

    float *xz, *xi, *xdbc, *xdp, *dt, *ym, *ycomb, *ff;
    cudaGetSymbolAddress((void**)&xz, g_xz);       cudaGetSymbolAddress((void**)&xi, g_xi);
    cudaGetSymbolAddress((void**)&xdbc, g_xdbc);   cudaGetSymbolAddress((void**)&xdp, g_xdp);
    cudaGetSymbolAddress((void**)&dt, g_dt);       cudaGetSymbolAddress((void**)&ym, g_ym);
    cudaGetSymbolAddress((void**)&ycomb, g_ycomb); cudaGetSymbolAddress((void**)&ff, g_ff);

    __half *xh, *xih, *xdh, *gyh, *ych, *fhh;
    cudaGetSymbolAddress((void**)&xh, g_xh);   cudaGetSymbolAddress((void**)&xih, g_xih);
    cudaGetSymbolAddress((void**)&xdh, g_xdh); cudaGetSymbolAddress((void**)&gyh, g_gyh);
    cudaGetSymbolAddress((void**)&ych, g_ych); cudaGetSymbolAddress((void**)&fhh, g_fhh);

    __half *tWinH0,*tWinH1,*tWxH0,*tWxL0,*tWxH1,*tWxL1;
    __half *tWdtH0,*tWdtL0,*tWdtH1,*tWdtL1,*tWoH0,*tWoH1,*tF1H,*tF2H;
    cudaGetSymbolAddress((void**)&tWinH0, g_tWinH0);
    cudaGetSymbolAddress((void**)&tWinH1, g_tWinH1);
    cudaGetSymbolAddress((void**)&tWxH0, g_tWxH0);   cudaGetSymbolAddress((void**)&tWxL0, g_tWxL0);
    cudaGetSymbolAddress((void**)&tWxH1, g_tWxH1);   cudaGetSymbolAddress((void**)&tWxL1, g_tWxL1);
    cudaGetSymbolAddress((void**)&tWdtH0, g_tWdtH0); cudaGetSymbolAddress((void**)&tWdtL0, g_tWdtL0);
    cudaGetSymbolAddress((void**)&tWdtH1, g_tWdtH1); cudaGetSymbolAddress((void**)&tWdtL1, g_tWdtL1);
    cudaGetSymbolAddress((void**)&tWoH0, g_tWoH0);
    cudaGetSymbolAddress((void**)&tWoH1, g_tWoH1);
    cudaGetSymbolAddress((void**)&tF1H, g_tF1H);
    cudaGetSymbolAddress((void**)&tF2H, g_tF2H);

    // 0: x -> fp16
    convert_h<<<(NR*DM)/256, 256>>>(x, xh, NR*DM);

    // 1: Win transposes (hi only)
    {
        TBatch P = {};
        P.count = 2;
        P.W[0]=Win0; P.Th[0]=tWinH0; P.Tl[0]=nullptr; P.K[0]=1024; P.N[0]=4096; P.Npad[0]=4096; P.ntiles[0]=4096;
        P.W[1]=Win1; P.Th[1]=tWinH1; P.Tl[1]=nullptr; P.K[1]=1024; P.N[1]=4096; P.Npad[1]=4096; P.ntiles[1]=4096;
        transpose_batch<<<8192, 256>>>(P);
    }
    // 2: remaining transposes
    {
        TBatch P = {};
        P.count = 8;
        P.W[0]=Wx0;   P.Th[0]=tWxH0;  P.Tl[0]=tWxL0;   P.K[0]=2048; P.N[0]=96;   P.Npad[0]=128;  P.ntiles[0]=256;
        P.W[1]=Wx1;   P.Th[1]=tWxH1;  P.Tl[1]=tWxL1;   P.K[1]=2048; P.N[1]=96;   P.Npad[1]=128;  P.ntiles[1]=256;
        P.W[2]=Wdt0;  P.Th[2]=tWdtH0; P.Tl[2]=tWdtL0;  P.K[2]=64;   P.N[2]=2048; P.Npad[2]=2048; P.ntiles[2]=128;
        P.W[3]=Wdt1;  P.Th[3]=tWdtH1; P.Tl[3]=tWdtL1;  P.K[3]=64;   P.N[3]=2048; P.Npad[3]=2048; P.ntiles[3]=128;
        P.W[4]=Wout0; P.Th[4]=tWoH0;  P.Tl[4]=nullptr; P.K[4]=2048; P.N[4]=1024; P.Npad[4]=1024; P.ntiles[4]=2048;
        P.W[5]=Wout1; P.Th[5]=tWoH1;  P.Tl[5]=nullptr; P.K[5]=2048; P.N[5]=1024; P.Npad[5]=1024; P.ntiles[5]=2048;
        P.W[6]=ff_W1; P.Th[6]=tF1H;   P.Tl[6]=nullptr; P.K[6]=1024; P.N[6]=2048; P.Npad[6]=2048; P.ntiles[6]=2048;
        P.W[7]=ff_W2; P.Th[7]=tF2H;   P.Tl[7]=nullptr; P.K[7]=2048; P.N[7]=1024; P.Npad[7]=1024; P.ntiles[7]=2048;
        transpose_batch<<<8960, 256>>>(P);
    }

    // 3 (profiled): xz = [x ; flip(x)] @ {Win0|Win1}  1-pass, M=8192 N=4096 K=1024
    mma_gemm<false,false><<<dim3(32, 64), 256, SMEM_GEMM>>>(
        xh, DM, tWinH0, nullptr, tWinH1, nullptr, DM, DM,
        xz, 2*DI, nullptr, NR, 1, 0, EP_NONE, nullptr, nullptr, 0);

    // 4: conv + silu
    conv_silu_kernel<<<(NR2*DI)/256, 256>>>(convw0, convb0, convw1, convb1);

    // 5: xdbc partials: split-K=4, 2-pass.  M=8192 N=128 Kchunk=512, ldb=2048
    mma_gemm<true,true><<<dim3(1, 64, 4), 256, SMEM_GEMM>>>(
        xih, DI, tWxH0, tWxL0, tWxH1, tWxL1, 512, DI,
        xdp, NXP, nullptr, NR, 0, 0, EP_NONE, nullptr, nullptr, NR2);

    // 6: reduce partials
    reduce_xdbc<<<(NR2*NXP)/256, 256>>>();

    // 7: dt = softplus(xdh[:, :64] @ {Wdt0|Wdt1} + bdt)  2-pass, M=8192 N=2048 K=64
    mma_gemm<true,false><<<dim3(16, 64), 256, SMEM_GEMM>>>(
        xdh, NXP, tWdtH0, tWdtL0, tWdtH1, tWdtL1, DTR, DTR,
        dt, DI, nullptr, NR, 0, 0, EP_SOFTPLUS, bdt0, bdt1, 0);

    // 8: transpose dt / xi / z into t-major
    transpose3_kernel<<<dim3(64, 64, 4), 256>>>();

    // 9: selective scan (t-major)
    scan_kernel<<<512, 256>>>(Alog0, Dp0, Alog1, Dp1);

    // 10: gy^T -> row-major fp16
    transpose_gy16<<<dim3(64, 64, 4), 256>>>();

    // 11: ym = gy @ {Wout0|Wout1}  1-pass, bw flip-stored.  M=8192 N=1024 K=2048
    mma_gemm<false,false><<<dim3(8, 64), 256, SMEM_GEMM>>>(
        gyh, DI, tWoH0, nullptr, tWoH1, nullptr, DI, DI,
        ym, DM, nullptr, NR, 0, 1, EP_NONE, nullptr, nullptr, 0);

    // 12: ycomb = LN(ym_fw + x) + LN(ym_bw + x)
    ln_dual_kernel<<<NR, 256>>>(x, fwn_w, fwn_b);

    // 13: ffh(fp16 only) = relu(ycomb @ W1 + b1)  1-pass, M=4096 N=2048 K=1024
    mma_gemm<false,false><<<dim3(16, 32), 256, SMEM_GEMM>>>(
        ych, DM, tF1H, nullptr, nullptr, nullptr, DM, DM,
        nullptr, DI, fhh, 0, 0, 0, EP_RELU, ff_b1, nullptr, 0);

    // 14: ff = ffh @ W2 + b2  1-pass, M=4096 N=1024 K=2048
    mma_gemm<false,false><<<dim3(8, 32), 256, SMEM_GEMM>>>(
        fhh, DI, tF2H, nullptr, nullptr, nullptr, DI, DI,
        ff, DM, nullptr, 0, 0, 0, EP_BIAS, ff_b2, nullptr, 0);

    // 15: out = LN(ff + ycomb)
    ln_final_kernel<<<NR, 256>>>(fin_w, fin_b, (float*)d_out);
}

// round 10
// speedup vs baseline: 7.3991x; 1.0787x over previous
#include <cuda_runtime.h>
#include <cuda_fp16.h>
#include <math.h>
#include <stdint.h>

// ---------------------------------------------------------------------------
// BiMamba on GB300 (sm_103 baseline PTX).  Fully t-major scan dataflow:
// Win GEMM -> xz^T (fp32), conv coalesced per-channel, dt GEMM -> dt^T,
// scan with contiguous loads, ym/Wx GEMMs consume t-major via ldmatrix.trans.
// Fix vs R8: dual-A (selA==1) second-half row index is array-local.
// ---------------------------------------------------------------------------

#define NB   2
#define SEQ  2048
#define DM   1024
#define DI   2048
#define DS   16
#define DTR  64
#define NXP  128
#define NR   (NB*SEQ)        // 4096 rows per direction
#define NR2  (2*NR)          // 8192
#define LN_EPS 1e-5f

#define EP_NONE     0
#define EP_SOFTPLUS 1
#define EP_RELU     2
#define EP_BIAS     3

// ---- scratch ---------------------------------------------------------------
__device__ float  g_xzT [(size_t)NR2 * 4096];   // xz^T  [dir*4096 + c][b*2048+t] fp32
__device__ float  g_xiT [(size_t)NR2 * DI];     // xi^T  [ch][t] fp32 (scan u)
__device__ __half g_xih [(size_t)NR2 * DI];     // xi^T fp16 (Wx GEMM)
__device__ float  g_xdbc[(size_t)NR2 * NXP];
__device__ float  g_xdp [(size_t)4 * NR2 * NXP];
__device__ __half g_xdh [(size_t)NR2 * NXP];
__device__ float  g_dtT [(size_t)NR2 * DI];     // dt^T  [ch][t]
__device__ __half g_gyh [(size_t)NR2 * DI];     // gy^T  [ch][t]
__device__ float  g_ym  [(size_t)NR2 * DM];
__device__ float  g_ycomb[(size_t)NR * DM];
__device__ float  g_ff  [(size_t)NR * DM];

__device__ __half g_xh  [(size_t)NR*DM];
__device__ __half g_ych [(size_t)NR*DM];
__device__ __half g_fhh [(size_t)NR*DI];

// transposed weights [N][K] fp16 (hi; lo only where 2-pass)
__device__ __half g_tWinH0[(size_t)4096*1024];
__device__ __half g_tWinH1[(size_t)4096*1024];
__device__ __half g_tWxH0 [(size_t)128*2048],  g_tWxL0 [(size_t)128*2048];
__device__ __half g_tWxH1 [(size_t)128*2048],  g_tWxL1 [(size_t)128*2048];
__device__ __half g_tWdtH0[(size_t)2048*64],   g_tWdtL0[(size_t)2048*64];
__device__ __half g_tWdtH1[(size_t)2048*64],   g_tWdtL1[(size_t)2048*64];
__device__ __half g_tWoH0 [(size_t)1024*2048];
__device__ __half g_tWoH1 [(size_t)1024*2048];
__device__ __half g_tF1H  [(size_t)2048*1024];
__device__ __half g_tF2H  [(size_t)1024*2048];

// ---------------------------------------------------------------------------
// helpers
// ---------------------------------------------------------------------------
__device__ __forceinline__ uint32_t smem_u32(const void* p) {
    uint32_t a;
    asm("{ .reg .u64 t; cvta.to.shared.u64 t, %1; cvt.u32.u64 %0, t; }"
        : "=r"(a) : "l"(p));
    return a;
}
__device__ __forceinline__ void ldsm4(uint32_t* r, uint32_t addr) {
    asm volatile("ldmatrix.sync.aligned.m8n8.x4.shared.b16 {%0,%1,%2,%3}, [%4];"
        : "=r"(r[0]), "=r"(r[1]), "=r"(r[2]), "=r"(r[3]) : "r"(addr));
}
__device__ __forceinline__ void ldsm4t(uint32_t* r, uint32_t addr) {
    asm volatile("ldmatrix.sync.aligned.m8n8.x4.trans.shared.b16 {%0,%1,%2,%3}, [%4];"
        : "=r"(r[0]), "=r"(r[1]), "=r"(r[2]), "=r"(r[3]) : "r"(addr));
}
__device__ __forceinline__ void mma_f16(float* c, const uint32_t* a, const uint32_t* b) {
    asm volatile("mma.sync.aligned.m16n8k16.row.col.f32.f16.f16.f32 "
        "{%0,%1,%2,%3}, {%4,%5,%6,%7}, {%8,%9}, {%0,%1,%2,%3};"
        : "+f"(c[0]), "+f"(c[1]), "+f"(c[2]), "+f"(c[3])
        : "r"(a[0]), "r"(a[1]), "r"(a[2]), "r"(a[3]), "r"(b[0]), "r"(b[1]));
}
__device__ __forceinline__ void cp16(uint32_t dst, const void* src) {
    asm volatile("{ .reg .u64 g; cvta.to.global.u64 g, %1; "
                 "cp.async.cg.shared.global [%0], [g], 16; }"
                 :: "r"(dst), "l"(src) : "memory");
}
#define CP_COMMIT() asm volatile("cp.async.commit_group;" ::: "memory")
#define CP_WAIT1()  asm volatile("cp.async.wait_group 1;" ::: "memory")

__device__ __forceinline__ int fliprow(int m) {
    return (m & ~(SEQ - 1)) | ((SEQ - 1) - (m & (SEQ - 1)));
}
__device__ __forceinline__ void split_h(float v, __half& h, __half& l) {
    h = __float2half_rn(v);
    l = __float2half_rn(v - __half2float(h));
}

// ---------------------------------------------------------------------------
// Unified GEMM.  C[M,N] = A[M,K] @ B[N,K]^T.
//  ATRANS: A stored t-major [K-rows][M-cols] with per-2048-M-block base
//          (row index = (m>>11)*2048 + k), loaded via ldmatrix.trans.
//  A2P:    A hi/lo 2-pass (normal layout only).   B2P: B hi/lo 2-pass.
//  SPLITK: blockIdx.z K-chunks into partial buffers.
// ---------------------------------------------------------------------------
struct GArgs {
    const __half *A1h, *A1l, *A2h, *A2l; long lda;
    const __half *B1h, *B1l, *B2h, *B2l; long ldb;
    int K;
    float* C; int ldc; __half* Ch;
    int mhalf, nhalf;
    int selA, selB;          // selA: 1 by bm (A2 array-local), 2 by bn; selB: 1 by bm
    int flipB2, flipC2, outT;
    int epi; const float *bias1, *bias2; int biasRow;
    long zrows;
};

template<bool ATRANS, bool A2P, bool B2P, bool SPLITK>
__global__ void __launch_bounds__(256, 2)
mma_gemm(GArgs g)
{
    constexpr int NBA = A2P ? 2 : 1;
    constexpr int NBB = B2P ? 2 : 1;
    constexpr int APL = ATRANS ? (32 * 272) : (128 * 80);
    constexpr int BPL = 128 * 80;
    constexpr int STG_ = NBA * APL + NBB * BPL;
    constexpr int NJ = 2 * (NBA + NBB);

    extern __shared__ char smem[];
    const uint32_t sb = smem_u32(smem);

    const int tid  = threadIdx.x;
    const int wid  = tid >> 5, lane = tid & 31;
    const int wm   = wid >> 2, wn = wid & 3;
    const int bm   = blockIdx.y * 128;
    const int bn   = blockIdx.x * 128;
    const int koff = SPLITK ? blockIdx.z * g.K : 0;
    float* Cc = g.C;
    if (SPLITK && Cc) Cc += (size_t)blockIdx.z * g.zrows * g.ldc;

    int half2;
    if (g.selA == 2)      half2 = (bn >= g.nhalf);
    else if (g.selA == 1 || g.selB == 1) half2 = (bm >= g.mhalf);
    else                  half2 = 0;

    const __half* Ah = (half2 && g.selA) ? g.A2h : g.A1h;
    const __half* Al = (half2 && g.selA) ? g.A2l : g.A1l;
    const __half* Bh = (half2 && g.selB) ? g.B2h : g.B1h;
    const __half* Bl = (half2 && g.selB) ? g.B2l : g.B1l;
    const float*  bias = (half2 && g.bias2) ? g.bias2 : g.bias1;

    // ---- cp.async mapping ---------------------------------------------------
    const __half* src[NJ];
    uint32_t dst0[NJ];
    long str[NJ];
    #pragma unroll
    for (int j = 0; j < NJ; ++j) {
        const int c = j * 256 + tid;
        const int p = c >> 9;
        const int cc = c & 511;
        if (p < NBA) {
            if (ATRANS) {
                const int row = cc >> 4, q = cc & 15;
                dst0[j] = sb + p * APL + row * 272 + q * 16;
                src[j] = Ah + (size_t)((bm >> 11) * 2048 + koff + row) * g.lda
                            + (bm & 2047) + q * 8;
                str[j] = 32 * g.lda;
            } else {
                const int row = cc >> 2, q = cc & 3;
                dst0[j] = sb + p * APL + row * 80 + q * 16;
                const __half* Ap = p ? Al : Ah;
                int m = bm + row;
                if (half2 && g.selA == 1) m -= g.mhalf;   // FIX: A2 array-local rows
                src[j] = Ap + (size_t)m * g.lda + koff + q * 8;
                str[j] = 32;
            }
        } else {
            const int bp = p - NBA;
            const int row = cc >> 2, q = cc & 3;
            const __half* Bp = bp ? Bl : Bh;
            int n = bn + row;
            if (half2 && g.flipB2) n = fliprow(n);
            dst0[j] = sb + NBA * APL + bp * BPL + row * 80 + q * 16;
            src[j] = Bp + (size_t)n * g.ldb + koff + q * 8;
            str[j] = 32;
        }
    }

    // ---- ldmatrix lane offsets ------------------------------------------------
    const uint32_t a_loffN = ((lane & 7) + ((lane >> 3) & 1) * 8) * 80 + (lane >> 4) * 16;
    const uint32_t a_loffT = ((lane & 7) + ((lane >> 4) & 1) * 8) * 272 + ((lane >> 3) & 1) * 16;
    const uint32_t b_loff  = ((lane & 7) + (lane >> 4) * 8) * 80 + ((lane >> 3) & 1) * 16;
    const uint32_t awN = wm * 64 * 80 + a_loffN;
    const uint32_t awT = wm * 128 + a_loffT;
    const uint32_t bw  = NBA * APL + wn * 32 * 80 + b_loff;

    float acc[4][4][4];
    #pragma unroll
    for (int mt = 0; mt < 4; ++mt)
        #pragma unroll
        for (int nt = 0; nt < 4; ++nt)
            #pragma unroll
            for (int i = 0; i < 4; ++i) acc[mt][nt][i] = 0.f;

    const int S = g.K / 32;
    int ns = 0;
    #pragma unroll
    for (int p = 0; p < 2; ++p) {
        if (p < S) {
            const uint32_t so = (uint32_t)p * STG_;
            #pragma unroll
            for (int j = 0; j < NJ; ++j) cp16(dst0[j] + so, src[j] + (size_t)p * str[j]);
            ++ns;
        }
        CP_COMMIT();
    }

    for (int s = 0; s < S; ++s) {
        CP_WAIT1();
        __syncthreads();

        if (ns < S) {
            const uint32_t so = (uint32_t)(ns % 3) * STG_;
            #pragma unroll
            for (int j = 0; j < NJ; ++j) cp16(dst0[j] + so, src[j] + (size_t)ns * str[j]);
            ++ns;
        }
        CP_COMMIT();

        const uint32_t bo = sb + (uint32_t)(s % 3) * STG_;
        #pragma unroll
        for (int ks = 0; ks < 2; ++ks) {
            uint32_t bhf[8];
            ldsm4(&bhf[0], bo + bw + ks * 32);
            ldsm4(&bhf[4], bo + bw + 16 * 80 + ks * 32);
            uint32_t blf[8];
            if (B2P) {
                ldsm4(&blf[0], bo + bw + BPL + ks * 32);
                ldsm4(&blf[4], bo + bw + BPL + 16 * 80 + ks * 32);
            }
            #pragma unroll
            for (int mt = 0; mt < 4; ++mt) {
                uint32_t a[4];
                if (ATRANS) ldsm4t(a, bo + awT + mt * 32 + ks * 16 * 272);
                else        ldsm4 (a, bo + awN + mt * 16 * 80 + ks * 32);
                #pragma unroll
                for (int nt = 0; nt < 4; ++nt) mma_f16(acc[mt][nt], a, &bhf[nt * 2]);
                if (B2P) {
                    #pragma unroll
                    for (int nt = 0; nt < 4; ++nt) mma_f16(acc[mt][nt], a, &blf[nt * 2]);
                }
                if (A2P) {
                    uint32_t a2[4];
                    ldsm4(a2, bo + APL + awN + mt * 16 * 80 + ks * 32);
                    #pragma unroll
                    for (int nt = 0; nt < 4; ++nt) mma_f16(acc[mt][nt], a2, &bhf[nt * 2]);
                }
            }
        }
    }

    // ---- epilogue ---------------------------------------------------------------
    #pragma unroll
    for (int mt = 0; mt < 4; ++mt) {
        const int r0 = bm + wm * 64 + mt * 16 + (lane >> 2);
        #pragma unroll
        for (int half = 0; half < 2; ++half) {
            const int rg = r0 + half * 8;
            int mg = rg;
            if (half2 && g.flipC2) mg = g.mhalf + fliprow(rg & (g.mhalf - 1));
            #pragma unroll
            for (int nt = 0; nt < 4; ++nt) {
                const int col = bn + wn * 32 + nt * 8 + (lane & 3) * 2;
                float v0 = acc[mt][nt][half * 2 + 0];
                float v1 = acc[mt][nt][half * 2 + 1];
                if (g.epi != EP_NONE) {
                    const float b0 = g.biasRow ? bias[mg] : bias[col];
                    const float b1 = g.biasRow ? b0 : bias[col + 1];
                    v0 += b0; v1 += b1;
                }
                if (g.epi == EP_SOFTPLUS) {
                    v0 = (v0 > 20.f) ? v0 : log1pf(expf(v0));
                    v1 = (v1 > 20.f) ? v1 : log1pf(expf(v1));
                } else if (g.epi == EP_RELU) {
                    v0 = fmaxf(v0, 0.f); v1 = fmaxf(v1, 0.f);
                }
                if (Cc) {
                    float* ptr;
                    if (g.outT)
                        ptr = Cc + ((size_t)(col >> 11) * 2048 + mg) * g.ldc + (col & 2047);
                    else
                        ptr = Cc + (size_t)mg * g.ldc + col;
                    *reinterpret_cast<float2*>(ptr) = make_float2(v0, v1);
                }
                if (g.Ch) {
                    __half2 p2; p2.x = __float2half_rn(v0); p2.y = __float2half_rn(v1);
                    *reinterpret_cast<__half2*>(g.Ch + (size_t)mg * g.ldc + col) = p2;
                }
            }
        }
    }
}

// ---------------------------------------------------------------------------
// batched transpose + hi/lo fp16
// ---------------------------------------------------------------------------
struct TBatch {
    const float* W[8];
    __half* Th[8];
    __half* Tl[8];
    int K[8], N[8], Npad[8], ntiles[8];
    int count;
};

__global__ void __launch_bounds__(256)
transpose_batch(TBatch P)
{
    int t = blockIdx.x;
    int di = 0, base = 0;
    while (di < P.count && t >= base + P.ntiles[di]) { base += P.ntiles[di]; ++di; }
    if (di >= P.count) return;
    const int local = t - base;
    const int nx = P.Npad[di] / 32;
    const int k0 = (local / nx) * 32;
    const int n0 = (local % nx) * 32;
    const float* W = P.W[di];
    const int K = P.K[di], N = P.N[di];

    __shared__ float tsh[32][33];
    const int tx = threadIdx.x & 31, ty = threadIdx.x >> 5;
    #pragma unroll
    for (int i = 0; i < 4; ++i) {
        int k = k0 + ty + i * 8, n = n0 + tx;
        tsh[ty + i * 8][tx] = (n < N) ? W[(size_t)k * N + n] : 0.f;
    }
    __syncthreads();
    __half* Th = P.Th[di]; __half* Tl = P.Tl[di];
    #pragma unroll
    for (int i = 0; i < 4; ++i) {
        int n = n0 + ty + i * 8, k = k0 + tx;
        float v = tsh[tx][ty + i * 8];
        __half h, l; split_h(v, h, l);
        Th[(size_t)n * K + k] = h;
        if (Tl) Tl[(size_t)n * K + k] = l;
    }
}

__global__ void __launch_bounds__(256)
convert_h(const float* __restrict__ src, __half* __restrict__ h, int n)
{
    int i = blockIdx.x * 256 + threadIdx.x;
    if (i < n) h[i] = __float2half_rn(src[i]);
}

__global__ void __launch_bounds__(256)
reduce_xdbc()
{
    int i = blockIdx.x * 256 + threadIdx.x;
    const size_t P = (size_t)NR2 * NXP;
    float s = g_xdp[i] + g_xdp[P + i] + g_xdp[2*P + i] + g_xdp[3*P + i];
    g_xdbc[i] = s;
    g_xdh[i]  = __float2half_rn(s);
}

// ---------------------------------------------------------------------------
// causal dwconv(4) + SiLU, t-major.  One block per (dirb, d) channel.
// ---------------------------------------------------------------------------
__global__ void __launch_bounds__(256)
conv_silu_kernel(const float* __restrict__ convw0, const float* __restrict__ convb0,
                 const float* __restrict__ convw1, const float* __restrict__ convb1)
{
    const int blk  = blockIdx.x;            // 8192 = dirb*2048 + d
    const int dirb = blk >> 11;
    const int d    = blk & 2047;
    const int dir  = dirb >> 1;
    const int b    = dirb & 1;

    const float* convw = dir ? convw1 : convw0;
    const float* convb = dir ? convb1 : convb0;
    const float4 w = *reinterpret_cast<const float4*>(convw + d * 4);
    const float bv = convb[d];

    const float* srcr = g_xzT + (size_t)(dir * 4096 + d) * 4096 + b * 2048;
    float* oF = g_xiT + (size_t)blk * SEQ;
    __half* oH = g_xih + (size_t)blk * SEQ;

    const int t0 = threadIdx.x * 8;
    float v[11];
    #pragma unroll
    for (int i = 0; i < 11; ++i) {
        const int t = t0 - 3 + i;
        v[i] = (t >= 0) ? srcr[t] : 0.f;
    }
    float out[8];
    __half oh[8];
    #pragma unroll
    for (int j = 0; j < 8; ++j) {
        float a = bv;
        a = fmaf(v[j],     w.x, a);
        a = fmaf(v[j + 1], w.y, a);
        a = fmaf(v[j + 2], w.z, a);
        a = fmaf(v[j + 3], w.w, a);
        float y = a / (1.f + expf(-a));
        out[j] = y;
        oh[j]  = __float2half_rn(y);
    }
    *reinterpret_cast<float4*>(oF + t0)     = make_float4(out[0], out[1], out[2], out[3]);
    *reinterpret_cast<float4*>(oF + t0 + 4) = make_float4(out[4], out[5], out[6], out[7]);
    *reinterpret_cast<uint4*>(oH + t0)      = *reinterpret_cast<uint4*>(oh);
}

// ---------------------------------------------------------------------------
// selective scan, t-major, unroll x8
// ---------------------------------------------------------------------------
__global__ void __launch_bounds__(256)
scan_kernel(const float* __restrict__ Alog0, const float* __restrict__ Dpar0,
            const float* __restrict__ Alog1, const float* __restrict__ Dpar1)
{
    const int lane = threadIdx.x & 31;
    const int gw   = blockIdx.x * 8 + (threadIdx.x >> 5);   // 4096 warps
    const int half = lane >> 4;
    const int s    = lane & 15;
    const int ch   = gw * 2 + half;                          // 0..8191
    const int dirb = ch >> 11;
    const int d    = ch & 2047;
    const int dir  = dirb >> 1;
    const int b    = dirb & 1;

    const float* Alog = dir ? Alog1 : Alog0;
    const float* Dpar = dir ? Dpar1 : Dpar0;
    const float Ac = -expf(Alog[d * DS + s]);
    const float Dp = Dpar[d];

    const float*  dt_p = g_dtT + (size_t)ch * SEQ;
    const float*  u_p  = g_xiT + (size_t)ch * SEQ;
    const float*  z_p  = g_xzT + (size_t)(dir * 4096 + DI + d) * 4096 + b * 2048;
    const float*  bc_p = g_xdbc + (size_t)dirb * SEQ * NXP + DTR + s;
    __half*       o_p  = g_gyh + (size_t)ch * SEQ;

    float h = 0.f;
    for (int t0 = 0; t0 < SEQ; t0 += 8) {
        float4 dtA = *reinterpret_cast<const float4*>(dt_p + t0);
        float4 dtB = *reinterpret_cast<const float4*>(dt_p + t0 + 4);
        float4 uA  = *reinterpret_cast<const float4*>(u_p + t0);
        float4 uB  = *reinterpret_cast<const float4*>(u_p + t0 + 4);
        float4 zA  = *reinterpret_cast<const float4*>(z_p + t0);
        float4 zB  = *reinterpret_cast<const float4*>(z_p + t0 + 4);
        float dtv[8] = {dtA.x, dtA.y, dtA.z, dtA.w, dtB.x, dtB.y, dtB.z, dtB.w};
        float uu[8]  = {uA.x, uA.y, uA.z, uA.w, uB.x, uB.y, uB.z, uB.w};
        float zf[8]  = {zA.x, zA.y, zA.z, zA.w, zB.x, zB.y, zB.z, zB.w};
        float Bv[8], Cv[8];
        #pragma unroll
        for (int i = 0; i < 8; ++i) {
            Bv[i] = bc_p[(size_t)(t0 + i) * NXP];
            Cv[i] = bc_p[(size_t)(t0 + i) * NXP + DS];
        }
        __half ov[8];
        #pragma unroll
        for (int i = 0; i < 8; ++i) {
            const float dA = __expf(dtv[i] * Ac);
            h = fmaf(dA, h, dtv[i] * uu[i] * Bv[i]);
            float p = h * Cv[i];
            #pragma unroll
            for (int o = 8; o; o >>= 1) p += __shfl_xor_sync(0xffffffffu, p, o);
            const float z = zf[i];
            const float gt = z / (1.f + __expf(-z));
            ov[i] = __float2half_rn((p + uu[i] * Dp) * gt);
        }
        if (s == 0)
            *reinterpret_cast<uint4*>(o_p + t0) = *reinterpret_cast<uint4*>(ov);
    }
}

// ---------------------------------------------------------------------------
// layernorms
// ---------------------------------------------------------------------------
__device__ __forceinline__ float blockReduceSum(float v)
{
    __shared__ float sh[8];
    __syncthreads();
    #pragma unroll
    for (int o = 16; o; o >>= 1) v += __shfl_xor_sync(0xffffffffu, v, o);
    if ((threadIdx.x & 31) == 0) sh[threadIdx.x >> 5] = v;
    __syncthreads();
    if (threadIdx.x < 32) {
        float t = (threadIdx.x < 8) ? sh[threadIdx.x] : 0.f;
        #pragma unroll
        for (int o = 4; o; o >>= 1) t += __shfl_xor_sync(0xffffffffu, t, o);
        if (threadIdx.x == 0) sh[0] = t;
    }
    __syncthreads();
    return sh[0];
}

__global__ void __launch_bounds__(256)
ln_dual_kernel(const float* __restrict__ x,
               const float* __restrict__ w, const float* __restrict__ bs)
{
    const int row = blockIdx.x;
    const float* xr = x    + (size_t)row * DM;
    const float* fr = g_ym + (size_t)row * DM;
    const float* br = g_ym + (size_t)(NR + row) * DM;
    float* out      = g_ycomb + (size_t)row * DM;
    __half* oh      = g_ych   + (size_t)row * DM;

    float a[4], c[4];
    float sa = 0.f, sb = 0.f;
    #pragma unroll
    for (int i = 0; i < 4; ++i) {
        int idx = threadIdx.x + i * 256;
        float xv = xr[idx];
        a[i] = fr[idx] + xv;
        c[i] = br[idx] + xv;
        sa += a[i]; sb += c[i];
    }
    sa = blockReduceSum(sa);
    sb = blockReduceSum(sb);
    const float mua = sa * (1.f / DM), mub = sb * (1.f / DM);
    float va = 0.f, vb = 0.f;
    #pragma unroll
    for (int i = 0; i < 4; ++i) {
        float da = a[i] - mua; va += da * da;
        float db = c[i] - mub; vb += db * db;
    }
    va = blockReduceSum(va);
    vb = blockReduceSum(vb);
    const float ra = rsqrtf(va * (1.f / DM) + LN_EPS);
    const float rb = rsqrtf(vb * (1.f / DM) + LN_EPS);
    #pragma unroll
    for (int i = 0; i < 4; ++i) {
        int idx = threadIdx.x + i * 256;
        float wv = w[idx], bv = bs[idx];
        float o = ((a[i] - mua) * ra * wv + bv) + ((c[i] - mub) * rb * wv + bv);
        out[idx] = o;
        oh[idx]  = __float2half_rn(o);
    }
}

__global__ void __launch_bounds__(256)
ln_final_kernel(const float* __restrict__ w, const float* __restrict__ bs,
                float* __restrict__ out)
{
    const int row = blockIdx.x;
    const float* fr = g_ff    + (size_t)row * DM;
    const float* yr = g_ycomb + (size_t)row * DM;
    float* orow = out + (size_t)row * DM;

    float a[4];
    float sa = 0.f;
    #pragma unroll
    for (int i = 0; i < 4; ++i) {
        int idx = threadIdx.x + i * 256;
        a[i] = fr[idx] + yr[idx];
        sa += a[i];
    }
    sa = blockReduceSum(sa);
    const float mu = sa * (1.f / DM);
    float va = 0.f;
    #pragma unroll
    for (int i = 0; i < 4; ++i) { float dd = a[i] - mu; va += dd * dd; }
    va = blockReduceSum(va);
    const float rs = rsqrtf(va * (1.f / DM) + LN_EPS);
    #pragma unroll
    for (int i = 0; i < 4; ++i) {
        int idx = threadIdx.x + i * 256;
        orow[idx] = (a[i] - mu) * rs * w[idx] + bs[idx];
    }
}

// ---------------------------------------------------------------------------
// launch
// ---------------------------------------------------------------------------
static inline int smem_of(bool atrans, bool a2p, bool b2p) {
    int apl = atrans ? 32 * 272 : 128 * 80;
    return 3 * ((a2p ? 2 : 1) * apl + (b2p ? 2 : 1) * 128 * 80);
}

extern "C" void kernel_launch(void* const* d_in, const int* in_sizes, int n_in,
                              void* d_out, int out_size)
{
    (void)in_sizes; (void)n_in; (void)out_size;
    const float* x      = (const float*)d_in[0];
    const float* Win0   = (const float*)d_in[1];
    const float* convw0 = (const float*)d_in[2];
    const float* convb0 = (const float*)d_in[3];
    const float* Wx0    = (const float*)d_in[4];
    const float* Wdt0   = (const float*)d_in[5];
    const float* bdt0   = (const float*)d_in[6];
    const float* Alog0  = (const float*)d_in[7];
    const float* Dp0    = (const float*)d_in[8];
    const float* Wout0  = (const float*)d_in[9];
    const float* Win1   = (const float*)d_in[10];
    const float* convw1 = (const float*)d_in[11];
    const float* convb1 = (const float*)d_in[12];
    const float* Wx1    = (const float*)d_in[13];
    const float* Wdt1   = (const float*)d_in[14];
    const float* bdt1   = (const float*)d_in[15];
    const float* Alog1  = (const float*)d_in[16];
    const float* Dp1    = (const float*)d_in[17];
    const float* Wout1  = (const float*)d_in[18];
    const float* fwn_w  = (const float*)d_in[19];
    const float* fwn_b  = (const float*)d_in[20];
    const float* fin_w  = (const float*)d_in[21];
    const float* fin_b  = (const float*)d_in[22];
    const float* ff_W1  = (const float*)d_in[23];
    const float* ff_b1  = (const float*)d_in[24];
    const float* ff_W2  = (const float*)d_in[25];
    const float* ff_b2  = (const float*)d_in[26];

    cudaFuncSetAttribute(mma_gemm<false,false,false,false>, cudaFuncAttributeMaxDynamicSharedMemorySize, smem_of(0,0,0));
    cudaFuncSetAttribute(mma_gemm<true,false,true,true>,    cudaFuncAttributeMaxDynamicSharedMemorySize, smem_of(1,0,1));
    cudaFuncSetAttribute(mma_gemm<false,true,false,false>,  cudaFuncAttributeMaxDynamicSharedMemorySize, smem_of(0,1,0));
    cudaFuncSetAttribute(mma_gemm<true,false,false,false>,  cudaFuncAttributeMaxDynamicSharedMemorySize, smem_of(1,0,0));

    __half *xih, *xdh, *gyh, *xh, *ych, *fhh;
    float *xzT, *xiT, *xdbc, *xdp, *dtT, *ym, *ycomb, *ff;
    cudaGetSymbolAddress((void**)&xzT, g_xzT);
    cudaGetSymbolAddress((void**)&xiT, g_xiT);
    cudaGetSymbolAddress((void**)&xih, g_xih);
    cudaGetSymbolAddress((void**)&xdbc, g_xdbc);
    cudaGetSymbolAddress((void**)&xdp, g_xdp);
    cudaGetSymbolAddress((void**)&xdh, g_xdh);
    cudaGetSymbolAddress((void**)&dtT, g_dtT);
    cudaGetSymbolAddress((void**)&gyh, g_gyh);
    cudaGetSymbolAddress((void**)&ym, g_ym);
    cudaGetSymbolAddress((void**)&ycomb, g_ycomb);
    cudaGetSymbolAddress((void**)&ff, g_ff);
    cudaGetSymbolAddress((void**)&xh, g_xh);
    cudaGetSymbolAddress((void**)&ych, g_ych);
    cudaGetSymbolAddress((void**)&fhh, g_fhh);

    __half *tWinH0,*tWinH1,*tWxH0,*tWxL0,*tWxH1,*tWxL1;
    __half *tWdtH0,*tWdtL0,*tWdtH1,*tWdtL1,*tWoH0,*tWoH1,*tF1H,*tF2H;
    cudaGetSymbolAddress((void**)&tWinH0, g_tWinH0);
    cudaGetSymbolAddress((void**)&tWinH1, g_tWinH1);
    cudaGetSymbolAddress((void**)&tWxH0, g_tWxH0);   cudaGetSymbolAddress((void**)&tWxL0, g_tWxL0);
    cudaGetSymbolAddress((void**)&tWxH1, g_tWxH1);   cudaGetSymbolAddress((void**)&tWxL1, g_tWxL1);
    cudaGetSymbolAddress((void**)&tWdtH0, g_tWdtH0); cudaGetSymbolAddress((void**)&tWdtL0, g_tWdtL0);
    cudaGetSymbolAddress((void**)&tWdtH1, g_tWdtH1); cudaGetSymbolAddress((void**)&tWdtL1, g_tWdtL1);
    cudaGetSymbolAddress((void**)&tWoH0, g_tWoH0);
    cudaGetSymbolAddress((void**)&tWoH1, g_tWoH1);
    cudaGetSymbolAddress((void**)&tF1H, g_tF1H);
    cudaGetSymbolAddress((void**)&tF2H, g_tF2H);

    // 0: x -> fp16
    convert_h<<<(NR*DM)/256, 256>>>(x, xh, NR*DM);

    // 1: Win transposes (hi only)
    {
        TBatch P = {};
        P.count = 2;
        P.W[0]=Win0; P.Th[0]=tWinH0; P.Tl[0]=nullptr; P.K[0]=1024; P.N[0]=4096; P.Npad[0]=4096; P.ntiles[0]=4096;
        P.W[1]=Win1; P.Th[1]=tWinH1; P.Tl[1]=nullptr; P.K[1]=1024; P.N[1]=4096; P.Npad[1]=4096; P.ntiles[1]=4096;
        transpose_batch<<<8192, 256>>>(P);
    }
    // 2: remaining transposes
    {
        TBatch P = {};
        P.count = 8;
        P.W[0]=Wx0;   P.Th[0]=tWxH0;  P.Tl[0]=tWxL0;   P.K[0]=2048; P.N[0]=96;   P.Npad[0]=128;  P.ntiles[0]=256;
        P.W[1]=Wx1;   P.Th[1]=tWxH1;  P.Tl[1]=tWxL1;   P.K[1]=2048; P.N[1]=96;   P.Npad[1]=128;  P.ntiles[1]=256;
        P.W[2]=Wdt0;  P.Th[2]=tWdtH0; P.Tl[2]=tWdtL0;  P.K[2]=64;   P.N[2]=2048; P.Npad[2]=2048; P.ntiles[2]=128;
        P.W[3]=Wdt1;  P.Th[3]=tWdtH1; P.Tl[3]=tWdtL1;  P.K[3]=64;   P.N[3]=2048; P.Npad[3]=2048; P.ntiles[3]=128;
        P.W[4]=Wout0; P.Th[4]=tWoH0;  P.Tl[4]=nullptr; P.K[4]=2048; P.N[4]=1024; P.Npad[4]=1024; P.ntiles[4]=2048;
        P.W[5]=Wout1; P.Th[5]=tWoH1;  P.Tl[5]=nullptr; P.K[5]=2048; P.N[5]=1024; P.Npad[5]=1024; P.ntiles[5]=2048;
        P.W[6]=ff_W1; P.Th[6]=tF1H;   P.Tl[6]=nullptr; P.K[6]=1024; P.N[6]=2048; P.Npad[6]=2048; P.ntiles[6]=2048;
        P.W[7]=ff_W2; P.Th[7]=tF2H;   P.Tl[7]=nullptr; P.K[7]=2048; P.N[7]=1024; P.Npad[7]=1024; P.ntiles[7]=2048;
        transpose_batch<<<8960, 256>>>(P);
    }

    // 3 (profiled): xz^T = {Win0|Win1}^T @ x^T, fp32 out.  M=8192, N=4096.
    {
        GArgs a = {};
        a.A1h = tWinH0; a.A2h = tWinH1; a.lda = 1024;
        a.B1h = xh; a.ldb = 1024;
        a.K = 1024;
        a.C = xzT; a.ldc = 4096;
        a.mhalf = NR; a.selA = 1; a.flipB2 = 1;
        a.epi = EP_NONE;
        mma_gemm<false,false,false,false><<<dim3(32, 64), 256, smem_of(0,0,0)>>>(a);
    }

    // 4: conv + silu (t-major)
    conv_silu_kernel<<<8192, 256>>>(convw0, convb0, convw1, convb1);

    // 5: xdbc partials = xi @ {Wx0|Wx1}, split-K=4, 2-pass B.  A t-major.
    {
        GArgs a = {};
        a.A1h = xih; a.lda = SEQ;
        a.B1h = tWxH0; a.B1l = tWxL0; a.B2h = tWxH1; a.B2l = tWxL1; a.ldb = 2048;
        a.K = 512;
        a.C = xdp; a.ldc = NXP;
        a.mhalf = NR; a.selB = 1;
        a.epi = EP_NONE; a.zrows = NR2;
        mma_gemm<true,false,true,true><<<dim3(1, 64, 4), 256, smem_of(1,0,1)>>>(a);
    }

    // 6: reduce partials
    reduce_xdbc<<<(NR2*NXP)/256, 256>>>();

    // 7: dt^T = softplus({Wdt0|Wdt1}^T @ xdbc^T + bdt), 2-pass A, t-major out.
    {
        GArgs a = {};
        a.A1h = tWdtH0; a.A1l = tWdtL0; a.A2h = tWdtH1; a.A2l = tWdtL1; a.lda = 64;
        a.B1h = xdh; a.ldb = NXP;
        a.K = 64;
        a.C = dtT; a.ldc = SEQ; a.outT = 1;
        a.nhalf = NR; a.selA = 2;
        a.epi = EP_SOFTPLUS; a.bias1 = bdt0; a.bias2 = bdt1; a.biasRow = 1;
        mma_gemm<false,true,false,false><<<dim3(64, 16), 256, smem_of(0,1,0)>>>(a);
    }

    // 8: selective scan (t-major)
    scan_kernel<<<512, 256>>>(Alog0, Dp0, Alog1, Dp1);

    // 9: ym = gy @ {Wout0|Wout1}.  A = gy^T t-major; bw half flip-stored.
    {
        GArgs a = {};
        a.A1h = gyh; a.lda = SEQ;
        a.B1h = tWoH0; a.B2h = tWoH1; a.ldb = 2048;
        a.K = 2048;
        a.C = ym; a.ldc = DM;
        a.mhalf = NR; a.selB = 1; a.flipC2 = 1;
        a.epi = EP_NONE;
        mma_gemm<true,false,false,false><<<dim3(8, 64), 256, smem_of(1,0,0)>>>(a);
    }

    // 10: ycomb = LN(ym_fw + x) + LN(ym_bw + x)
    ln_dual_kernel<<<NR, 256>>>(x, fwn_w, fwn_b);

    // 11: ffh = relu(ycomb @ W1 + b1)  (fp16 out only)
    {
        GArgs a = {};
        a.A1h = ych; a.lda = 1024;
        a.B1h = tF1H; a.ldb = 1024;
        a.K = 1024;
        a.C = nullptr; a.Ch = fhh; a.ldc = DI;
        a.epi = EP_RELU; a.bias1 = ff_b1;
        mma_gemm<false,false,false,false><<<dim3(16, 32), 256, smem_of(0,0,0)>>>(a);
    }

    // 12: ff = ffh @ W2 + b2
    {
        GArgs a = {};
        a.A1h = fhh; a.lda = 2048;
        a.B1h = tF2H; a.ldb = 2048;
        a.K = 2048;
        a.C = ff; a.ldc = DM;
        a.epi = EP_BIAS; a.bias1 = ff_b2;
        mma_gemm<false,false,false,false><<<dim3(8, 32), 256, smem_of(0,0,0)>>>(a);
    }

    // 13: out = LN(ff + ycomb)
    ln_final_kernel<<<NR, 256>>>(fin_w, fin_b, (float*)d_out);
}